// round 1
// baseline (speedup 1.0000x reference)
#include <cuda_runtime.h>
#include <cstdint>

// ---------------------------------------------------------------------------
// Problem constants
// ---------------------------------------------------------------------------
#define BATCH 8
#define NNODE 500
#define NQ    25
#define ENC   512
#define DIN   300
#define NC    70
#define NET   3
#define HOPS  3
#define MROWS (BATCH*NNODE)   // 4000
#define QROWS (BATCH*NQ)      // 200

// ---------------------------------------------------------------------------
// Device scratch (module-load allocated; no cudaMalloc anywhere)
// ---------------------------------------------------------------------------
__device__ float g_nc  [MROWS*ENC];      // nodes_compress (unmasked, tanh)
__device__ float g_qc  [QROWS*ENC];      // query_compress
__device__ float g_L   [MROWS*ENC];      // last_hop
__device__ float g_hm  [MROWS*ENC];
__device__ float g_U   [MROWS*ENC];      // update
__device__ float g_att [MROWS*ENC];
__device__ float g_A2  [BATCH*NNODE*NNODE]; // sum_e adj
__device__ float g_sq  [QROWS];
__device__ float g_n2q [MROWS*ENC];
__device__ float g_smax[MROWS];
__device__ float g_q2n [BATCH*ENC];
__device__ float g_g   [MROWS*4*ENC];    // concat features
__device__ float g_h1  [MROWS*128];
__device__ float g_raw [MROWS];

// ---------------------------------------------------------------------------
// Helpers
// ---------------------------------------------------------------------------
__device__ __forceinline__ float warpSum(float v) {
#pragma unroll
    for (int o = 16; o; o >>= 1) v += __shfl_xor_sync(0xffffffffu, v, o);
    return v;
}
__device__ __forceinline__ float warpMax(float v) {
#pragma unroll
    for (int o = 16; o; o >>= 1) v = fmaxf(v, __shfl_xor_sync(0xffffffffu, v, o));
    return v;
}

// ---------------------------------------------------------------------------
// Tiled SGEMM: C = epi(A @ W + bias)
//   A logical [M,K]; physically split at ksplit between pointers A (lead dim
//   ksplit) and Ab (lead dim K-ksplit)  -> lets us do concat([U,L]) @ Wc
//   without materializing the concat.
//   EPI: 0 = +bias           1 = tanh(+bias)
//        2 = (+bias)*nmask   3 = sigmoid(+bias)*nmask     (nmask from nlen)
// ---------------------------------------------------------------------------
template<int BM, int BN, int BK, int TM, int TN, int EPI>
__global__ void gemm_k(const float* __restrict__ A, const float* __restrict__ Ab,
                       int ksplit,
                       const float* __restrict__ W, const float* __restrict__ bias,
                       float* __restrict__ C,
                       int M, int K, int Nn, const int* __restrict__ nlen)
{
    constexpr int THREADS = (BM/TM) * (BN/TN);
    constexpr int PAD = 4;
    __shared__ float As[BK][BM + PAD];
    __shared__ float Bs[BK][BN];

    const int tid = threadIdx.x;
    constexpr int TXC = BN / TN;
    const int tx = tid % TXC;
    const int ty = tid / TXC;
    const int rowBlock = blockIdx.y * BM;
    const int colBlock = blockIdx.x * BN;

    float acc[TM][TN];
#pragma unroll
    for (int i = 0; i < TM; i++)
#pragma unroll
        for (int j = 0; j < TN; j++) acc[i][j] = 0.f;

    for (int k0 = 0; k0 < K; k0 += BK) {
        // A tile (BM x BK) -> As[k][r]
#pragma unroll
        for (int l = tid; l < BM*BK; l += THREADS) {
            int r = l / BK, k = l % BK;
            int gr = rowBlock + r, gk = k0 + k;
            float v = 0.f;
            if (gr < M && gk < K) {
                if (gk < ksplit) v = A [(size_t)gr * ksplit + gk];
                else             v = Ab[(size_t)gr * (K - ksplit) + (gk - ksplit)];
            }
            As[k][r] = v;
        }
        // B tile (BK x BN)
#pragma unroll
        for (int l = tid; l < BK*BN; l += THREADS) {
            int k = l / BN, n = l % BN;
            int gk = k0 + k, gn = colBlock + n;
            Bs[k][n] = (gk < K && gn < Nn) ? W[(size_t)gk * Nn + gn] : 0.f;
        }
        __syncthreads();

#pragma unroll
        for (int k = 0; k < BK; k++) {
            float a[TM], bfr[TN];
#pragma unroll
            for (int i = 0; i < TM; i += 4) {
                float4 t = *reinterpret_cast<const float4*>(&As[k][ty*TM + i]);
                a[i] = t.x; a[i+1] = t.y; a[i+2] = t.z; a[i+3] = t.w;
            }
#pragma unroll
            for (int j = 0; j < TN; j += 4) {
                float4 t = *reinterpret_cast<const float4*>(&Bs[k][tx*TN + j]);
                bfr[j] = t.x; bfr[j+1] = t.y; bfr[j+2] = t.z; bfr[j+3] = t.w;
            }
#pragma unroll
            for (int i = 0; i < TM; i++)
#pragma unroll
                for (int j = 0; j < TN; j++) acc[i][j] += a[i] * bfr[j];
        }
        __syncthreads();
    }

#pragma unroll
    for (int i = 0; i < TM; i++) {
        int r = rowBlock + ty*TM + i;
        if (r >= M) continue;
        float rowmask = 1.f;
        if (EPI == 2 || EPI == 3) {
            int bb = r / NNODE, ii = r - bb * NNODE;
            rowmask = (ii < nlen[bb]) ? 1.f : 0.f;
        }
#pragma unroll
        for (int j = 0; j < TN; j++) {
            int c = colBlock + tx*TN + j;
            if (c >= Nn) continue;
            float v = acc[i][j] + bias[c];
            if      (EPI == 1) v = tanhf(v);
            else if (EPI == 2) v *= rowmask;
            else if (EPI == 3) v = rowmask / (1.f + __expf(-v));
            C[(size_t)r * Nn + c] = v;
        }
    }
}

// ---------------------------------------------------------------------------
// A2 = sum over 3 nets of adj
// ---------------------------------------------------------------------------
__global__ void a2_kernel(const float* __restrict__ adj, float* __restrict__ A2)
{
    int idx = blockIdx.x * 256 + threadIdx.x;
    if (idx >= BATCH * NNODE * NNODE) return;
    int b = idx / (NNODE*NNODE), r = idx - b * (NNODE*NNODE);
    const float* base = adj + (size_t)b * NET * NNODE * NNODE;
    A2[idx] = base[r] + base[NNODE*NNODE + r] + base[2*NNODE*NNODE + r];
}

// ---------------------------------------------------------------------------
// L = nc * nmask
// ---------------------------------------------------------------------------
__global__ void init_L(const float* __restrict__ nc, const int* __restrict__ nlen,
                       float* __restrict__ L)
{
    int idx = blockIdx.x * 256 + threadIdx.x;      // exactly MROWS*ENC launched
    int m = idx >> 9;
    int b = m / NNODE, i = m - b * NNODE;
    L[idx] = (i < nlen[b]) ? nc[idx] : 0.f;
}

// ---------------------------------------------------------------------------
// U[b,i,:] = A2[b,i,:] @ hm[b,:,:] + hm[b,i,:]   (zero-skipping over A2 row)
// one block (128 thr) per node row; each thread owns 4 channels (float4)
// ---------------------------------------------------------------------------
__global__ void spmm_update(const float* __restrict__ A2, const float* __restrict__ hm,
                            float* __restrict__ U)
{
    const int m = blockIdx.x;
    const int b = m / NNODE, i = m - b * NNODE;
    const float* arow = A2 + ((size_t)b * NNODE + i) * NNODE;
    const float* hmb  = hm + (size_t)b * NNODE * ENC;
    const int d0 = threadIdx.x * 4;
    float4 acc = *reinterpret_cast<const float4*>(hm + (size_t)m * ENC + d0);
    __shared__ float s[128];
    for (int jb = 0; jb < NNODE; jb += 128) {
        int j = jb + threadIdx.x;
        s[threadIdx.x] = (j < NNODE) ? arow[j] : 0.f;
        __syncthreads();
        int lim = min(128, NNODE - jb);
        for (int jj = 0; jj < lim; jj++) {
            float a = s[jj];                     // uniform across block
            if (a != 0.f) {
                const float4 hv = *reinterpret_cast<const float4*>(
                    hmb + (size_t)(jb + jj) * ENC + d0);
                acc.x += a * hv.x; acc.y += a * hv.y;
                acc.z += a * hv.z; acc.w += a * hv.w;
            }
        }
        __syncthreads();
    }
    *reinterpret_cast<float4*>(U + (size_t)m * ENC + d0) = acc;
}

// ---------------------------------------------------------------------------
// L = att*tanh(U) + (1-att)*L
// ---------------------------------------------------------------------------
__global__ void hop_update(const float* __restrict__ att, const float* __restrict__ U,
                           float* __restrict__ L)
{
    int idx = blockIdx.x * 256 + threadIdx.x;      // exactly MROWS*ENC launched
    float a = att[idx];
    L[idx] = a * tanhf(U[idx]) + (1.f - a) * L[idx];
}

// ---------------------------------------------------------------------------
// sq[b,q] = qc[b,q,:] . wa_q     (one warp per row)
// ---------------------------------------------------------------------------
__global__ void sq_kernel(const float* __restrict__ qc, const float* __restrict__ wa,
                          float* __restrict__ sq)
{
    int gw = (blockIdx.x * blockDim.x + threadIdx.x) >> 5;
    int lane = threadIdx.x & 31;
    if (gw >= QROWS) return;
    float s = 0.f;
    for (int d = lane; d < ENC; d += 32) s += qc[(size_t)gw * ENC + d] * wa[ENC + d];
    s = warpSum(s);
    if (lane == 0) sq[gw] = s;
}

// ---------------------------------------------------------------------------
// Per node m: sim[q] = L.wa_n + sq[q] + (L*wa_s).qc[q]; softmax over q;
// n2q[m,:] = softmax @ qc; smax[m] = max_q sim.
// ---------------------------------------------------------------------------
__global__ void attn_kernel(const float* __restrict__ L, const float* __restrict__ qc,
                            const float* __restrict__ wa, const float* __restrict__ sq,
                            float* __restrict__ n2q, float* __restrict__ smax)
{
    const int m = blockIdx.x;
    const int b = m / NNODE;
    const int tid = threadIdx.x;           // 128
    const int lane = tid & 31, warp = tid >> 5;
    __shared__ float Lws[ENC];
    __shared__ float red[4];
    __shared__ float simv[NQ];
    __shared__ float p[NQ];

    float snp = 0.f;
#pragma unroll
    for (int d = tid; d < ENC; d += 128) {
        float v = L[(size_t)m * ENC + d];
        Lws[d] = v * wa[2 * ENC + d];
        snp += v * wa[d];
    }
    snp = warpSum(snp);
    if (lane == 0) red[warp] = snp;
    __syncthreads();
    float sn = red[0] + red[1] + red[2] + red[3];

    for (int q = warp; q < NQ; q += 4) {
        const float* qr = qc + ((size_t)b * NQ + q) * ENC;
        float s = 0.f;
        for (int d = lane; d < ENC; d += 32) s += Lws[d] * qr[d];
        s = warpSum(s);
        if (lane == 0) simv[q] = sn + sq[b * NQ + q] + s;
    }
    __syncthreads();

    if (tid < 32) {
        float v = (lane < NQ) ? simv[lane] : -1e30f;
        float mx = warpMax(v);
        float e = (lane < NQ) ? __expf(v - mx) : 0.f;
        float Z = warpSum(e);
        if (lane < NQ) p[lane] = e / Z;
        if (lane == 0) smax[m] = mx;
    }
    __syncthreads();

#pragma unroll
    for (int d = tid; d < ENC; d += 128) {
        float acc = 0.f;
#pragma unroll
        for (int q = 0; q < NQ; q++) acc += p[q] * qc[((size_t)b * NQ + q) * ENC + d];
        n2q[(size_t)m * ENC + d] = acc;
    }
}

// ---------------------------------------------------------------------------
// Per batch: bvec = softmax_n(smax); q2n = bvec @ nc
// ---------------------------------------------------------------------------
__global__ void q2n_kernel(const float* __restrict__ smax, const float* __restrict__ nc,
                           float* __restrict__ q2n)
{
    const int b = blockIdx.x;
    const int tid = threadIdx.x;            // 256
    const int lane = tid & 31, warp = tid >> 5;
    __shared__ float w[NNODE];
    __shared__ float red[8];

    float mx = -1e30f;
    for (int n = tid; n < NNODE; n += 256) mx = fmaxf(mx, smax[b * NNODE + n]);
    mx = warpMax(mx);
    if (lane == 0) red[warp] = mx;
    __syncthreads();
    float bmax = red[0];
#pragma unroll
    for (int i = 1; i < 8; i++) bmax = fmaxf(bmax, red[i]);
    __syncthreads();

    float s = 0.f;
    for (int n = tid; n < NNODE; n += 256) {
        float e = __expf(smax[b * NNODE + n] - bmax);
        w[n] = e; s += e;
    }
    s = warpSum(s);
    if (lane == 0) red[warp] = s;
    __syncthreads();
    float Z = 0.f;
#pragma unroll
    for (int i = 0; i < 8; i++) Z += red[i];
    float inv = 1.f / Z;

    const int d0 = tid * 2;
    float a0 = 0.f, a1 = 0.f;
    for (int n = 0; n < NNODE; n++) {
        float ww = w[n] * inv;
        const float2 r = *reinterpret_cast<const float2*>(
            nc + ((size_t)b * NNODE + n) * ENC + d0);
        a0 += ww * r.x; a1 += ww * r.y;
    }
    q2n[b * ENC + d0]     = a0;
    q2n[b * ENC + d0 + 1] = a1;
}

// ---------------------------------------------------------------------------
// g = [nc, n2q, nc*n2q, nc*q2n]
// ---------------------------------------------------------------------------
__global__ void build_g(const float* __restrict__ nc, const float* __restrict__ n2q,
                        const float* __restrict__ q2n, float* __restrict__ g)
{
    int idx = blockIdx.x * 256 + threadIdx.x;      // MROWS*ENC
    int m = idx >> 9, d = idx & 511;
    int b = m / NNODE;
    float a = nc[idx], t = n2q[idx], qn = q2n[b * ENC + d];
    size_t base = (size_t)m * (4 * ENC) + d;
    g[base]           = a;
    g[base + ENC]     = t;
    g[base + 2 * ENC] = a * t;
    g[base + 3 * ENC] = a * qn;
}

// ---------------------------------------------------------------------------
// raw[m] = h1[m,:].W2 + b2     (one warp per row)
// ---------------------------------------------------------------------------
__global__ void raw_kernel(const float* __restrict__ h1, const float* __restrict__ W2,
                           const float* __restrict__ b2, float* __restrict__ raw)
{
    int gw = (blockIdx.x * blockDim.x + threadIdx.x) >> 5;
    int lane = threadIdx.x & 31;
    if (gw >= MROWS) return;
    float s = 0.f;
    for (int h = lane; h < 128; h += 32) s += h1[(size_t)gw * 128 + h] * W2[h];
    s = warpSum(s);
    if (lane == 0) raw[gw] = s + b2[0];
}

// ---------------------------------------------------------------------------
// out[b,c] = max_n f(mask*raw),  f(0) = -1e6   (one warp per (b,c))
// ---------------------------------------------------------------------------
__global__ void out_kernel(const int* __restrict__ mask, const float* __restrict__ raw,
                           float* __restrict__ out)
{
    int gw = (blockIdx.x * blockDim.x + threadIdx.x) >> 5;
    int lane = threadIdx.x & 31;
    if (gw >= BATCH * NC) return;
    int b = gw / NC, c = gw - b * NC;
    const int* mr = mask + ((size_t)b * NC + c) * NNODE;
    const float* rr = raw + b * NNODE;
    float mx = -1e30f;
    for (int n = lane; n < NNODE; n += 32) {
        float p = (float)mr[n] * rr[n];
        if (p == 0.f) p = -1e6f;
        mx = fmaxf(mx, p);
    }
    mx = warpMax(mx);
    if (lane == 0) out[gw] = mx;
}

// ---------------------------------------------------------------------------
// Launch
// ---------------------------------------------------------------------------
extern "C" void kernel_launch(void* const* d_in, const int* in_sizes, int n_in,
                              void* d_out, int out_size)
{
    const float* nodes_glove = (const float*)d_in[0];
    const float* query_glove = (const float*)d_in[1];
    const float* adj         = (const float*)d_in[2];
    const int*   nlen        = (const int*)  d_in[3];
    const int*   mask        = (const int*)  d_in[4];
    const float* Wn = (const float*)d_in[5];
    const float* bn = (const float*)d_in[6];
    const float* Wq = (const float*)d_in[7];
    const float* bq = (const float*)d_in[8];
    const float* Wh = (const float*)d_in[9];
    const float* bh = (const float*)d_in[10];
    const float* Wc = (const float*)d_in[11];
    const float* bc = (const float*)d_in[12];
    const float* wa = (const float*)d_in[13];
    const float* W1 = (const float*)d_in[14];
    const float* b1 = (const float*)d_in[15];
    const float* W2 = (const float*)d_in[16];
    const float* b2 = (const float*)d_in[17];
    float* out = (float*)d_out;

    float *p_nc, *p_qc, *p_L, *p_hm, *p_U, *p_att, *p_A2, *p_sq,
          *p_n2q, *p_smax, *p_q2n, *p_g, *p_h1, *p_raw;
    cudaGetSymbolAddress((void**)&p_nc,  g_nc);
    cudaGetSymbolAddress((void**)&p_qc,  g_qc);
    cudaGetSymbolAddress((void**)&p_L,   g_L);
    cudaGetSymbolAddress((void**)&p_hm,  g_hm);
    cudaGetSymbolAddress((void**)&p_U,   g_U);
    cudaGetSymbolAddress((void**)&p_att, g_att);
    cudaGetSymbolAddress((void**)&p_A2,  g_A2);
    cudaGetSymbolAddress((void**)&p_sq,  g_sq);
    cudaGetSymbolAddress((void**)&p_n2q, g_n2q);
    cudaGetSymbolAddress((void**)&p_smax,g_smax);
    cudaGetSymbolAddress((void**)&p_q2n, g_q2n);
    cudaGetSymbolAddress((void**)&p_g,   g_g);
    cudaGetSymbolAddress((void**)&p_h1,  g_h1);
    cudaGetSymbolAddress((void**)&p_raw, g_raw);

    // A2 = sum_e adj
    a2_kernel<<<(BATCH*NNODE*NNODE + 255) / 256, 256>>>(adj, p_A2);

    // nodes_compress = tanh(ng @ Wn + bn)    [4000 x 300 x 512]
    gemm_k<128,64,16,8,4,1><<<dim3(ENC/64, (MROWS+127)/128), 256>>>(
        nodes_glove, nodes_glove, DIN, Wn, bn, p_nc, MROWS, DIN, ENC, nullptr);

    // query_compress = qg @ Wq + bq          [200 x 300 x 512]
    gemm_k<64,64,16,4,4,0><<<dim3(ENC/64, (QROWS+63)/64), 256>>>(
        query_glove, query_glove, DIN, Wq, bq, p_qc, QROWS, DIN, ENC, nullptr);

    // L = nc * nmask
    init_L<<<MROWS*ENC/256, 256>>>(p_nc, nlen, p_L);

    for (int h = 0; h < HOPS; h++) {
        // hm = (L @ Wh + bh) * nmask          [4000 x 512 x 512]
        gemm_k<128,64,16,8,4,2><<<dim3(ENC/64, (MROWS+127)/128), 256>>>(
            p_L, p_L, ENC, Wh, bh, p_hm, MROWS, ENC, ENC, nlen);
        // U = A2 @ hm + hm   (sparse skip)
        spmm_update<<<MROWS, 128>>>(p_A2, p_hm, p_U);
        // att = sigmoid(concat([U,L]) @ Wc + bc) * nmask   [4000 x 1024 x 512]
        gemm_k<128,64,16,8,4,3><<<dim3(ENC/64, (MROWS+127)/128), 256>>>(
            p_U, p_L, ENC, Wc, bc, p_att, MROWS, 2*ENC, ENC, nlen);
        // L = att*tanh(U) + (1-att)*L
        hop_update<<<MROWS*ENC/256, 256>>>(p_att, p_U, p_L);
    }

    // attention
    sq_kernel<<<(QROWS*32 + 255) / 256, 256>>>(p_qc, wa, p_sq);
    attn_kernel<<<MROWS, 128>>>(p_L, p_qc, wa, p_sq, p_n2q, p_smax);
    q2n_kernel<<<BATCH, 256>>>(p_smax, p_nc, p_q2n);

    // scorer
    build_g<<<MROWS*ENC/256, 256>>>(p_nc, p_n2q, p_q2n, p_g);
    // h1 = tanh(g @ W1 + b1)                  [4000 x 2048 x 128]
    gemm_k<64,64,16,4,4,1><<<dim3(2, (MROWS+63)/64), 256>>>(
        p_g, p_g, 4*ENC, W1, b1, p_h1, MROWS, 4*ENC, 128, nullptr);
    raw_kernel<<<(MROWS*32 + 255) / 256, 256>>>(p_h1, W2, b2, p_raw);

    // masked max
    out_kernel<<<(BATCH*NC*32 + 255) / 256, 256>>>(mask, p_raw, out);
}

// round 2
// speedup vs baseline: 1.8818x; 1.8818x over previous
#include <cuda_runtime.h>
#include <cstdint>

// ---------------------------------------------------------------------------
// Problem constants
// ---------------------------------------------------------------------------
#define BATCH 8
#define NNODE 500
#define NQ    25
#define ENC   512
#define DIN   300
#define NC    70
#define NET   3
#define HOPS  3
#define MROWS (BATCH*NNODE)   // 4000
#define QROWS (BATCH*NQ)      // 200

// ---------------------------------------------------------------------------
// Device scratch (module-load allocated; no cudaMalloc anywhere)
// ---------------------------------------------------------------------------
__device__ float g_nc  [MROWS*ENC];
__device__ float g_qc  [QROWS*ENC];
__device__ float g_L   [MROWS*ENC];      // last_hop ping
__device__ float g_L2  [MROWS*ENC];      // last_hop pong
__device__ float g_hm  [MROWS*ENC];
__device__ float g_U   [MROWS*ENC];
__device__ float g_A2  [BATCH*NNODE*NNODE];
__device__ float g_sq  [QROWS];
__device__ float g_n2q [MROWS*ENC];
__device__ float g_smax[MROWS];
__device__ float g_q2n [BATCH*ENC];
__device__ float g_g   [MROWS*4*ENC];
__device__ float g_h1  [MROWS*128];
__device__ float g_raw [MROWS];

// ---------------------------------------------------------------------------
// Helpers
// ---------------------------------------------------------------------------
__device__ __forceinline__ float warpSum(float v) {
#pragma unroll
    for (int o = 16; o; o >>= 1) v += __shfl_xor_sync(0xffffffffu, v, o);
    return v;
}
__device__ __forceinline__ float warpMax(float v) {
#pragma unroll
    for (int o = 16; o; o >>= 1) v = fmaxf(v, __shfl_xor_sync(0xffffffffu, v, o));
    return v;
}
__device__ __forceinline__ uint32_t f2tf(float f) {
    uint32_t u;
    asm("cvt.rna.tf32.f32 %0, %1;" : "=r"(u) : "f"(f));
    return u;
}
__device__ __forceinline__ void mma_tf32(float* c, const uint32_t* a, const uint32_t* b) {
    asm volatile(
        "mma.sync.aligned.m16n8k8.row.col.f32.tf32.tf32.f32 "
        "{%0,%1,%2,%3}, {%4,%5,%6,%7}, {%8,%9}, {%0,%1,%2,%3};"
        : "+f"(c[0]), "+f"(c[1]), "+f"(c[2]), "+f"(c[3])
        : "r"(a[0]), "r"(a[1]), "r"(a[2]), "r"(a[3]), "r"(b[0]), "r"(b[1]));
}

// ---------------------------------------------------------------------------
// Tensor-core TF32 GEMM:  pre-epilogue v = (A@W)[r,c] + bias[c]
//   A logical [M,K] split at ksplit between A (ld=ksplit) and Ab (ld=K-ksplit).
//   Requirements used here: K % 4 == 0, ksplit % 4 == 0 (all call sites obey),
//   Nn % 64 == 0 or block fully covers columns.
//   EPI 0: C = v
//   EPI 1: C = tanh(v)
//   EPI 2: C = v * nmask
//   EPI 3: att = sigmoid(v)*nmask; Lnew = att*tanh(U)+(1-att)*Lold   (C unused)
//   EPI 4: C = tanh(v); Lnew = C * nmask
// Block 256 thr (8 warps, 4x2), tile 128x64, BK=32.
// ---------------------------------------------------------------------------
template<int EPI>
__global__ void __launch_bounds__(256, 2) gemm_tc(
    const float* __restrict__ A, const float* __restrict__ Ab, int ksplit,
    const float* __restrict__ W, const float* __restrict__ bias,
    float* __restrict__ C, int M, int K, int Nn, const int* __restrict__ nlen,
    const float* __restrict__ Uin, const float* __restrict__ Lold,
    float* __restrict__ Lnew)
{
    __shared__ uint32_t As[32][129];   // [k][m], pad for conflict-free frag reads
    __shared__ uint32_t Bs[32][68];    // [k][n]

    const int tid  = threadIdx.x;
    const int lane = tid & 31, warp = tid >> 5;
    const int wm = warp >> 1, wn = warp & 1;
    const int tg = lane >> 2, tq = lane & 3;
    const int rowBlock = blockIdx.y * 128;
    const int colBlock = blockIdx.x * 64;
    const int Kb = K - ksplit;

    float acc[2][4][4];
#pragma unroll
    for (int i = 0; i < 2; i++)
#pragma unroll
        for (int j = 0; j < 4; j++)
#pragma unroll
            for (int l = 0; l < 4; l++) acc[i][j][l] = 0.f;

    for (int k0 = 0; k0 < K; k0 += 32) {
        // ---- load A tile 128x32 (4 float4 per thread) ----
        {
            int r  = tid >> 3;            // 0..31
            int kc = (tid & 7) * 4;       // 0..28
            int gk = k0 + kc;
#pragma unroll
            for (int rr = 0; rr < 4; rr++, r += 32) {
                int gr = rowBlock + r;
                float4 v = make_float4(0.f, 0.f, 0.f, 0.f);
                if (gr < M && gk < K) {
                    const float* src = (gk < ksplit)
                        ? A  + (size_t)gr * ksplit + gk
                        : Ab + (size_t)gr * Kb + (gk - ksplit);
                    v = *reinterpret_cast<const float4*>(src);
                }
                As[kc + 0][r] = f2tf(v.x);
                As[kc + 1][r] = f2tf(v.y);
                As[kc + 2][r] = f2tf(v.z);
                As[kc + 3][r] = f2tf(v.w);
            }
        }
        // ---- load B tile 32x64 (2 float4 per thread) ----
        {
            int k  = tid >> 4;            // 0..15
            int nc4 = (tid & 15) * 4;     // 0..60
#pragma unroll
            for (int kk = 0; kk < 2; kk++, k += 16) {
                int gk = k0 + k;
                float4 v = make_float4(0.f, 0.f, 0.f, 0.f);
                if (gk < K)
                    v = *reinterpret_cast<const float4*>(
                        W + (size_t)gk * Nn + colBlock + nc4);
                Bs[k][nc4 + 0] = f2tf(v.x);
                Bs[k][nc4 + 1] = f2tf(v.y);
                Bs[k][nc4 + 2] = f2tf(v.z);
                Bs[k][nc4 + 3] = f2tf(v.w);
            }
        }
        __syncthreads();

#pragma unroll
        for (int ks = 0; ks < 4; ks++) {
            const int kb = ks * 8;
            uint32_t af[2][4], bf[4][2];
#pragma unroll
            for (int mt = 0; mt < 2; mt++) {
                int r0 = wm * 32 + mt * 16 + tg;
                af[mt][0] = As[kb + tq][r0];
                af[mt][1] = As[kb + tq][r0 + 8];
                af[mt][2] = As[kb + 4 + tq][r0];
                af[mt][3] = As[kb + 4 + tq][r0 + 8];
            }
#pragma unroll
            for (int nt = 0; nt < 4; nt++) {
                int c0 = wn * 32 + nt * 8 + tg;
                bf[nt][0] = Bs[kb + tq][c0];
                bf[nt][1] = Bs[kb + 4 + tq][c0];
            }
#pragma unroll
            for (int mt = 0; mt < 2; mt++)
#pragma unroll
                for (int nt = 0; nt < 4; nt++)
                    mma_tf32(acc[mt][nt], af[mt], bf[nt]);
        }
        __syncthreads();
    }

    // ---- epilogue ----
#pragma unroll
    for (int mt = 0; mt < 2; mt++) {
#pragma unroll
        for (int half = 0; half < 2; half++) {     // c0/c1 vs c2/c3
            int r = rowBlock + wm * 32 + mt * 16 + tg + half * 8;
            if (r >= M) continue;
            float rowmask = 1.f;
            if (EPI == 2 || EPI == 3 || EPI == 4) {
                int bb = r / NNODE, ii = r - bb * NNODE;
                rowmask = (ii < nlen[bb]) ? 1.f : 0.f;
            }
#pragma unroll
            for (int nt = 0; nt < 4; nt++) {
#pragma unroll
                for (int e = 0; e < 2; e++) {
                    int c = colBlock + wn * 32 + nt * 8 + tq * 2 + e;
                    float v = acc[mt][nt][half * 2 + e] + bias[c];
                    size_t off = (size_t)r * Nn + c;
                    if (EPI == 0) {
                        C[off] = v;
                    } else if (EPI == 1) {
                        C[off] = tanhf(v);
                    } else if (EPI == 2) {
                        C[off] = v * rowmask;
                    } else if (EPI == 3) {
                        float att = rowmask / (1.f + __expf(-v));
                        Lnew[off] = att * tanhf(Uin[off]) + (1.f - att) * Lold[off];
                    } else { // EPI == 4
                        float t = tanhf(v);
                        C[off] = t;
                        Lnew[off] = t * rowmask;
                    }
                }
            }
        }
    }
}

// ---------------------------------------------------------------------------
// A2 = sum over 3 nets of adj (float4)
// ---------------------------------------------------------------------------
#define NN4 (NNODE*NNODE/4)   // 62500
__global__ void a2_kernel(const float4* __restrict__ adj, float4* __restrict__ A2)
{
    int idx = blockIdx.x * 256 + threadIdx.x;
    if (idx >= BATCH * NN4) return;
    int b = idx / NN4, r = idx - b * NN4;
    const float4* base = adj + (size_t)b * NET * NN4;
    float4 x = base[r], y = base[NN4 + r], z = base[2 * NN4 + r];
    A2[idx] = make_float4(x.x + y.x + z.x, x.y + y.y + z.y,
                          x.z + y.z + z.z, x.w + y.w + z.w);
}

// ---------------------------------------------------------------------------
// U[b,i,:] = A2[b,i,:] @ hm[b,:,:] + hm[b,i,:]   (zero-skipping over A2 row)
// ---------------------------------------------------------------------------
__global__ void spmm_update(const float* __restrict__ A2, const float* __restrict__ hm,
                            float* __restrict__ U)
{
    const int m = blockIdx.x;
    const int b = m / NNODE, i = m - b * NNODE;
    const float* arow = A2 + ((size_t)b * NNODE + i) * NNODE;
    const float* hmb  = hm + (size_t)b * NNODE * ENC;
    const int d0 = threadIdx.x * 4;
    float4 acc = *reinterpret_cast<const float4*>(hm + (size_t)m * ENC + d0);
    __shared__ float s[128];
    for (int jb = 0; jb < NNODE; jb += 128) {
        int j = jb + threadIdx.x;
        s[threadIdx.x] = (j < NNODE) ? arow[j] : 0.f;
        __syncthreads();
        int lim = min(128, NNODE - jb);
        for (int jj = 0; jj < lim; jj++) {
            float a = s[jj];
            if (a != 0.f) {
                const float4 hv = *reinterpret_cast<const float4*>(
                    hmb + (size_t)(jb + jj) * ENC + d0);
                acc.x += a * hv.x; acc.y += a * hv.y;
                acc.z += a * hv.z; acc.w += a * hv.w;
            }
        }
        __syncthreads();
    }
    *reinterpret_cast<float4*>(U + (size_t)m * ENC + d0) = acc;
}

// ---------------------------------------------------------------------------
// sq[b,q] = qc[b,q,:] . wa_q
// ---------------------------------------------------------------------------
__global__ void sq_kernel(const float* __restrict__ qc, const float* __restrict__ wa,
                          float* __restrict__ sq)
{
    int gw = (blockIdx.x * blockDim.x + threadIdx.x) >> 5;
    int lane = threadIdx.x & 31;
    if (gw >= QROWS) return;
    float s = 0.f;
    for (int d = lane; d < ENC; d += 32) s += qc[(size_t)gw * ENC + d] * wa[ENC + d];
    s = warpSum(s);
    if (lane == 0) sq[gw] = s;
}

// ---------------------------------------------------------------------------
// Per node m: sim/softmax over q; n2q; smax
// ---------------------------------------------------------------------------
__global__ void attn_kernel(const float* __restrict__ L, const float* __restrict__ qc,
                            const float* __restrict__ wa, const float* __restrict__ sq,
                            float* __restrict__ n2q, float* __restrict__ smax)
{
    const int m = blockIdx.x;
    const int b = m / NNODE;
    const int tid = threadIdx.x;           // 128
    const int lane = tid & 31, warp = tid >> 5;
    __shared__ float Lws[ENC];
    __shared__ float red[4];
    __shared__ float simv[NQ];
    __shared__ float p[NQ];

    float snp = 0.f;
#pragma unroll
    for (int d = tid; d < ENC; d += 128) {
        float v = L[(size_t)m * ENC + d];
        Lws[d] = v * wa[2 * ENC + d];
        snp += v * wa[d];
    }
    snp = warpSum(snp);
    if (lane == 0) red[warp] = snp;
    __syncthreads();
    float sn = red[0] + red[1] + red[2] + red[3];

    for (int q = warp; q < NQ; q += 4) {
        const float* qr = qc + ((size_t)b * NQ + q) * ENC;
        float s = 0.f;
        for (int d = lane; d < ENC; d += 32) s += Lws[d] * qr[d];
        s = warpSum(s);
        if (lane == 0) simv[q] = sn + sq[b * NQ + q] + s;
    }
    __syncthreads();

    if (tid < 32) {
        float v = (lane < NQ) ? simv[lane] : -1e30f;
        float mx = warpMax(v);
        float e = (lane < NQ) ? __expf(v - mx) : 0.f;
        float Z = warpSum(e);
        if (lane < NQ) p[lane] = e / Z;
        if (lane == 0) smax[m] = mx;
    }
    __syncthreads();

#pragma unroll
    for (int d = tid; d < ENC; d += 128) {
        float acc = 0.f;
#pragma unroll
        for (int q = 0; q < NQ; q++) acc += p[q] * qc[((size_t)b * NQ + q) * ENC + d];
        n2q[(size_t)m * ENC + d] = acc;
    }
}

// ---------------------------------------------------------------------------
// Per batch: bvec = softmax_n(smax); q2n = bvec @ nc
// ---------------------------------------------------------------------------
__global__ void q2n_kernel(const float* __restrict__ smax, const float* __restrict__ nc,
                           float* __restrict__ q2n)
{
    const int b = blockIdx.x;
    const int tid = threadIdx.x;            // 256
    const int lane = tid & 31, warp = tid >> 5;
    __shared__ float w[NNODE];
    __shared__ float red[8];

    float mx = -1e30f;
    for (int n = tid; n < NNODE; n += 256) mx = fmaxf(mx, smax[b * NNODE + n]);
    mx = warpMax(mx);
    if (lane == 0) red[warp] = mx;
    __syncthreads();
    float bmax = red[0];
#pragma unroll
    for (int i = 1; i < 8; i++) bmax = fmaxf(bmax, red[i]);
    __syncthreads();

    float s = 0.f;
    for (int n = tid; n < NNODE; n += 256) {
        float e = __expf(smax[b * NNODE + n] - bmax);
        w[n] = e; s += e;
    }
    s = warpSum(s);
    if (lane == 0) red[warp] = s;
    __syncthreads();
    float Z = 0.f;
#pragma unroll
    for (int i = 0; i < 8; i++) Z += red[i];
    float inv = 1.f / Z;

    const int d0 = tid * 2;
    float a0 = 0.f, a1 = 0.f;
    for (int n = 0; n < NNODE; n++) {
        float ww = w[n] * inv;
        const float2 r = *reinterpret_cast<const float2*>(
            nc + ((size_t)b * NNODE + n) * ENC + d0);
        a0 += ww * r.x; a1 += ww * r.y;
    }
    q2n[b * ENC + d0]     = a0;
    q2n[b * ENC + d0 + 1] = a1;
}

// ---------------------------------------------------------------------------
// g = [nc, n2q, nc*n2q, nc*q2n]
// ---------------------------------------------------------------------------
__global__ void build_g(const float* __restrict__ nc, const float* __restrict__ n2q,
                        const float* __restrict__ q2n, float* __restrict__ g)
{
    int idx = blockIdx.x * 256 + threadIdx.x;
    int m = idx >> 9, d = idx & 511;
    int b = m / NNODE;
    float a = nc[idx], t = n2q[idx], qn = q2n[b * ENC + d];
    size_t base = (size_t)m * (4 * ENC) + d;
    g[base]           = a;
    g[base + ENC]     = t;
    g[base + 2 * ENC] = a * t;
    g[base + 3 * ENC] = a * qn;
}

// ---------------------------------------------------------------------------
// raw[m] = h1[m,:].W2 + b2
// ---------------------------------------------------------------------------
__global__ void raw_kernel(const float* __restrict__ h1, const float* __restrict__ W2,
                           const float* __restrict__ b2, float* __restrict__ raw)
{
    int gw = (blockIdx.x * blockDim.x + threadIdx.x) >> 5;
    int lane = threadIdx.x & 31;
    if (gw >= MROWS) return;
    float s = 0.f;
    for (int h = lane; h < 128; h += 32) s += h1[(size_t)gw * 128 + h] * W2[h];
    s = warpSum(s);
    if (lane == 0) raw[gw] = s + b2[0];
}

// ---------------------------------------------------------------------------
// out[b,c] = max_n f(mask*raw),  f(0) = -1e6
// ---------------------------------------------------------------------------
__global__ void out_kernel(const int* __restrict__ mask, const float* __restrict__ raw,
                           float* __restrict__ out)
{
    int gw = (blockIdx.x * blockDim.x + threadIdx.x) >> 5;
    int lane = threadIdx.x & 31;
    if (gw >= BATCH * NC) return;
    int b = gw / NC, c = gw - b * NC;
    const int* mr = mask + ((size_t)b * NC + c) * NNODE;
    const float* rr = raw + b * NNODE;
    float mx = -1e30f;
    for (int n = lane; n < NNODE; n += 32) {
        float p = (float)mr[n] * rr[n];
        if (p == 0.f) p = -1e6f;
        mx = fmaxf(mx, p);
    }
    mx = warpMax(mx);
    if (lane == 0) out[gw] = mx;
}

// ---------------------------------------------------------------------------
// Launch
// ---------------------------------------------------------------------------
extern "C" void kernel_launch(void* const* d_in, const int* in_sizes, int n_in,
                              void* d_out, int out_size)
{
    const float* nodes_glove = (const float*)d_in[0];
    const float* query_glove = (const float*)d_in[1];
    const float* adj         = (const float*)d_in[2];
    const int*   nlen        = (const int*)  d_in[3];
    const int*   mask        = (const int*)  d_in[4];
    const float* Wn = (const float*)d_in[5];
    const float* bn = (const float*)d_in[6];
    const float* Wq = (const float*)d_in[7];
    const float* bq = (const float*)d_in[8];
    const float* Wh = (const float*)d_in[9];
    const float* bh = (const float*)d_in[10];
    const float* Wc = (const float*)d_in[11];
    const float* bc = (const float*)d_in[12];
    const float* wa = (const float*)d_in[13];
    const float* W1 = (const float*)d_in[14];
    const float* b1 = (const float*)d_in[15];
    const float* W2 = (const float*)d_in[16];
    const float* b2 = (const float*)d_in[17];
    float* out = (float*)d_out;

    float *p_nc, *p_qc, *p_L, *p_L2, *p_hm, *p_U, *p_A2, *p_sq,
          *p_n2q, *p_smax, *p_q2n, *p_g, *p_h1, *p_raw;
    cudaGetSymbolAddress((void**)&p_nc,  g_nc);
    cudaGetSymbolAddress((void**)&p_qc,  g_qc);
    cudaGetSymbolAddress((void**)&p_L,   g_L);
    cudaGetSymbolAddress((void**)&p_L2,  g_L2);
    cudaGetSymbolAddress((void**)&p_hm,  g_hm);
    cudaGetSymbolAddress((void**)&p_U,   g_U);
    cudaGetSymbolAddress((void**)&p_A2,  g_A2);
    cudaGetSymbolAddress((void**)&p_sq,  g_sq);
    cudaGetSymbolAddress((void**)&p_n2q, g_n2q);
    cudaGetSymbolAddress((void**)&p_smax,g_smax);
    cudaGetSymbolAddress((void**)&p_q2n, g_q2n);
    cudaGetSymbolAddress((void**)&p_g,   g_g);
    cudaGetSymbolAddress((void**)&p_h1,  g_h1);
    cudaGetSymbolAddress((void**)&p_raw, g_raw);

    // A2 = sum_e adj
    a2_kernel<<<(BATCH*NN4 + 255) / 256, 256>>>(
        (const float4*)adj, (float4*)p_A2);

    // nodes_compress = tanh(ng @ Wn + bn), L = nc*nmask   [4000 x 300 x 512]
    gemm_tc<4><<<dim3(ENC/64, 32), 256>>>(
        nodes_glove, nodes_glove, DIN, Wn, bn, p_nc, MROWS, DIN, ENC, nlen,
        nullptr, nullptr, p_L);

    // query_compress = qg @ Wq + bq   [200 x 300 x 512]
    gemm_tc<0><<<dim3(ENC/64, 2), 256>>>(
        query_glove, query_glove, DIN, Wq, bq, p_qc, QROWS, DIN, ENC, nullptr,
        nullptr, nullptr, nullptr);

    float* Lc = p_L;
    float* Ln = p_L2;
    for (int h = 0; h < HOPS; h++) {
        // hm = (L @ Wh + bh) * nmask   [4000 x 512 x 512]
        gemm_tc<2><<<dim3(ENC/64, 32), 256>>>(
            Lc, Lc, ENC, Wh, bh, p_hm, MROWS, ENC, ENC, nlen,
            nullptr, nullptr, nullptr);
        // U = A2 @ hm + hm
        spmm_update<<<MROWS, 128>>>(p_A2, p_hm, p_U);
        // fused: att = sigmoid(concat([U,L]) @ Wc + bc)*nmask;
        //        Ln = att*tanh(U) + (1-att)*Lc          [4000 x 1024 x 512]
        gemm_tc<3><<<dim3(ENC/64, 32), 256>>>(
            p_U, Lc, ENC, Wc, bc, p_hm /*unused*/, MROWS, 2*ENC, ENC, nlen,
            p_U, Lc, Ln);
        float* t = Lc; Lc = Ln; Ln = t;
    }

    // attention (final L is in Lc)
    sq_kernel<<<(QROWS*32 + 255) / 256, 256>>>(p_qc, wa, p_sq);
    attn_kernel<<<MROWS, 128>>>(Lc, p_qc, wa, p_sq, p_n2q, p_smax);
    q2n_kernel<<<BATCH, 256>>>(p_smax, p_nc, p_q2n);

    // scorer
    build_g<<<MROWS*ENC/256, 256>>>(p_nc, p_n2q, p_q2n, p_g);
    // h1 = tanh(g @ W1 + b1)   [4000 x 2048 x 128]
    gemm_tc<1><<<dim3(2, 32), 256>>>(
        p_g, p_g, 4*ENC, W1, b1, p_h1, MROWS, 4*ENC, 128, nullptr,
        nullptr, nullptr, nullptr);
    raw_kernel<<<(MROWS*32 + 255) / 256, 256>>>(p_h1, W2, b2, p_raw);

    // masked max
    out_kernel<<<(BATCH*NC*32 + 255) / 256, 256>>>(mask, p_raw, out);
}

// round 3
// speedup vs baseline: 2.2082x; 1.1735x over previous
#include <cuda_runtime.h>
#include <cstdint>

// ---------------------------------------------------------------------------
// Problem constants
// ---------------------------------------------------------------------------
#define BATCH 8
#define NNODE 500
#define NQ    25
#define ENC   512
#define DIN   300
#define NC    70
#define NET   3
#define HOPS  3
#define MROWS (BATCH*NNODE)   // 4000
#define QROWS (BATCH*NQ)      // 200

// ---------------------------------------------------------------------------
// Device scratch
// ---------------------------------------------------------------------------
__device__ float g_nc  [MROWS*ENC];
__device__ float g_qc  [QROWS*ENC];
__device__ float g_L   [MROWS*ENC];
__device__ float g_L2  [MROWS*ENC];
__device__ float g_hm  [MROWS*ENC];
__device__ float g_U   [MROWS*ENC];
__device__ float g_A2  [BATCH*NNODE*NNODE];
__device__ float g_sq  [QROWS];
__device__ float g_n2q [MROWS*ENC];
__device__ float g_smax[MROWS];
__device__ float g_q2n [BATCH*ENC];
__device__ float g_g   [MROWS*4*ENC];
__device__ float g_h1p [4*MROWS*128];   // split-K partials for W1 GEMM
__device__ float g_raw [MROWS];

// ---------------------------------------------------------------------------
// Helpers
// ---------------------------------------------------------------------------
__device__ __forceinline__ float warpSum(float v) {
#pragma unroll
    for (int o = 16; o; o >>= 1) v += __shfl_xor_sync(0xffffffffu, v, o);
    return v;
}
__device__ __forceinline__ float warpMax(float v) {
#pragma unroll
    for (int o = 16; o; o >>= 1) v = fmaxf(v, __shfl_xor_sync(0xffffffffu, v, o));
    return v;
}
// round-to-nearest tf32, returned as float (low 13 mantissa bits zero)
__device__ __forceinline__ float tf32r(float f) {
    uint32_t u;
    asm("cvt.rna.tf32.f32 %0, %1;" : "=r"(u) : "f"(f));
    return __uint_as_float(u);
}
__device__ __forceinline__ void mma_tf32(float* c, const uint32_t* a, const uint32_t* b) {
    asm volatile(
        "mma.sync.aligned.m16n8k8.row.col.f32.tf32.tf32.f32 "
        "{%0,%1,%2,%3}, {%4,%5,%6,%7}, {%8,%9}, {%0,%1,%2,%3};"
        : "+f"(c[0]), "+f"(c[1]), "+f"(c[2]), "+f"(c[3])
        : "r"(a[0]), "r"(a[1]), "r"(a[2]), "r"(a[3]), "r"(b[0]), "r"(b[1]));
}
__device__ __forceinline__ uint32_t smem_u32(const void* p) {
    return (uint32_t)__cvta_generic_to_shared(p);
}
__device__ __forceinline__ void cp_async16(uint32_t dst, const void* src, int sz) {
    asm volatile("cp.async.ca.shared.global [%0], [%1], 16, %2;\n"
                 :: "r"(dst), "l"(src), "r"(sz));
}
__device__ __forceinline__ void cp_commit() {
    asm volatile("cp.async.commit_group;\n" ::: "memory");
}
__device__ __forceinline__ void cp_wait0() {
    asm volatile("cp.async.wait_group 0;\n" ::: "memory");
}

// ---------------------------------------------------------------------------
// TF32 tensor-core GEMM, cp.async double-buffered.
//   Tile 128x64, BK=16, 4 warps (each warp: 32 rows x 64 cols).
//   Logical A [M,Ktot] split at ksplit between A(lda) and Ab(ldab).
//   blockIdx.z = split-K chunk index; chunk size = K; kBase = z*K.
//   v = (A@W)[r,c] (+bias unless EPI 5)
//   EPI 0: C=v+bias      EPI 2: C=(v+bias)*nmask
//   EPI 3: att=sig(v+bias)*nmask; Lnew=tf32r(att*tanh(U)+(1-att)*Lold)
//   EPI 4: C=tanh(v+bias); Lnew=tf32r(C)*nmask
//   EPI 5: C[z partial slab] = v   (no bias)
// ---------------------------------------------------------------------------
template<int EPI>
__global__ void __launch_bounds__(128, 4) gemm_tc(
    const float* __restrict__ A, int lda,
    const float* __restrict__ Ab, int ldab, int ksplit,
    const float* __restrict__ W, int ldw,
    const float* __restrict__ bias,
    float* __restrict__ C, int ldc, int M, int K,
    const int* __restrict__ nlen,
    const float* __restrict__ Uin, const float* __restrict__ Lold,
    float* __restrict__ Lnew)
{
    __shared__ uint32_t As[2][128][20];   // [m][k] pad->stride 20 (conflict-free)
    __shared__ uint32_t Bs[2][16][72];    // [k][n] pad->stride 72 (conflict-free)

    const int tid  = threadIdx.x;
    const int lane = tid & 31, warp = tid >> 5;      // 4 warps
    const int tg = lane >> 2, tq = lane & 3;
    const int rowBlock = blockIdx.y * 128;
    const int colBlock = blockIdx.x * 64;
    const int z = blockIdx.z;
    const int kBase = z * K;

    float acc[2][8][4];
#pragma unroll
    for (int i = 0; i < 2; i++)
#pragma unroll
        for (int j = 0; j < 8; j++)
#pragma unroll
            for (int l = 0; l < 4; l++) acc[i][j][l] = 0.f;

    auto loadTiles = [&](int k0, int buf) {
        // A tile 128x16: 512 16B chunks, 4 per thread
#pragma unroll
        for (int it = 0; it < 4; it++) {
            int idx = it * 128 + tid;
            int m = idx >> 2, cc = idx & 3;
            int gr = rowBlock + m;
            int kk = k0 + cc * 4;
            int gkl = kBase + kk;
            const float* src = (gkl < ksplit)
                ? A  + (size_t)gr * lda  + gkl
                : Ab + (size_t)gr * ldab + (gkl - ksplit);
            int sz = (gr < M && kk < K) ? 16 : 0;
            cp_async16(smem_u32(&As[buf][m][cc * 4]), src, sz);
        }
        // B tile 16x64: 256 chunks, 2 per thread
#pragma unroll
        for (int it = 0; it < 2; it++) {
            int idx = it * 128 + tid;
            int k = idx >> 4, cc = idx & 15;
            int kk = k0 + k;
            const float* src = W + (size_t)(kBase + kk) * ldw + colBlock + cc * 4;
            int sz = (kk < K) ? 16 : 0;
            cp_async16(smem_u32(&Bs[buf][k][cc * 4]), src, sz);
        }
        cp_commit();
    };

    const int nsteps = (K + 15) / 16;
    loadTiles(0, 0);
    int buf = 0;

    for (int s = 0; s < nsteps; s++) {
        cp_wait0();
        __syncthreads();
        if (s + 1 < nsteps) loadTiles((s + 1) * 16, buf ^ 1);

#pragma unroll
        for (int ks = 0; ks < 2; ks++) {
            const int kb = ks * 8;
            uint32_t af[2][4], bf[8][2];
#pragma unroll
            for (int mt = 0; mt < 2; mt++) {
                int r0 = warp * 32 + mt * 16 + tg;
                af[mt][0] = As[buf][r0    ][kb + tq];
                af[mt][1] = As[buf][r0 + 8][kb + tq];
                af[mt][2] = As[buf][r0    ][kb + tq + 4];
                af[mt][3] = As[buf][r0 + 8][kb + tq + 4];
            }
#pragma unroll
            for (int nt = 0; nt < 8; nt++) {
                int c0 = nt * 8 + tg;
                bf[nt][0] = Bs[buf][kb + tq    ][c0];
                bf[nt][1] = Bs[buf][kb + tq + 4][c0];
            }
#pragma unroll
            for (int mt = 0; mt < 2; mt++)
#pragma unroll
                for (int nt = 0; nt < 8; nt++)
                    mma_tf32(acc[mt][nt], af[mt], bf[nt]);
        }
        buf ^= 1;
    }

    // ---- epilogue ----
#pragma unroll
    for (int mt = 0; mt < 2; mt++) {
#pragma unroll
        for (int half = 0; half < 2; half++) {
            int r = rowBlock + warp * 32 + mt * 16 + tg + half * 8;
            if (r >= M) continue;
            float rowmask = 1.f;
            if (EPI == 2 || EPI == 3 || EPI == 4) {
                int bb = r / NNODE, ii = r - bb * NNODE;
                rowmask = (ii < nlen[bb]) ? 1.f : 0.f;
            }
#pragma unroll
            for (int nt = 0; nt < 8; nt++) {
#pragma unroll
                for (int e = 0; e < 2; e++) {
                    int c = colBlock + nt * 8 + tq * 2 + e;
                    float v = acc[mt][nt][half * 2 + e];
                    if (EPI != 5) v += bias[c];
                    size_t off = (size_t)r * ldc + c;
                    if (EPI == 0) {
                        C[off] = v;
                    } else if (EPI == 2) {
                        C[off] = v * rowmask;
                    } else if (EPI == 3) {
                        float att = rowmask / (1.f + __expf(-v));
                        Lnew[off] = tf32r(att * tanhf(Uin[off]) +
                                          (1.f - att) * Lold[off]);
                    } else if (EPI == 4) {
                        float t = tanhf(v);
                        C[off] = t;
                        Lnew[off] = tf32r(t) * rowmask;
                    } else { // EPI 5: split-K partial slab z
                        C[((size_t)z * M + r) * ldc + c] = v;
                    }
                }
            }
        }
    }
}

// ---------------------------------------------------------------------------
// A2 = sum over 3 nets of adj (float4)
// ---------------------------------------------------------------------------
#define NN4 (NNODE*NNODE/4)   // 62500
__global__ void a2_kernel(const float4* __restrict__ adj, float4* __restrict__ A2)
{
    int idx = blockIdx.x * 256 + threadIdx.x;
    if (idx >= BATCH * NN4) return;
    int b = idx / NN4, r = idx - b * NN4;
    const float4* base = adj + (size_t)b * NET * NN4;
    float4 x = base[r], y = base[NN4 + r], z = base[2 * NN4 + r];
    A2[idx] = make_float4(x.x + y.x + z.x, x.y + y.y + z.y,
                          x.z + y.z + z.z, x.w + y.w + z.w);
}

// ---------------------------------------------------------------------------
// U[b,i,:] = A2[b,i,:] @ hm[b,:,:] + hm[b,i,:]  (zero-skipping) ; U tf32-rounded
// ---------------------------------------------------------------------------
__global__ void spmm_update(const float* __restrict__ A2, const float* __restrict__ hm,
                            float* __restrict__ U)
{
    const int m = blockIdx.x;
    const int b = m / NNODE, i = m - b * NNODE;
    const float* arow = A2 + ((size_t)b * NNODE + i) * NNODE;
    const float* hmb  = hm + (size_t)b * NNODE * ENC;
    const int d0 = threadIdx.x * 4;
    float4 acc = *reinterpret_cast<const float4*>(hm + (size_t)m * ENC + d0);
    __shared__ float s[128];
    for (int jb = 0; jb < NNODE; jb += 128) {
        int j = jb + threadIdx.x;
        s[threadIdx.x] = (j < NNODE) ? arow[j] : 0.f;
        __syncthreads();
        int lim = min(128, NNODE - jb);
        for (int jj = 0; jj < lim; jj++) {
            float a = s[jj];
            if (a != 0.f) {
                const float4 hv = *reinterpret_cast<const float4*>(
                    hmb + (size_t)(jb + jj) * ENC + d0);
                acc.x += a * hv.x; acc.y += a * hv.y;
                acc.z += a * hv.z; acc.w += a * hv.w;
            }
        }
        __syncthreads();
    }
    acc.x = tf32r(acc.x); acc.y = tf32r(acc.y);
    acc.z = tf32r(acc.z); acc.w = tf32r(acc.w);
    *reinterpret_cast<float4*>(U + (size_t)m * ENC + d0) = acc;
}

// ---------------------------------------------------------------------------
// sq[b,q] = qc[b,q,:] . wa_q
// ---------------------------------------------------------------------------
__global__ void sq_kernel(const float* __restrict__ qc, const float* __restrict__ wa,
                          float* __restrict__ sq)
{
    int gw = (blockIdx.x * blockDim.x + threadIdx.x) >> 5;
    int lane = threadIdx.x & 31;
    if (gw >= QROWS) return;
    float s = 0.f;
    for (int d = lane; d < ENC; d += 32) s += qc[(size_t)gw * ENC + d] * wa[ENC + d];
    s = warpSum(s);
    if (lane == 0) sq[gw] = s;
}

// ---------------------------------------------------------------------------
// Per node m: sim/softmax over q; n2q; smax
// ---------------------------------------------------------------------------
__global__ void attn_kernel(const float* __restrict__ L, const float* __restrict__ qc,
                            const float* __restrict__ wa, const float* __restrict__ sq,
                            float* __restrict__ n2q, float* __restrict__ smax)
{
    const int m = blockIdx.x;
    const int b = m / NNODE;
    const int tid = threadIdx.x;           // 128
    const int lane = tid & 31, warp = tid >> 5;
    __shared__ float Lws[ENC];
    __shared__ float red[4];
    __shared__ float simv[NQ];
    __shared__ float p[NQ];

    float snp = 0.f;
#pragma unroll
    for (int d = tid; d < ENC; d += 128) {
        float v = L[(size_t)m * ENC + d];
        Lws[d] = v * wa[2 * ENC + d];
        snp += v * wa[d];
    }
    snp = warpSum(snp);
    if (lane == 0) red[warp] = snp;
    __syncthreads();
    float sn = red[0] + red[1] + red[2] + red[3];

    for (int q = warp; q < NQ; q += 4) {
        const float* qr = qc + ((size_t)b * NQ + q) * ENC;
        float s = 0.f;
        for (int d = lane; d < ENC; d += 32) s += Lws[d] * qr[d];
        s = warpSum(s);
        if (lane == 0) simv[q] = sn + sq[b * NQ + q] + s;
    }
    __syncthreads();

    if (tid < 32) {
        float v = (lane < NQ) ? simv[lane] : -1e30f;
        float mx = warpMax(v);
        float e = (lane < NQ) ? __expf(v - mx) : 0.f;
        float Z = warpSum(e);
        if (lane < NQ) p[lane] = e / Z;
        if (lane == 0) smax[m] = mx;
    }
    __syncthreads();

#pragma unroll
    for (int d = tid; d < ENC; d += 128) {
        float acc = 0.f;
#pragma unroll
        for (int q = 0; q < NQ; q++) acc += p[q] * qc[((size_t)b * NQ + q) * ENC + d];
        n2q[(size_t)m * ENC + d] = acc;
    }
}

// ---------------------------------------------------------------------------
// Per batch: bvec = softmax_n(smax); q2n = bvec @ nc
// ---------------------------------------------------------------------------
__global__ void q2n_kernel(const float* __restrict__ smax, const float* __restrict__ nc,
                           float* __restrict__ q2n)
{
    const int b = blockIdx.x;
    const int tid = threadIdx.x;            // 256
    const int lane = tid & 31, warp = tid >> 5;
    __shared__ float w[NNODE];
    __shared__ float red[8];

    float mx = -1e30f;
    for (int n = tid; n < NNODE; n += 256) mx = fmaxf(mx, smax[b * NNODE + n]);
    mx = warpMax(mx);
    if (lane == 0) red[warp] = mx;
    __syncthreads();
    float bmax = red[0];
#pragma unroll
    for (int i = 1; i < 8; i++) bmax = fmaxf(bmax, red[i]);
    __syncthreads();

    float s = 0.f;
    for (int n = tid; n < NNODE; n += 256) {
        float e = __expf(smax[b * NNODE + n] - bmax);
        w[n] = e; s += e;
    }
    s = warpSum(s);
    if (lane == 0) red[warp] = s;
    __syncthreads();
    float Z = 0.f;
#pragma unroll
    for (int i = 0; i < 8; i++) Z += red[i];
    float inv = 1.f / Z;

    const int d0 = tid * 2;
    float a0 = 0.f, a1 = 0.f;
    for (int n = 0; n < NNODE; n++) {
        float ww = w[n] * inv;
        const float2 r = *reinterpret_cast<const float2*>(
            nc + ((size_t)b * NNODE + n) * ENC + d0);
        a0 += ww * r.x; a1 += ww * r.y;
    }
    q2n[b * ENC + d0]     = a0;
    q2n[b * ENC + d0 + 1] = a1;
}

// ---------------------------------------------------------------------------
// g = [nc, n2q, nc*n2q, nc*q2n], tf32-rounded (feeds W1 GEMM)
// ---------------------------------------------------------------------------
__global__ void build_g(const float* __restrict__ nc, const float* __restrict__ n2q,
                        const float* __restrict__ q2n, float* __restrict__ g)
{
    int idx = blockIdx.x * 256 + threadIdx.x;
    int m = idx >> 9, d = idx & 511;
    int b = m / NNODE;
    float a = nc[idx], t = n2q[idx], qn = q2n[b * ENC + d];
    size_t base = (size_t)m * (4 * ENC) + d;
    g[base]           = tf32r(a);
    g[base + ENC]     = tf32r(t);
    g[base + 2 * ENC] = tf32r(a * t);
    g[base + 3 * ENC] = tf32r(a * qn);
}

// ---------------------------------------------------------------------------
// raw[m] = sum_h tanh(sum_s h1p[s][m][h] + b1[h]) * W2[h] + b2
// ---------------------------------------------------------------------------
__global__ void raw2_kernel(const float* __restrict__ h1p, const float* __restrict__ b1,
                            const float* __restrict__ W2, const float* __restrict__ b2,
                            float* __restrict__ raw)
{
    int gw = (blockIdx.x * blockDim.x + threadIdx.x) >> 5;
    int lane = threadIdx.x & 31;
    if (gw >= MROWS) return;
    const size_t stride = (size_t)MROWS * 128;
    float s = 0.f;
    for (int h = lane; h < 128; h += 32) {
        size_t o = (size_t)gw * 128 + h;
        float v = h1p[o] + h1p[o + stride] + h1p[o + 2*stride] + h1p[o + 3*stride]
                + b1[h];
        s += tanhf(v) * W2[h];
    }
    s = warpSum(s);
    if (lane == 0) raw[gw] = s + b2[0];
}

// ---------------------------------------------------------------------------
// out[b,c] = max_n f(mask*raw),  f(0) = -1e6
// ---------------------------------------------------------------------------
__global__ void out_kernel(const int* __restrict__ mask, const float* __restrict__ raw,
                           float* __restrict__ out)
{
    int gw = (blockIdx.x * blockDim.x + threadIdx.x) >> 5;
    int lane = threadIdx.x & 31;
    if (gw >= BATCH * NC) return;
    int b = gw / NC, c = gw - b * NC;
    const int* mr = mask + ((size_t)b * NC + c) * NNODE;
    const float* rr = raw + b * NNODE;
    float mx = -1e30f;
    for (int n = lane; n < NNODE; n += 32) {
        float p = (float)mr[n] * rr[n];
        if (p == 0.f) p = -1e6f;
        mx = fmaxf(mx, p);
    }
    mx = warpMax(mx);
    if (lane == 0) out[gw] = mx;
}

// ---------------------------------------------------------------------------
// Launch
// ---------------------------------------------------------------------------
extern "C" void kernel_launch(void* const* d_in, const int* in_sizes, int n_in,
                              void* d_out, int out_size)
{
    const float* nodes_glove = (const float*)d_in[0];
    const float* query_glove = (const float*)d_in[1];
    const float* adj         = (const float*)d_in[2];
    const int*   nlen        = (const int*)  d_in[3];
    const int*   mask        = (const int*)  d_in[4];
    const float* Wn = (const float*)d_in[5];
    const float* bn = (const float*)d_in[6];
    const float* Wq = (const float*)d_in[7];
    const float* bq = (const float*)d_in[8];
    const float* Wh = (const float*)d_in[9];
    const float* bh = (const float*)d_in[10];
    const float* Wc = (const float*)d_in[11];
    const float* bc = (const float*)d_in[12];
    const float* wa = (const float*)d_in[13];
    const float* W1 = (const float*)d_in[14];
    const float* b1 = (const float*)d_in[15];
    const float* W2 = (const float*)d_in[16];
    const float* b2 = (const float*)d_in[17];
    float* out = (float*)d_out;

    float *p_nc, *p_qc, *p_L, *p_L2, *p_hm, *p_U, *p_A2, *p_sq,
          *p_n2q, *p_smax, *p_q2n, *p_g, *p_h1p, *p_raw;
    cudaGetSymbolAddress((void**)&p_nc,  g_nc);
    cudaGetSymbolAddress((void**)&p_qc,  g_qc);
    cudaGetSymbolAddress((void**)&p_L,   g_L);
    cudaGetSymbolAddress((void**)&p_L2,  g_L2);
    cudaGetSymbolAddress((void**)&p_hm,  g_hm);
    cudaGetSymbolAddress((void**)&p_U,   g_U);
    cudaGetSymbolAddress((void**)&p_A2,  g_A2);
    cudaGetSymbolAddress((void**)&p_sq,  g_sq);
    cudaGetSymbolAddress((void**)&p_n2q, g_n2q);
    cudaGetSymbolAddress((void**)&p_smax,g_smax);
    cudaGetSymbolAddress((void**)&p_q2n, g_q2n);
    cudaGetSymbolAddress((void**)&p_g,   g_g);
    cudaGetSymbolAddress((void**)&p_h1p, g_h1p);
    cudaGetSymbolAddress((void**)&p_raw, g_raw);

    // A2 = sum_e adj
    a2_kernel<<<(BATCH*NN4 + 255) / 256, 256>>>(
        (const float4*)adj, (float4*)p_A2);

    // nodes_compress = tanh(ng @ Wn + bn); L = tf32r(nc)*nmask
    gemm_tc<4><<<dim3(ENC/64, 32, 1), 128>>>(
        nodes_glove, DIN, nodes_glove, DIN, DIN, Wn, ENC, bn,
        p_nc, ENC, MROWS, DIN, nlen, nullptr, nullptr, p_L);

    // query_compress = qg @ Wq + bq
    gemm_tc<0><<<dim3(ENC/64, 2, 1), 128>>>(
        query_glove, DIN, query_glove, DIN, DIN, Wq, ENC, bq,
        p_qc, ENC, QROWS, DIN, nullptr, nullptr, nullptr, nullptr);

    float* Lc = p_L;
    float* Ln = p_L2;
    for (int h = 0; h < HOPS; h++) {
        // hm = (L @ Wh + bh) * nmask
        gemm_tc<2><<<dim3(ENC/64, 32, 1), 128>>>(
            Lc, ENC, Lc, ENC, ENC, Wh, ENC, bh,
            p_hm, ENC, MROWS, ENC, nlen, nullptr, nullptr, nullptr);
        // U = A2 @ hm + hm
        spmm_update<<<MROWS, 128>>>(p_A2, p_hm, p_U);
        // att = sigmoid([U,L] @ Wc + bc)*nmask; Ln = att*tanh(U)+(1-att)*Lc
        gemm_tc<3><<<dim3(ENC/64, 32, 1), 128>>>(
            p_U, ENC, Lc, ENC, ENC, Wc, ENC, bc,
            nullptr, ENC, MROWS, 2*ENC, nlen, p_U, Lc, Ln);
        float* t = Lc; Lc = Ln; Ln = t;
    }

    // attention
    sq_kernel<<<(QROWS*32 + 255) / 256, 256>>>(p_qc, wa, p_sq);
    attn_kernel<<<MROWS, 128>>>(Lc, p_qc, wa, p_sq, p_n2q, p_smax);
    q2n_kernel<<<BATCH, 256>>>(p_smax, p_nc, p_q2n);

    // scorer
    build_g<<<MROWS*ENC/256, 256>>>(p_nc, p_n2q, p_q2n, p_g);
    // h1 partials: split-K=4 over K=2048 (chunk 512), grid (2,32,4)
    gemm_tc<5><<<dim3(128/64, 32, 4), 128>>>(
        p_g, 4*ENC, p_g, 4*ENC, 4*ENC, W1, 128, nullptr,
        p_h1p, 128, MROWS, 512, nullptr, nullptr, nullptr, nullptr);
    raw2_kernel<<<(MROWS*32 + 255) / 256, 256>>>(p_h1p, b1, W2, b2, p_raw);

    // masked max
    out_kernel<<<(BATCH*NC*32 + 255) / 256, 256>>>(mask, p_raw, out);
}

// round 4
// speedup vs baseline: 3.8350x; 1.7367x over previous
#include <cuda_runtime.h>
#include <cstdint>

// ---------------------------------------------------------------------------
// Problem constants
// ---------------------------------------------------------------------------
#define BATCH 8
#define NNODE 500
#define NQ    25
#define ENC   512
#define DIN   300
#define NC    70
#define NET   3
#define HOPS  3
#define MROWS (BATCH*NNODE)   // 4000
#define QROWS (BATCH*NQ)      // 200
#define MAXNZ 192

// ---------------------------------------------------------------------------
// Device scratch
// ---------------------------------------------------------------------------
__device__ float g_nc  [MROWS*ENC];
__device__ float g_qc  [QROWS*ENC];
__device__ float g_L   [MROWS*ENC];
__device__ float g_L2  [MROWS*ENC];
__device__ float g_hm  [MROWS*ENC];
__device__ float g_U   [MROWS*ENC];
__device__ float g_sq  [QROWS];
__device__ float g_n2q [MROWS*ENC];
__device__ float g_smax[MROWS];
__device__ float g_q2n [BATCH*ENC];
__device__ float g_g   [MROWS*4*ENC];
__device__ float g_h1p [4*MROWS*128];
__device__ float g_raw [MROWS];
// tf32-rounded copies of inputs
__device__ float g_Wnr [DIN*ENC];
__device__ float g_Wqr [DIN*ENC];
__device__ float g_Whr [ENC*ENC];
__device__ float g_Wcr [2*ENC*ENC];
__device__ float g_W1r [4*ENC*128];
__device__ float g_ngr [MROWS*DIN];
__device__ float g_qgr [QROWS*DIN];
// adjacency sparsity
__device__ int   g_nzc [MROWS];
__device__ int   g_nzi [MROWS*MAXNZ];
__device__ float g_nzv [MROWS*MAXNZ];

// ---------------------------------------------------------------------------
// Helpers
// ---------------------------------------------------------------------------
__device__ __forceinline__ float warpSum(float v) {
#pragma unroll
    for (int o = 16; o; o >>= 1) v += __shfl_xor_sync(0xffffffffu, v, o);
    return v;
}
__device__ __forceinline__ float warpMax(float v) {
#pragma unroll
    for (int o = 16; o; o >>= 1) v = fmaxf(v, __shfl_xor_sync(0xffffffffu, v, o));
    return v;
}
__device__ __forceinline__ float tf32r(float f) {
    uint32_t u;
    asm("cvt.rna.tf32.f32 %0, %1;" : "=r"(u) : "f"(f));
    return __uint_as_float(u);
}
__device__ __forceinline__ void mma_tf32(float* c, const uint32_t* a, const uint32_t* b) {
    asm volatile(
        "mma.sync.aligned.m16n8k8.row.col.f32.tf32.tf32.f32 "
        "{%0,%1,%2,%3}, {%4,%5,%6,%7}, {%8,%9}, {%0,%1,%2,%3};"
        : "+f"(c[0]), "+f"(c[1]), "+f"(c[2]), "+f"(c[3])
        : "r"(a[0]), "r"(a[1]), "r"(a[2]), "r"(a[3]), "r"(b[0]), "r"(b[1]));
}
__device__ __forceinline__ uint32_t smem_u32(const void* p) {
    return (uint32_t)__cvta_generic_to_shared(p);
}
__device__ __forceinline__ void cp_async16(uint32_t dst, const void* src, int sz) {
    asm volatile("cp.async.ca.shared.global [%0], [%1], 16, %2;\n"
                 :: "r"(dst), "l"(src), "r"(sz));
}
__device__ __forceinline__ void cp_commit() {
    asm volatile("cp.async.commit_group;\n" ::: "memory");
}
__device__ __forceinline__ void cp_wait0() {
    asm volatile("cp.async.wait_group 0;\n" ::: "memory");
}

// ---------------------------------------------------------------------------
// Round all GEMM operand inputs to tf32 (rna), once.
// Segment table (float4 units): Wn 38400 | Wq 38400 | Wh 65536 | Wc 131072 |
//   W1 65536 | ng 300000 | qg 15000 ; total 653944
// ---------------------------------------------------------------------------
__global__ void round_inputs(
    const float4* __restrict__ Wn, const float4* __restrict__ Wq,
    const float4* __restrict__ Wh, const float4* __restrict__ Wc,
    const float4* __restrict__ W1, const float4* __restrict__ ng,
    const float4* __restrict__ qg,
    float4* __restrict__ oWn, float4* __restrict__ oWq, float4* __restrict__ oWh,
    float4* __restrict__ oWc, float4* __restrict__ oW1, float4* __restrict__ ong,
    float4* __restrict__ oqg)
{
    int idx = blockIdx.x * 256 + threadIdx.x;
    const float4* src; float4* dst; int off;
    if      (idx < 38400)  { src = Wn; dst = oWn; off = idx; }
    else if (idx < 76800)  { src = Wq; dst = oWq; off = idx - 38400; }
    else if (idx < 142336) { src = Wh; dst = oWh; off = idx - 76800; }
    else if (idx < 273408) { src = Wc; dst = oWc; off = idx - 142336; }
    else if (idx < 338944) { src = W1; dst = oW1; off = idx - 273408; }
    else if (idx < 638944) { src = ng; dst = ong; off = idx - 338944; }
    else if (idx < 653944) { src = qg; dst = oqg; off = idx - 638944; }
    else return;
    float4 v = src[off];
    v.x = tf32r(v.x); v.y = tf32r(v.y); v.z = tf32r(v.z); v.w = tf32r(v.w);
    dst[off] = v;
}

// ---------------------------------------------------------------------------
// Build per-row nonzero lists of A2 = sum_e adj. One warp per row.
// ---------------------------------------------------------------------------
__global__ void build_nz(const float* __restrict__ adj, int* __restrict__ nzc,
                         int* __restrict__ nzi, float* __restrict__ nzv)
{
    int gw = (blockIdx.x * blockDim.x + threadIdx.x) >> 5;
    int lane = threadIdx.x & 31;
    if (gw >= MROWS) return;
    int b = gw / NNODE, i = gw - b * NNODE;
    const float* a0 = adj + ((size_t)b * NET) * NNODE * NNODE + (size_t)i * NNODE;
    const float* a1 = a0 + NNODE * NNODE;
    const float* a2 = a1 + NNODE * NNODE;
    int cnt = 0;
    for (int jb = 0; jb < NNODE; jb += 32) {
        int j = jb + lane;
        float v = 0.f;
        if (j < NNODE) v = a0[j] + a1[j] + a2[j];
        unsigned m = __ballot_sync(0xffffffffu, v != 0.f);
        int pos = cnt + __popc(m & ((1u << lane) - 1u));
        if (v != 0.f && pos < MAXNZ) {
            nzi[gw * MAXNZ + pos] = j;
            nzv[gw * MAXNZ + pos] = v;
        }
        cnt += __popc(m);
    }
    if (lane == 0) nzc[gw] = cnt;
}

// ---------------------------------------------------------------------------
// TF32 tensor-core GEMM, cp.async double-buffered.
//   Tile 128x128, BK=16, 8 warps (4x2); warp tile 32x64.
//   Logical A [M,Ktot] split at ksplit between A(lda) and Ab(ldab).
//   blockIdx.z = split-K chunk; chunk size K; kBase=z*K.
//   EPI 0: C=v+bias      EPI 2: C=(v+bias)*nmask
//   EPI 3: att=sig(v+bias)*nmask; Lnew=tf32r(att*tanh(U)+(1-att)*Lold)
//   EPI 4: C=tanh(v+bias); Lnew=tf32r(C)*nmask
//   EPI 5: C[z slab] = v (no bias)
// ---------------------------------------------------------------------------
template<int EPI>
__global__ void __launch_bounds__(256, 1) gemm_tc(
    const float* __restrict__ A, int lda,
    const float* __restrict__ Ab, int ldab, int ksplit,
    const float* __restrict__ W, int ldw,
    const float* __restrict__ bias,
    float* __restrict__ C, int ldc, int M, int K,
    const int* __restrict__ nlen,
    const float* __restrict__ Uin, const float* __restrict__ Lold,
    float* __restrict__ Lnew)
{
    __shared__ uint32_t As[2][128][20];   // [m][k], stride 20 -> conflict-free frags
    __shared__ uint32_t Bs[2][16][132];   // [k][n], stride 132

    const int tid  = threadIdx.x;
    const int lane = tid & 31, warp = tid >> 5;
    const int wm = warp >> 1, wn = warp & 1;
    const int tg = lane >> 2, tq = lane & 3;
    const int rowBlock = blockIdx.y * 128;
    const int colBlock = blockIdx.x * 128;
    const int z = blockIdx.z;
    const int kBase = z * K;

    float acc[2][8][4];
#pragma unroll
    for (int i = 0; i < 2; i++)
#pragma unroll
        for (int j = 0; j < 8; j++)
#pragma unroll
            for (int l = 0; l < 4; l++) acc[i][j][l] = 0.f;

    auto loadTiles = [&](int k0, int buf) {
        // A tile 128x16: 512 16B chunks, 2 per thread
#pragma unroll
        for (int it = 0; it < 2; it++) {
            int idx = it * 256 + tid;
            int m = idx >> 2, cc = idx & 3;
            int gr = rowBlock + m;
            int kk = k0 + cc * 4;
            int gk = kBase + kk;
            const float* src = (gk < ksplit)
                ? A  + (size_t)gr * lda  + gk
                : Ab + (size_t)gr * ldab + (gk - ksplit);
            int sz = (gr < M && kk < K) ? 16 : 0;
            cp_async16(smem_u32(&As[buf][m][cc * 4]), src, sz);
        }
        // B tile 16x128: 512 chunks, 2 per thread
#pragma unroll
        for (int it = 0; it < 2; it++) {
            int idx = it * 256 + tid;
            int k = idx >> 5, cc = idx & 31;
            int kk = k0 + k;
            const float* src = W + (size_t)(kBase + kk) * ldw + colBlock + cc * 4;
            int sz = (kk < K) ? 16 : 0;
            cp_async16(smem_u32(&Bs[buf][k][cc * 4]), src, sz);
        }
        cp_commit();
    };

    const int nsteps = (K + 15) / 16;
    loadTiles(0, 0);
    int buf = 0;

    for (int s = 0; s < nsteps; s++) {
        cp_wait0();
        __syncthreads();
        if (s + 1 < nsteps) loadTiles((s + 1) * 16, buf ^ 1);

#pragma unroll
        for (int ks = 0; ks < 2; ks++) {
            const int kb = ks * 8;
            uint32_t af[2][4], bf[8][2];
#pragma unroll
            for (int mt = 0; mt < 2; mt++) {
                int r0 = wm * 32 + mt * 16 + tg;
                af[mt][0] = As[buf][r0    ][kb + tq];
                af[mt][1] = As[buf][r0 + 8][kb + tq];
                af[mt][2] = As[buf][r0    ][kb + tq + 4];
                af[mt][3] = As[buf][r0 + 8][kb + tq + 4];
            }
#pragma unroll
            for (int nt = 0; nt < 8; nt++) {
                int c0 = wn * 64 + nt * 8 + tg;
                bf[nt][0] = Bs[buf][kb + tq    ][c0];
                bf[nt][1] = Bs[buf][kb + tq + 4][c0];
            }
#pragma unroll
            for (int mt = 0; mt < 2; mt++)
#pragma unroll
                for (int nt = 0; nt < 8; nt++)
                    mma_tf32(acc[mt][nt], af[mt], bf[nt]);
        }
        buf ^= 1;
    }

    // ---- epilogue ----
#pragma unroll
    for (int mt = 0; mt < 2; mt++) {
#pragma unroll
        for (int half = 0; half < 2; half++) {
            int r = rowBlock + wm * 32 + mt * 16 + tg + half * 8;
            if (r >= M) continue;
            float rowmask = 1.f;
            if (EPI == 2 || EPI == 3 || EPI == 4) {
                int bb = r / NNODE, ii = r - bb * NNODE;
                rowmask = (ii < nlen[bb]) ? 1.f : 0.f;
            }
#pragma unroll
            for (int nt = 0; nt < 8; nt++) {
#pragma unroll
                for (int e = 0; e < 2; e++) {
                    int c = colBlock + wn * 64 + nt * 8 + tq * 2 + e;
                    float v = acc[mt][nt][half * 2 + e];
                    if (EPI != 5) v += bias[c];
                    size_t off = (size_t)r * ldc + c;
                    if (EPI == 0) {
                        C[off] = v;
                    } else if (EPI == 2) {
                        C[off] = v * rowmask;
                    } else if (EPI == 3) {
                        float att = rowmask / (1.f + __expf(-v));
                        Lnew[off] = tf32r(att * tanhf(Uin[off]) +
                                          (1.f - att) * Lold[off]);
                    } else if (EPI == 4) {
                        float t = tanhf(v);
                        C[off] = t;
                        Lnew[off] = tf32r(t) * rowmask;
                    } else { // EPI 5
                        C[((size_t)z * M + r) * ldc + c] = v;
                    }
                }
            }
        }
    }
}

// ---------------------------------------------------------------------------
// U[m,:] = sum_t val[t]*hm[b, idx[t], :] + hm[m,:]; tf32-rounded.
// One block (128 thr) per row; sparse list in smem.
// ---------------------------------------------------------------------------
__global__ void spmm_nz(const int* __restrict__ nzc, const int* __restrict__ nzi,
                        const float* __restrict__ nzv, const float* __restrict__ adj,
                        const float* __restrict__ hm, float* __restrict__ U)
{
    const int m = blockIdx.x;
    const int b = m / NNODE;
    const float* hmb = hm + (size_t)b * NNODE * ENC;
    const int d0 = threadIdx.x * 4;
    int cnt = nzc[m];
    float4 acc = *reinterpret_cast<const float4*>(hm + (size_t)m * ENC + d0);

    if (cnt <= MAXNZ) {
        __shared__ int   si[MAXNZ];
        __shared__ float sv[MAXNZ];
        for (int t = threadIdx.x; t < cnt; t += 128) {
            si[t] = nzi[m * MAXNZ + t];
            sv[t] = nzv[m * MAXNZ + t];
        }
        __syncthreads();
#pragma unroll 4
        for (int t = 0; t < cnt; t++) {
            float a = sv[t];
            const float4 hv = *reinterpret_cast<const float4*>(
                hmb + (size_t)si[t] * ENC + d0);
            acc.x += a * hv.x; acc.y += a * hv.y;
            acc.z += a * hv.z; acc.w += a * hv.w;
        }
    } else {
        // dense fallback (statistically unreachable; correctness safety)
        int i = m - b * NNODE;
        const float* a0 = adj + ((size_t)b * NET) * NNODE * NNODE + (size_t)i * NNODE;
        const float* a1 = a0 + NNODE * NNODE;
        const float* a2 = a1 + NNODE * NNODE;
        for (int j = 0; j < NNODE; j++) {
            float a = a0[j] + a1[j] + a2[j];
            if (a != 0.f) {
                const float4 hv = *reinterpret_cast<const float4*>(
                    hmb + (size_t)j * ENC + d0);
                acc.x += a * hv.x; acc.y += a * hv.y;
                acc.z += a * hv.z; acc.w += a * hv.w;
            }
        }
    }
    acc.x = tf32r(acc.x); acc.y = tf32r(acc.y);
    acc.z = tf32r(acc.z); acc.w = tf32r(acc.w);
    *reinterpret_cast<float4*>(U + (size_t)m * ENC + d0) = acc;
}

// ---------------------------------------------------------------------------
// sq[b,q] = qc[b,q,:] . wa_q
// ---------------------------------------------------------------------------
__global__ void sq_kernel(const float* __restrict__ qc, const float* __restrict__ wa,
                          float* __restrict__ sq)
{
    int gw = (blockIdx.x * blockDim.x + threadIdx.x) >> 5;
    int lane = threadIdx.x & 31;
    if (gw >= QROWS) return;
    float s = 0.f;
    for (int d = lane; d < ENC; d += 32) s += qc[(size_t)gw * ENC + d] * wa[ENC + d];
    s = warpSum(s);
    if (lane == 0) sq[gw] = s;
}

// ---------------------------------------------------------------------------
// Per node m: sim/softmax over q; n2q; smax
// ---------------------------------------------------------------------------
__global__ void attn_kernel(const float* __restrict__ L, const float* __restrict__ qc,
                            const float* __restrict__ wa, const float* __restrict__ sq,
                            float* __restrict__ n2q, float* __restrict__ smax)
{
    const int m = blockIdx.x;
    const int b = m / NNODE;
    const int tid = threadIdx.x;           // 128
    const int lane = tid & 31, warp = tid >> 5;
    __shared__ float Lws[ENC];
    __shared__ float red[4];
    __shared__ float simv[NQ];
    __shared__ float p[NQ];

    float snp = 0.f;
#pragma unroll
    for (int d = tid; d < ENC; d += 128) {
        float v = L[(size_t)m * ENC + d];
        Lws[d] = v * wa[2 * ENC + d];
        snp += v * wa[d];
    }
    snp = warpSum(snp);
    if (lane == 0) red[warp] = snp;
    __syncthreads();
    float sn = red[0] + red[1] + red[2] + red[3];

    for (int q = warp; q < NQ; q += 4) {
        const float* qr = qc + ((size_t)b * NQ + q) * ENC;
        float s = 0.f;
        for (int d = lane; d < ENC; d += 32) s += Lws[d] * qr[d];
        s = warpSum(s);
        if (lane == 0) simv[q] = sn + sq[b * NQ + q] + s;
    }
    __syncthreads();

    if (tid < 32) {
        float v = (lane < NQ) ? simv[lane] : -1e30f;
        float mx = warpMax(v);
        float e = (lane < NQ) ? __expf(v - mx) : 0.f;
        float Z = warpSum(e);
        if (lane < NQ) p[lane] = e / Z;
        if (lane == 0) smax[m] = mx;
    }
    __syncthreads();

#pragma unroll
    for (int d = tid; d < ENC; d += 128) {
        float acc = 0.f;
#pragma unroll
        for (int q = 0; q < NQ; q++) acc += p[q] * qc[((size_t)b * NQ + q) * ENC + d];
        n2q[(size_t)m * ENC + d] = acc;
    }
}

// ---------------------------------------------------------------------------
// Per batch: bvec = softmax_n(smax); q2n = bvec @ nc
// ---------------------------------------------------------------------------
__global__ void q2n_kernel(const float* __restrict__ smax, const float* __restrict__ nc,
                           float* __restrict__ q2n)
{
    const int b = blockIdx.x;
    const int tid = threadIdx.x;            // 256
    const int lane = tid & 31, warp = tid >> 5;
    __shared__ float w[NNODE];
    __shared__ float red[8];

    float mx = -1e30f;
    for (int n = tid; n < NNODE; n += 256) mx = fmaxf(mx, smax[b * NNODE + n]);
    mx = warpMax(mx);
    if (lane == 0) red[warp] = mx;
    __syncthreads();
    float bmax = red[0];
#pragma unroll
    for (int i = 1; i < 8; i++) bmax = fmaxf(bmax, red[i]);
    __syncthreads();

    float s = 0.f;
    for (int n = tid; n < NNODE; n += 256) {
        float e = __expf(smax[b * NNODE + n] - bmax);
        w[n] = e; s += e;
    }
    s = warpSum(s);
    if (lane == 0) red[warp] = s;
    __syncthreads();
    float Z = 0.f;
#pragma unroll
    for (int i = 0; i < 8; i++) Z += red[i];
    float inv = 1.f / Z;

    const int d0 = tid * 2;
    float a0 = 0.f, a1 = 0.f;
    for (int n = 0; n < NNODE; n++) {
        float ww = w[n] * inv;
        const float2 r = *reinterpret_cast<const float2*>(
            nc + ((size_t)b * NNODE + n) * ENC + d0);
        a0 += ww * r.x; a1 += ww * r.y;
    }
    q2n[b * ENC + d0]     = a0;
    q2n[b * ENC + d0 + 1] = a1;
}

// ---------------------------------------------------------------------------
// g = [nc, n2q, nc*n2q, nc*q2n], tf32-rounded (feeds W1 GEMM)
// ---------------------------------------------------------------------------
__global__ void build_g(const float* __restrict__ nc, const float* __restrict__ n2q,
                        const float* __restrict__ q2n, float* __restrict__ g)
{
    int idx = blockIdx.x * 256 + threadIdx.x;
    int m = idx >> 9, d = idx & 511;
    int b = m / NNODE;
    float a = nc[idx], t = n2q[idx], qn = q2n[b * ENC + d];
    size_t base = (size_t)m * (4 * ENC) + d;
    g[base]           = tf32r(a);
    g[base + ENC]     = tf32r(t);
    g[base + 2 * ENC] = tf32r(a * t);
    g[base + 3 * ENC] = tf32r(a * qn);
}

// ---------------------------------------------------------------------------
// raw[m] = sum_h tanh(sum_s h1p[s][m][h] + b1[h]) * W2[h] + b2
// ---------------------------------------------------------------------------
__global__ void raw2_kernel(const float* __restrict__ h1p, const float* __restrict__ b1,
                            const float* __restrict__ W2, const float* __restrict__ b2,
                            float* __restrict__ raw)
{
    int gw = (blockIdx.x * blockDim.x + threadIdx.x) >> 5;
    int lane = threadIdx.x & 31;
    if (gw >= MROWS) return;
    const size_t stride = (size_t)MROWS * 128;
    float s = 0.f;
    for (int h = lane; h < 128; h += 32) {
        size_t o = (size_t)gw * 128 + h;
        float v = h1p[o] + h1p[o + stride] + h1p[o + 2*stride] + h1p[o + 3*stride]
                + b1[h];
        s += tanhf(v) * W2[h];
    }
    s = warpSum(s);
    if (lane == 0) raw[gw] = s + b2[0];
}

// ---------------------------------------------------------------------------
// out[b,c] = max_n f(mask*raw),  f(0) = -1e6
// ---------------------------------------------------------------------------
__global__ void out_kernel(const int* __restrict__ mask, const float* __restrict__ raw,
                           float* __restrict__ out)
{
    int gw = (blockIdx.x * blockDim.x + threadIdx.x) >> 5;
    int lane = threadIdx.x & 31;
    if (gw >= BATCH * NC) return;
    int b = gw / NC, c = gw - b * NC;
    const int* mr = mask + ((size_t)b * NC + c) * NNODE;
    const float* rr = raw + b * NNODE;
    float mx = -1e30f;
    for (int n = lane; n < NNODE; n += 32) {
        float p = (float)mr[n] * rr[n];
        if (p == 0.f) p = -1e6f;
        mx = fmaxf(mx, p);
    }
    mx = warpMax(mx);
    if (lane == 0) out[gw] = mx;
}

// ---------------------------------------------------------------------------
// Launch
// ---------------------------------------------------------------------------
extern "C" void kernel_launch(void* const* d_in, const int* in_sizes, int n_in,
                              void* d_out, int out_size)
{
    const float* nodes_glove = (const float*)d_in[0];
    const float* query_glove = (const float*)d_in[1];
    const float* adj         = (const float*)d_in[2];
    const int*   nlen        = (const int*)  d_in[3];
    const int*   mask        = (const int*)  d_in[4];
    const float* Wn = (const float*)d_in[5];
    const float* bn = (const float*)d_in[6];
    const float* Wq = (const float*)d_in[7];
    const float* bq = (const float*)d_in[8];
    const float* Wh = (const float*)d_in[9];
    const float* bh = (const float*)d_in[10];
    const float* Wc = (const float*)d_in[11];
    const float* bc = (const float*)d_in[12];
    const float* wa = (const float*)d_in[13];
    const float* W1 = (const float*)d_in[14];
    const float* b1 = (const float*)d_in[15];
    const float* W2 = (const float*)d_in[16];
    const float* b2 = (const float*)d_in[17];
    float* out = (float*)d_out;

    float *p_nc, *p_qc, *p_L, *p_L2, *p_hm, *p_U, *p_sq,
          *p_n2q, *p_smax, *p_q2n, *p_g, *p_h1p, *p_raw;
    float *p_Wnr, *p_Wqr, *p_Whr, *p_Wcr, *p_W1r, *p_ngr, *p_qgr;
    float *p_nzv; int *p_nzc, *p_nzi;
    cudaGetSymbolAddress((void**)&p_nc,  g_nc);
    cudaGetSymbolAddress((void**)&p_qc,  g_qc);
    cudaGetSymbolAddress((void**)&p_L,   g_L);
    cudaGetSymbolAddress((void**)&p_L2,  g_L2);
    cudaGetSymbolAddress((void**)&p_hm,  g_hm);
    cudaGetSymbolAddress((void**)&p_U,   g_U);
    cudaGetSymbolAddress((void**)&p_sq,  g_sq);
    cudaGetSymbolAddress((void**)&p_n2q, g_n2q);
    cudaGetSymbolAddress((void**)&p_smax,g_smax);
    cudaGetSymbolAddress((void**)&p_q2n, g_q2n);
    cudaGetSymbolAddress((void**)&p_g,   g_g);
    cudaGetSymbolAddress((void**)&p_h1p, g_h1p);
    cudaGetSymbolAddress((void**)&p_raw, g_raw);
    cudaGetSymbolAddress((void**)&p_Wnr, g_Wnr);
    cudaGetSymbolAddress((void**)&p_Wqr, g_Wqr);
    cudaGetSymbolAddress((void**)&p_Whr, g_Whr);
    cudaGetSymbolAddress((void**)&p_Wcr, g_Wcr);
    cudaGetSymbolAddress((void**)&p_W1r, g_W1r);
    cudaGetSymbolAddress((void**)&p_ngr, g_ngr);
    cudaGetSymbolAddress((void**)&p_qgr, g_qgr);
    cudaGetSymbolAddress((void**)&p_nzc, g_nzc);
    cudaGetSymbolAddress((void**)&p_nzi, g_nzi);
    cudaGetSymbolAddress((void**)&p_nzv, g_nzv);

    // round all GEMM operand inputs to tf32 once
    round_inputs<<<(653944 + 255) / 256, 256>>>(
        (const float4*)Wn, (const float4*)Wq, (const float4*)Wh,
        (const float4*)Wc, (const float4*)W1,
        (const float4*)nodes_glove, (const float4*)query_glove,
        (float4*)p_Wnr, (float4*)p_Wqr, (float4*)p_Whr,
        (float4*)p_Wcr, (float4*)p_W1r, (float4*)p_ngr, (float4*)p_qgr);

    // adjacency sparsity lists
    build_nz<<<(MROWS * 32 + 255) / 256, 256>>>(adj, p_nzc, p_nzi, p_nzv);

    // nodes_compress = tanh(ng @ Wn + bn); L = tf32r(nc)*nmask
    gemm_tc<4><<<dim3(ENC/128, 32, 1), 256>>>(
        p_ngr, DIN, p_ngr, DIN, DIN, p_Wnr, ENC, bn,
        p_nc, ENC, MROWS, DIN, nlen, nullptr, nullptr, p_L);

    // query_compress = qg @ Wq + bq
    gemm_tc<0><<<dim3(ENC/128, 2, 1), 256>>>(
        p_qgr, DIN, p_qgr, DIN, DIN, p_Wqr, ENC, bq,
        p_qc, ENC, QROWS, DIN, nullptr, nullptr, nullptr, nullptr);

    float* Lc = p_L;
    float* Ln = p_L2;
    for (int h = 0; h < HOPS; h++) {
        // hm = (L @ Wh + bh) * nmask
        gemm_tc<2><<<dim3(ENC/128, 32, 1), 256>>>(
            Lc, ENC, Lc, ENC, ENC, p_Whr, ENC, bh,
            p_hm, ENC, MROWS, ENC, nlen, nullptr, nullptr, nullptr);
        // U = A2 @ hm + hm  (sparse)
        spmm_nz<<<MROWS, 128>>>(p_nzc, p_nzi, p_nzv, adj, p_hm, p_U);
        // att = sigmoid([U,L] @ Wc + bc)*nmask; Ln = att*tanh(U)+(1-att)*Lc
        gemm_tc<3><<<dim3(ENC/128, 32, 1), 256>>>(
            p_U, ENC, Lc, ENC, ENC, p_Wcr, ENC, bc,
            nullptr, ENC, MROWS, 2*ENC, nlen, p_U, Lc, Ln);
        float* t = Lc; Lc = Ln; Ln = t;
    }

    // attention
    sq_kernel<<<(QROWS*32 + 255) / 256, 256>>>(p_qc, wa, p_sq);
    attn_kernel<<<MROWS, 128>>>(Lc, p_qc, wa, p_sq, p_n2q, p_smax);
    q2n_kernel<<<BATCH, 256>>>(p_smax, p_nc, p_q2n);

    // scorer
    build_g<<<MROWS*ENC/256, 256>>>(p_nc, p_n2q, p_q2n, p_g);
    // h1 partials: split-K=4 over K=2048 (chunk 512)
    gemm_tc<5><<<dim3(1, 32, 4), 256>>>(
        p_g, 4*ENC, p_g, 4*ENC, 4*ENC, p_W1r, 128, nullptr,
        p_h1p, 128, MROWS, 512, nullptr, nullptr, nullptr, nullptr);
    raw2_kernel<<<(MROWS*32 + 255) / 256, 256>>>(p_h1p, b1, W2, b2, p_raw);

    // masked max
    out_kernel<<<(BATCH*NC*32 + 255) / 256, 256>>>(mask, p_raw, out);
}

// round 6
// speedup vs baseline: 4.0893x; 1.0663x over previous
#include <cuda_runtime.h>
#include <cstdint>

// ---------------------------------------------------------------------------
// Problem constants
// ---------------------------------------------------------------------------
#define BATCH 8
#define NNODE 500
#define NQ    25
#define ENC   512
#define DIN   300
#define NC    70
#define NET   3
#define HOPS  3
#define MROWS (BATCH*NNODE)   // 4000
#define QROWS (BATCH*NQ)      // 200
#define MAXNZ 192

// GEMM smem geometry (u32 units)
#define ASTRIDE 36
#define BSTRIDE 136
#define ABUF (128*ASTRIDE)          // 4608
#define BBUF (32*BSTRIDE)           // 4352
#define GEMM_SMEM ((2*ABUF + 2*BBUF) * 4)   // 71680 bytes
#define ATTN_SMEM (NQ*ENC*4)                // 51200 bytes

// ---------------------------------------------------------------------------
// Device scratch
// ---------------------------------------------------------------------------
__device__ float g_nc  [MROWS*ENC];
__device__ float g_qc  [QROWS*ENC];
__device__ float g_L   [MROWS*ENC];
__device__ float g_L2  [MROWS*ENC];
__device__ float g_hm  [MROWS*ENC];
__device__ float g_U   [MROWS*ENC];
__device__ float g_n2q [MROWS*ENC];
__device__ float g_smax[MROWS];
__device__ float g_q2n [BATCH*ENC];
__device__ float g_g   [MROWS*4*ENC];
__device__ float g_h1p [4*MROWS*128];
__device__ float g_raw [MROWS];
// tf32-rounded copies of inputs
__device__ float g_Wnr [DIN*ENC];
__device__ float g_Wqr [DIN*ENC];
__device__ float g_Whr [ENC*ENC];
__device__ float g_Wcr [2*ENC*ENC];
__device__ float g_W1r [4*ENC*128];
__device__ float g_ngr [MROWS*DIN];
__device__ float g_qgr [QROWS*DIN];
// adjacency sparsity
__device__ int   g_nzc [MROWS];
__device__ int   g_nzi [MROWS*MAXNZ];
__device__ float g_nzv [MROWS*MAXNZ];

// ---------------------------------------------------------------------------
// Helpers
// ---------------------------------------------------------------------------
__device__ __forceinline__ float warpSum(float v) {
#pragma unroll
    for (int o = 16; o; o >>= 1) v += __shfl_xor_sync(0xffffffffu, v, o);
    return v;
}
__device__ __forceinline__ float warpMax(float v) {
#pragma unroll
    for (int o = 16; o; o >>= 1) v = fmaxf(v, __shfl_xor_sync(0xffffffffu, v, o));
    return v;
}
__device__ __forceinline__ float tf32r(float f) {
    uint32_t u;
    asm("cvt.rna.tf32.f32 %0, %1;" : "=r"(u) : "f"(f));
    return __uint_as_float(u);
}
__device__ __forceinline__ void mma_tf32(float* c, const uint32_t* a, const uint32_t* b) {
    asm volatile(
        "mma.sync.aligned.m16n8k8.row.col.f32.tf32.tf32.f32 "
        "{%0,%1,%2,%3}, {%4,%5,%6,%7}, {%8,%9}, {%0,%1,%2,%3};"
        : "+f"(c[0]), "+f"(c[1]), "+f"(c[2]), "+f"(c[3])
        : "r"(a[0]), "r"(a[1]), "r"(a[2]), "r"(a[3]), "r"(b[0]), "r"(b[1]));
}
__device__ __forceinline__ uint32_t smem_u32(const void* p) {
    return (uint32_t)__cvta_generic_to_shared(p);
}
__device__ __forceinline__ void cp_async16(uint32_t dst, const void* src, int sz) {
    asm volatile("cp.async.ca.shared.global [%0], [%1], 16, %2;\n"
                 :: "r"(dst), "l"(src), "r"(sz));
}
__device__ __forceinline__ void cp_commit() {
    asm volatile("cp.async.commit_group;\n" ::: "memory");
}
__device__ __forceinline__ void cp_wait0() {
    asm volatile("cp.async.wait_group 0;\n" ::: "memory");
}

// ---------------------------------------------------------------------------
// prep: tf32-round all GEMM operand inputs + build adjacency nz lists.
// ---------------------------------------------------------------------------
#define NB_ROUND 2555    // ceil(653944/256)
#define NB_NZ    500     // 4000 rows / 8 warps per block
__global__ void prep_kernel(
    const float4* __restrict__ Wn, const float4* __restrict__ Wq,
    const float4* __restrict__ Wh, const float4* __restrict__ Wc,
    const float4* __restrict__ W1, const float4* __restrict__ ng,
    const float4* __restrict__ qg,
    float4* __restrict__ oWn, float4* __restrict__ oWq, float4* __restrict__ oWh,
    float4* __restrict__ oWc, float4* __restrict__ oW1, float4* __restrict__ ong,
    float4* __restrict__ oqg,
    const float* __restrict__ adj, int* __restrict__ nzc,
    int* __restrict__ nzi, float* __restrict__ nzv)
{
    if (blockIdx.x < NB_ROUND) {
        int idx = blockIdx.x * 256 + threadIdx.x;
        const float4* src; float4* dst; int off;
        if      (idx < 38400)  { src = Wn; dst = oWn; off = idx; }
        else if (idx < 76800)  { src = Wq; dst = oWq; off = idx - 38400; }
        else if (idx < 142336) { src = Wh; dst = oWh; off = idx - 76800; }
        else if (idx < 273408) { src = Wc; dst = oWc; off = idx - 142336; }
        else if (idx < 338944) { src = W1; dst = oW1; off = idx - 273408; }
        else if (idx < 638944) { src = ng; dst = ong; off = idx - 338944; }
        else if (idx < 653944) { src = qg; dst = oqg; off = idx - 638944; }
        else return;
        float4 v = src[off];
        v.x = tf32r(v.x); v.y = tf32r(v.y); v.z = tf32r(v.z); v.w = tf32r(v.w);
        dst[off] = v;
    } else {
        int gw = (blockIdx.x - NB_ROUND) * 8 + (threadIdx.x >> 5);
        int lane = threadIdx.x & 31;
        if (gw >= MROWS) return;
        int b = gw / NNODE;
        int i = gw - b * NNODE;
        const float* a0 = adj + ((size_t)b * NET) * NNODE * NNODE + (size_t)i * NNODE;
        const float* a1 = a0 + NNODE * NNODE;
        const float* a2 = a1 + NNODE * NNODE;
        int cnt = 0;
        for (int jb = 0; jb < NNODE; jb += 32) {
            int j = jb + lane;
            float v = 0.f;
            if (j < NNODE) v = a0[j] + a1[j] + a2[j];
            unsigned m = __ballot_sync(0xffffffffu, v != 0.f);
            int pos = cnt + __popc(m & ((1u << lane) - 1u));
            if (v != 0.f && pos < MAXNZ) {
                nzi[gw * MAXNZ + pos] = j;
                nzv[gw * MAXNZ + pos] = v;
            }
            cnt += __popc(m);
        }
        if (lane == 0) nzc[gw] = cnt;
    }
}

// ---------------------------------------------------------------------------
// GEMM core (BK=32, tile 128x128, 8 warps, cp.async double-buffered,
// dynamic smem). Fragments + accumulate; epilogue done by caller kernels.
// ---------------------------------------------------------------------------
struct GemmCtx {
    uint32_t* sh;
    int tid, lane, warp, wm, wn, tg, tq;
};

__device__ __forceinline__ void gemm_ctx_init(GemmCtx& cx, uint32_t* sh) {
    cx.sh = sh;
    cx.tid = threadIdx.x; cx.lane = cx.tid & 31; cx.warp = cx.tid >> 5;
    cx.wm = cx.warp >> 1; cx.wn = cx.warp & 1;
    cx.tg = cx.lane >> 2; cx.tq = cx.lane & 3;
}

__device__ __forceinline__ void gemm_core(
    GemmCtx& cx,
    const float* __restrict__ A, int lda,
    const float* __restrict__ Ab, int ldab, int ksplit,
    const float* __restrict__ W, int ldw,
    int rowBlock, int colBlock, int kBase, int M, int K,
    float acc[2][8][4])
{
    uint32_t* sh = cx.sh;
    const int tid = cx.tid, tg = cx.tg, tq = cx.tq, wm = cx.wm, wn = cx.wn;
    uint32_t* Bbase = sh + 2 * ABUF;

    auto loadTiles = [&](int k0, int buf) {
        uint32_t* Ad = sh + buf * ABUF;
        uint32_t* Bd = Bbase + buf * BBUF;
        // A tile 128x32: 1024 16B chunks, 4/thread
#pragma unroll
        for (int it = 0; it < 4; it++) {
            int idx = it * 256 + tid;
            int m = idx >> 3, cc = idx & 7;
            int gr = rowBlock + m;
            int kk = k0 + cc * 4;
            int gk = kBase + kk;
            const float* src = (gk < ksplit)
                ? A  + (size_t)gr * lda  + gk
                : Ab + (size_t)gr * ldab + (gk - ksplit);
            int sz = (gr < M && kk < K) ? 16 : 0;
            cp_async16(smem_u32(Ad + m * ASTRIDE + cc * 4), src, sz);
        }
        // B tile 32x128: 1024 chunks, 4/thread
#pragma unroll
        for (int it = 0; it < 4; it++) {
            int idx = it * 256 + tid;
            int k = idx >> 5, cc = idx & 31;
            int kk = k0 + k;
            const float* src = W + (size_t)(kBase + kk) * ldw + colBlock + cc * 4;
            int sz = (kk < K) ? 16 : 0;
            cp_async16(smem_u32(Bd + k * BSTRIDE + cc * 4), src, sz);
        }
        cp_commit();
    };

    const int nsteps = (K + 31) / 32;
    loadTiles(0, 0);
    int buf = 0;

    for (int s = 0; s < nsteps; s++) {
        cp_wait0();
        __syncthreads();
        if (s + 1 < nsteps) loadTiles((s + 1) * 32, buf ^ 1);

        uint32_t* As = sh + buf * ABUF;
        uint32_t* Bs = Bbase + buf * BBUF;
#pragma unroll
        for (int ks = 0; ks < 4; ks++) {
            const int kb = ks * 8;
            uint32_t af[2][4], bf[8][2];
#pragma unroll
            for (int mt = 0; mt < 2; mt++) {
                int r0 = wm * 32 + mt * 16 + tg;
                af[mt][0] = As[(r0    ) * ASTRIDE + kb + tq];
                af[mt][1] = As[(r0 + 8) * ASTRIDE + kb + tq];
                af[mt][2] = As[(r0    ) * ASTRIDE + kb + tq + 4];
                af[mt][3] = As[(r0 + 8) * ASTRIDE + kb + tq + 4];
            }
#pragma unroll
            for (int nt = 0; nt < 8; nt++) {
                int c0 = wn * 64 + nt * 8 + tg;
                bf[nt][0] = Bs[(kb + tq    ) * BSTRIDE + c0];
                bf[nt][1] = Bs[(kb + tq + 4) * BSTRIDE + c0];
            }
#pragma unroll
            for (int mt = 0; mt < 2; mt++)
#pragma unroll
                for (int nt = 0; nt < 8; nt++)
                    mma_tf32(acc[mt][nt], af[mt], bf[nt]);
        }
        buf ^= 1;
        __syncthreads();
    }
}

// ---------------------------------------------------------------------------
// Combined compress GEMM: blockIdx.y<32 -> nodes (tanh + masked L),
// else -> query (plain). K=300.
// ---------------------------------------------------------------------------
__global__ void __launch_bounds__(256, 1) gemm_compress(
    const float* __restrict__ ng, const float* __restrict__ Wn,
    const float* __restrict__ bn, float* __restrict__ nc,
    float* __restrict__ L, const int* __restrict__ nlen,
    const float* __restrict__ qg, const float* __restrict__ Wq,
    const float* __restrict__ bq, float* __restrict__ qc)
{
    extern __shared__ uint32_t sh_[];
    GemmCtx cx; gemm_ctx_init(cx, sh_);
    float acc[2][8][4];
#pragma unroll
    for (int i = 0; i < 2; i++)
#pragma unroll
        for (int j = 0; j < 8; j++)
#pragma unroll
            for (int l = 0; l < 4; l++) acc[i][j][l] = 0.f;

    const bool isQ = blockIdx.y >= 32;
    const float* A    = isQ ? qg : ng;
    const float* W    = isQ ? Wq : Wn;
    const float* bias = isQ ? bq : bn;
    float* C          = isQ ? qc : nc;
    const int M       = isQ ? QROWS : MROWS;
    const int rowBlock = (isQ ? blockIdx.y - 32 : blockIdx.y) * 128;
    const int colBlock = blockIdx.x * 128;

    gemm_core(cx, A, DIN, A, DIN, DIN, W, ENC,
              rowBlock, colBlock, 0, M, DIN, acc);

#pragma unroll
    for (int mt = 0; mt < 2; mt++) {
#pragma unroll
        for (int half = 0; half < 2; half++) {
            int r = rowBlock + cx.wm * 32 + mt * 16 + cx.tg + half * 8;
            if (r >= M) continue;
            float rowmask = 1.f;
            if (!isQ) {
                int bb = r / NNODE;
                int ii = r - bb * NNODE;
                rowmask = (ii < nlen[bb]) ? 1.f : 0.f;
            }
#pragma unroll
            for (int nt = 0; nt < 8; nt++) {
#pragma unroll
                for (int e = 0; e < 2; e++) {
                    int c = colBlock + cx.wn * 64 + nt * 8 + cx.tq * 2 + e;
                    float v = acc[mt][nt][half * 2 + e] + bias[c];
                    size_t off = (size_t)r * ENC + c;
                    if (isQ) {
                        C[off] = v;
                    } else {
                        float t = tanhf(v);
                        C[off] = t;
                        L[off] = tf32r(t) * rowmask;
                    }
                }
            }
        }
    }
}

// ---------------------------------------------------------------------------
// Hop GEMM A: hm = (L @ Wh + bh) * nmask
// ---------------------------------------------------------------------------
__global__ void __launch_bounds__(256, 1) gemm_hm(
    const float* __restrict__ Lc, const float* __restrict__ Wh,
    const float* __restrict__ bh, float* __restrict__ hm,
    const int* __restrict__ nlen)
{
    extern __shared__ uint32_t sh_[];
    GemmCtx cx; gemm_ctx_init(cx, sh_);
    float acc[2][8][4];
#pragma unroll
    for (int i = 0; i < 2; i++)
#pragma unroll
        for (int j = 0; j < 8; j++)
#pragma unroll
            for (int l = 0; l < 4; l++) acc[i][j][l] = 0.f;

    const int rowBlock = blockIdx.y * 128;
    const int colBlock = blockIdx.x * 128;
    const int M = MROWS;

    gemm_core(cx, Lc, ENC, Lc, ENC, ENC, Wh, ENC,
              rowBlock, colBlock, 0, M, ENC, acc);

#pragma unroll
    for (int mt = 0; mt < 2; mt++) {
#pragma unroll
        for (int half = 0; half < 2; half++) {
            int r = rowBlock + cx.wm * 32 + mt * 16 + cx.tg + half * 8;
            if (r >= M) continue;
            int bb = r / NNODE;
            int ii = r - bb * NNODE;
            float rowmask = (ii < nlen[bb]) ? 1.f : 0.f;
#pragma unroll
            for (int nt = 0; nt < 8; nt++) {
#pragma unroll
                for (int e = 0; e < 2; e++) {
                    int c = colBlock + cx.wn * 64 + nt * 8 + cx.tq * 2 + e;
                    float v = acc[mt][nt][half * 2 + e] + bh[c];
                    hm[(size_t)r * ENC + c] = v * rowmask;
                }
            }
        }
    }
}

// ---------------------------------------------------------------------------
// Hop GEMM B: att = sigmoid([U,L] @ Wc + bc)*nmask;
//             Lnew = tf32r(att*tanh(U) + (1-att)*Lold)
// ---------------------------------------------------------------------------
__global__ void __launch_bounds__(256, 1) gemm_att(
    const float* __restrict__ U, const float* __restrict__ Lold,
    const float* __restrict__ Wc, const float* __restrict__ bc,
    const int* __restrict__ nlen, float* __restrict__ Lnew)
{
    extern __shared__ uint32_t sh_[];
    GemmCtx cx; gemm_ctx_init(cx, sh_);
    float acc[2][8][4];
#pragma unroll
    for (int i = 0; i < 2; i++)
#pragma unroll
        for (int j = 0; j < 8; j++)
#pragma unroll
            for (int l = 0; l < 4; l++) acc[i][j][l] = 0.f;

    const int rowBlock = blockIdx.y * 128;
    const int colBlock = blockIdx.x * 128;
    const int M = MROWS;

    gemm_core(cx, U, ENC, Lold, ENC, ENC, Wc, ENC,
              rowBlock, colBlock, 0, M, 2 * ENC, acc);

#pragma unroll
    for (int mt = 0; mt < 2; mt++) {
#pragma unroll
        for (int half = 0; half < 2; half++) {
            int r = rowBlock + cx.wm * 32 + mt * 16 + cx.tg + half * 8;
            if (r >= M) continue;
            int bb = r / NNODE;
            int ii = r - bb * NNODE;
            float rowmask = (ii < nlen[bb]) ? 1.f : 0.f;
#pragma unroll
            for (int nt = 0; nt < 8; nt++) {
#pragma unroll
                for (int e = 0; e < 2; e++) {
                    int c = colBlock + cx.wn * 64 + nt * 8 + cx.tq * 2 + e;
                    float v = acc[mt][nt][half * 2 + e] + bc[c];
                    size_t off = (size_t)r * ENC + c;
                    float att = rowmask / (1.f + __expf(-v));
                    Lnew[off] = tf32r(att * tanhf(U[off]) +
                                      (1.f - att) * Lold[off]);
                }
            }
        }
    }
}

// ---------------------------------------------------------------------------
// W1 GEMM: split-K=4; slab z: h1p[z][r][c]
// ---------------------------------------------------------------------------
__global__ void __launch_bounds__(256, 1) gemm_w1(
    const float* __restrict__ g, const float* __restrict__ W1,
    float* __restrict__ h1p)
{
    extern __shared__ uint32_t sh_[];
    GemmCtx cx; gemm_ctx_init(cx, sh_);
    float acc[2][8][4];
#pragma unroll
    for (int i = 0; i < 2; i++)
#pragma unroll
        for (int j = 0; j < 8; j++)
#pragma unroll
            for (int l = 0; l < 4; l++) acc[i][j][l] = 0.f;

    const int rowBlock = blockIdx.y * 128;
    const int colBlock = 0;
    const int z = blockIdx.z;
    const int M = MROWS;

    gemm_core(cx, g, 4*ENC, g, 4*ENC, 4*ENC, W1, 128,
              rowBlock, colBlock, z * 512, M, 512, acc);

#pragma unroll
    for (int mt = 0; mt < 2; mt++) {
#pragma unroll
        for (int half = 0; half < 2; half++) {
            int r = rowBlock + cx.wm * 32 + mt * 16 + cx.tg + half * 8;
            if (r >= M) continue;
#pragma unroll
            for (int nt = 0; nt < 8; nt++) {
#pragma unroll
                for (int e = 0; e < 2; e++) {
                    int c = colBlock + cx.wn * 64 + nt * 8 + cx.tq * 2 + e;
                    float v = acc[mt][nt][half * 2 + e];
                    h1p[((size_t)z * M + r) * 128 + c] = v;
                }
            }
        }
    }
}

// ---------------------------------------------------------------------------
// U[m,:] = sum_t val[t]*hm[b, idx[t], :] + hm[m,:]; tf32-rounded.
// ---------------------------------------------------------------------------
__global__ void spmm_nz(const int* __restrict__ nzc, const int* __restrict__ nzi,
                        const float* __restrict__ nzv, const float* __restrict__ adj,
                        const float* __restrict__ hm, float* __restrict__ U)
{
    const int m = blockIdx.x;
    const int b = m / NNODE;
    const float* hmb = hm + (size_t)b * NNODE * ENC;
    const int d0 = threadIdx.x * 4;
    int cnt = nzc[m];
    float4 acc = *reinterpret_cast<const float4*>(hm + (size_t)m * ENC + d0);

    if (cnt <= MAXNZ) {
        __shared__ int   si[MAXNZ];
        __shared__ float sv[MAXNZ];
        for (int t = threadIdx.x; t < cnt; t += 128) {
            si[t] = nzi[m * MAXNZ + t];
            sv[t] = nzv[m * MAXNZ + t];
        }
        __syncthreads();
#pragma unroll 4
        for (int t = 0; t < cnt; t++) {
            float a = sv[t];
            const float4 hv = *reinterpret_cast<const float4*>(
                hmb + (size_t)si[t] * ENC + d0);
            acc.x += a * hv.x; acc.y += a * hv.y;
            acc.z += a * hv.z; acc.w += a * hv.w;
        }
    } else {
        int i = m - b * NNODE;
        const float* a0 = adj + ((size_t)b * NET) * NNODE * NNODE + (size_t)i * NNODE;
        const float* a1 = a0 + NNODE * NNODE;
        const float* a2 = a1 + NNODE * NNODE;
        for (int j = 0; j < NNODE; j++) {
            float a = a0[j] + a1[j] + a2[j];
            if (a != 0.f) {
                const float4 hv = *reinterpret_cast<const float4*>(
                    hmb + (size_t)j * ENC + d0);
                acc.x += a * hv.x; acc.y += a * hv.y;
                acc.z += a * hv.z; acc.w += a * hv.w;
            }
        }
    }
    acc.x = tf32r(acc.x); acc.y = tf32r(acc.y);
    acc.z = tf32r(acc.z); acc.w = tf32r(acc.w);
    *reinterpret_cast<float4*>(U + (size_t)m * ENC + d0) = acc;
}

// ---------------------------------------------------------------------------
// Attention: grid (16 tiles, 8 batches), block 256 (8 warps), qc tile in smem.
// ---------------------------------------------------------------------------
__global__ void __launch_bounds__(256) attn2(
    const float* __restrict__ L, const float* __restrict__ qc,
    const float* __restrict__ wa, float* __restrict__ n2q,
    float* __restrict__ smax)
{
    extern __shared__ float qs[];   // [NQ][ENC]
    __shared__ float sqv[32];
    const int b = blockIdx.y;
    const int tile = blockIdx.x;
    const int tid = threadIdx.x, lane = tid & 31, warp = tid >> 5;

    // stage qc[b] (25x512)
    {
        const float4* src = (const float4*)(qc + (size_t)b * NQ * ENC);
        float4* dst = (float4*)qs;
        for (int i = tid; i < NQ * ENC / 4; i += 256) dst[i] = src[i];
    }
    __syncthreads();

    // sq[q] = qc[q] . wa_q
    for (int q = warp; q < NQ; q += 8) {
        float s = 0.f;
        for (int d = lane; d < ENC; d += 32) s += qs[q * ENC + d] * wa[ENC + d];
        s = warpSum(s);
        if (lane == 0) sqv[q] = s;
    }

    float4 wan[4], was[4];
#pragma unroll
    for (int j = 0; j < 4; j++) {
        wan[j] = *(const float4*)(wa + j * 128 + lane * 4);
        was[j] = *(const float4*)(wa + 2 * ENC + j * 128 + lane * 4);
    }
    __syncthreads();

#pragma unroll
    for (int t = 0; t < 4; t++) {
        int n = tile * 32 + t * 8 + warp;
        if (n >= NNODE) continue;
        int m = b * NNODE + n;

        float4 lw[4];
        float sn = 0.f;
#pragma unroll
        for (int j = 0; j < 4; j++) {
            float4 Lv = *(const float4*)(L + (size_t)m * ENC + j * 128 + lane * 4);
            sn += Lv.x * wan[j].x + Lv.y * wan[j].y
                + Lv.z * wan[j].z + Lv.w * wan[j].w;
            lw[j].x = Lv.x * was[j].x; lw[j].y = Lv.y * was[j].y;
            lw[j].z = Lv.z * was[j].z; lw[j].w = Lv.w * was[j].w;
        }
        sn = warpSum(sn);

        float simq = -1e30f;
#pragma unroll
        for (int q = 0; q < NQ; q++) {
            float s = 0.f;
#pragma unroll
            for (int j = 0; j < 4; j++) {
                const float4 qv = *(const float4*)(qs + q * ENC + j * 128 + lane * 4);
                s += lw[j].x * qv.x + lw[j].y * qv.y
                   + lw[j].z * qv.z + lw[j].w * qv.w;
            }
            s = warpSum(s);
            if (lane == q) simq = sn + sqv[q] + s;
        }
        float mx = warpMax(lane < NQ ? simq : -1e30f);
        float e = (lane < NQ) ? __expf(simq - mx) : 0.f;
        float Z = warpSum(e);
        float p = e / Z;
        if (lane == 0) smax[m] = mx;

        float4 accv[4];
#pragma unroll
        for (int j = 0; j < 4; j++) accv[j] = make_float4(0.f, 0.f, 0.f, 0.f);
#pragma unroll
        for (int q = 0; q < NQ; q++) {
            float pq = __shfl_sync(0xffffffffu, p, q);
#pragma unroll
            for (int j = 0; j < 4; j++) {
                const float4 qv = *(const float4*)(qs + q * ENC + j * 128 + lane * 4);
                accv[j].x += pq * qv.x; accv[j].y += pq * qv.y;
                accv[j].z += pq * qv.z; accv[j].w += pq * qv.w;
            }
        }
#pragma unroll
        for (int j = 0; j < 4; j++)
            *(float4*)(n2q + (size_t)m * ENC + j * 128 + lane * 4) = accv[j];
    }
}

// ---------------------------------------------------------------------------
// Per batch: bvec = softmax_n(smax); q2n = bvec @ nc
// ---------------------------------------------------------------------------
__global__ void q2n_kernel(const float* __restrict__ smax, const float* __restrict__ nc,
                           float* __restrict__ q2n)
{
    const int b = blockIdx.x;
    const int tid = threadIdx.x;            // 256
    const int lane = tid & 31, warp = tid >> 5;
    __shared__ float w[NNODE];
    __shared__ float red[8];

    float mx = -1e30f;
    for (int n = tid; n < NNODE; n += 256) mx = fmaxf(mx, smax[b * NNODE + n]);
    mx = warpMax(mx);
    if (lane == 0) red[warp] = mx;
    __syncthreads();
    float bmax = red[0];
#pragma unroll
    for (int i = 1; i < 8; i++) bmax = fmaxf(bmax, red[i]);
    __syncthreads();

    float s = 0.f;
    for (int n = tid; n < NNODE; n += 256) {
        float e = __expf(smax[b * NNODE + n] - bmax);
        w[n] = e; s += e;
    }
    s = warpSum(s);
    if (lane == 0) red[warp] = s;
    __syncthreads();
    float Z = 0.f;
#pragma unroll
    for (int i = 0; i < 8; i++) Z += red[i];
    float inv = 1.f / Z;

    const int d0 = tid * 2;
    float a0 = 0.f, a1 = 0.f;
#pragma unroll 4
    for (int n = 0; n < NNODE; n++) {
        float ww = w[n] * inv;
        const float2 r = *reinterpret_cast<const float2*>(
            nc + ((size_t)b * NNODE + n) * ENC + d0);
        a0 += ww * r.x; a1 += ww * r.y;
    }
    q2n[b * ENC + d0]     = a0;
    q2n[b * ENC + d0 + 1] = a1;
}

// ---------------------------------------------------------------------------
// g = [nc, n2q, nc*n2q, nc*q2n], tf32-rounded
// ---------------------------------------------------------------------------
__global__ void build_g(const float* __restrict__ nc, const float* __restrict__ n2q,
                        const float* __restrict__ q2n, float* __restrict__ g)
{
    int idx = blockIdx.x * 256 + threadIdx.x;
    int m = idx >> 9, d = idx & 511;
    int b = m / NNODE;
    float a = nc[idx], t = n2q[idx], qn = q2n[b * ENC + d];
    size_t base = (size_t)m * (4 * ENC) + d;
    g[base]           = tf32r(a);
    g[base + ENC]     = tf32r(t);
    g[base + 2 * ENC] = tf32r(a * t);
    g[base + 3 * ENC] = tf32r(a * qn);
}

// ---------------------------------------------------------------------------
// raw[m] = sum_h tanh(sum_s h1p[s][m][h] + b1[h]) * W2[h] + b2
// ---------------------------------------------------------------------------
__global__ void raw2_kernel(const float* __restrict__ h1p, const float* __restrict__ b1,
                            const float* __restrict__ W2, const float* __restrict__ b2,
                            float* __restrict__ raw)
{
    int gw = (blockIdx.x * blockDim.x + threadIdx.x) >> 5;
    int lane = threadIdx.x & 31;
    if (gw >= MROWS) return;
    const size_t stride = (size_t)MROWS * 128;
    float s = 0.f;
    for (int h = lane; h < 128; h += 32) {
        size_t o = (size_t)gw * 128 + h;
        float v = h1p[o] + h1p[o + stride] + h1p[o + 2*stride] + h1p[o + 3*stride]
                + b1[h];
        s += tanhf(v) * W2[h];
    }
    s = warpSum(s);
    if (lane == 0) raw[gw] = s + b2[0];
}

// ---------------------------------------------------------------------------
// out[b,c] = max_n f(mask*raw),  f(0) = -1e6
// ---------------------------------------------------------------------------
__global__ void out_kernel(const int* __restrict__ mask, const float* __restrict__ raw,
                           float* __restrict__ out)
{
    int gw = (blockIdx.x * blockDim.x + threadIdx.x) >> 5;
    int lane = threadIdx.x & 31;
    if (gw >= BATCH * NC) return;
    int b = gw / NC, c = gw - b * NC;
    const int* mr = mask + ((size_t)b * NC + c) * NNODE;
    const float* rr = raw + b * NNODE;
    float mx = -1e30f;
    for (int n = lane; n < NNODE; n += 32) {
        float p = (float)mr[n] * rr[n];
        if (p == 0.f) p = -1e6f;
        mx = fmaxf(mx, p);
    }
    mx = warpMax(mx);
    if (lane == 0) out[gw] = mx;
}

// ---------------------------------------------------------------------------
// Launch
// ---------------------------------------------------------------------------
extern "C" void kernel_launch(void* const* d_in, const int* in_sizes, int n_in,
                              void* d_out, int out_size)
{
    const float* nodes_glove = (const float*)d_in[0];
    const float* query_glove = (const float*)d_in[1];
    const float* adj         = (const float*)d_in[2];
    const int*   nlen        = (const int*)  d_in[3];
    const int*   mask        = (const int*)  d_in[4];
    const float* Wn = (const float*)d_in[5];
    const float* bn = (const float*)d_in[6];
    const float* Wq = (const float*)d_in[7];
    const float* bq = (const float*)d_in[8];
    const float* Wh = (const float*)d_in[9];
    const float* bh = (const float*)d_in[10];
    const float* Wc = (const float*)d_in[11];
    const float* bc = (const float*)d_in[12];
    const float* wa = (const float*)d_in[13];
    const float* W1 = (const float*)d_in[14];
    const float* b1 = (const float*)d_in[15];
    const float* W2 = (const float*)d_in[16];
    const float* b2 = (const float*)d_in[17];
    float* out = (float*)d_out;

    float *p_nc, *p_qc, *p_L, *p_L2, *p_hm, *p_U,
          *p_n2q, *p_smax, *p_q2n, *p_g, *p_h1p, *p_raw;
    float *p_Wnr, *p_Wqr, *p_Whr, *p_Wcr, *p_W1r, *p_ngr, *p_qgr;
    float *p_nzv; int *p_nzc, *p_nzi;
    cudaGetSymbolAddress((void**)&p_nc,  g_nc);
    cudaGetSymbolAddress((void**)&p_qc,  g_qc);
    cudaGetSymbolAddress((void**)&p_L,   g_L);
    cudaGetSymbolAddress((void**)&p_L2,  g_L2);
    cudaGetSymbolAddress((void**)&p_hm,  g_hm);
    cudaGetSymbolAddress((void**)&p_U,   g_U);
    cudaGetSymbolAddress((void**)&p_n2q, g_n2q);
    cudaGetSymbolAddress((void**)&p_smax,g_smax);
    cudaGetSymbolAddress((void**)&p_q2n, g_q2n);
    cudaGetSymbolAddress((void**)&p_g,   g_g);
    cudaGetSymbolAddress((void**)&p_h1p, g_h1p);
    cudaGetSymbolAddress((void**)&p_raw, g_raw);
    cudaGetSymbolAddress((void**)&p_Wnr, g_Wnr);
    cudaGetSymbolAddress((void**)&p_Wqr, g_Wqr);
    cudaGetSymbolAddress((void**)&p_Whr, g_Whr);
    cudaGetSymbolAddress((void**)&p_Wcr, g_Wcr);
    cudaGetSymbolAddress((void**)&p_W1r, g_W1r);
    cudaGetSymbolAddress((void**)&p_ngr, g_ngr);
    cudaGetSymbolAddress((void**)&p_qgr, g_qgr);
    cudaGetSymbolAddress((void**)&p_nzc, g_nzc);
    cudaGetSymbolAddress((void**)&p_nzi, g_nzi);
    cudaGetSymbolAddress((void**)&p_nzv, g_nzv);

    // opt-in dynamic smem (idempotent)
    cudaFuncSetAttribute(gemm_compress, cudaFuncAttributeMaxDynamicSharedMemorySize, GEMM_SMEM);
    cudaFuncSetAttribute(gemm_hm,       cudaFuncAttributeMaxDynamicSharedMemorySize, GEMM_SMEM);
    cudaFuncSetAttribute(gemm_att,      cudaFuncAttributeMaxDynamicSharedMemorySize, GEMM_SMEM);
    cudaFuncSetAttribute(gemm_w1,       cudaFuncAttributeMaxDynamicSharedMemorySize, GEMM_SMEM);
    cudaFuncSetAttribute(attn2,         cudaFuncAttributeMaxDynamicSharedMemorySize, ATTN_SMEM);

    // prep: round inputs + adjacency nz lists (one launch)
    prep_kernel<<<NB_ROUND + NB_NZ, 256>>>(
        (const float4*)Wn, (const float4*)Wq, (const float4*)Wh,
        (const float4*)Wc, (const float4*)W1,
        (const float4*)nodes_glove, (const float4*)query_glove,
        (float4*)p_Wnr, (float4*)p_Wqr, (float4*)p_Whr,
        (float4*)p_Wcr, (float4*)p_W1r, (float4*)p_ngr, (float4*)p_qgr,
        adj, p_nzc, p_nzi, p_nzv);

    // nodes + query compress in one launch
    gemm_compress<<<dim3(ENC/128, 34), 256, GEMM_SMEM>>>(
        p_ngr, p_Wnr, bn, p_nc, p_L, nlen, p_qgr, p_Wqr, bq, p_qc);

    float* Lc = p_L;
    float* Ln = p_L2;
    for (int h = 0; h < HOPS; h++) {
        gemm_hm<<<dim3(ENC/128, 32), 256, GEMM_SMEM>>>(Lc, p_Whr, bh, p_hm, nlen);
        spmm_nz<<<MROWS, 128>>>(p_nzc, p_nzi, p_nzv, adj, p_hm, p_U);
        gemm_att<<<dim3(ENC/128, 32), 256, GEMM_SMEM>>>(p_U, Lc, p_Wcr, bc, nlen, Ln);
        float* t = Lc; Lc = Ln; Ln = t;
    }

    // attention (qc staged in smem)
    attn2<<<dim3(16, 8), 256, ATTN_SMEM>>>(Lc, p_qc, wa, p_n2q, p_smax);
    q2n_kernel<<<BATCH, 256>>>(p_smax, p_nc, p_q2n);

    // scorer
    build_g<<<MROWS*ENC/256, 256>>>(p_nc, p_n2q, p_q2n, p_g);
    gemm_w1<<<dim3(1, 32, 4), 256, GEMM_SMEM>>>(p_g, p_W1r, p_h1p);
    raw2_kernel<<<(MROWS*32 + 255) / 256, 256>>>(p_h1p, b1, W2, b2, p_raw);

    // masked max
    out_kernel<<<(BATCH*NC*32 + 255) / 256, 256>>>(mask, p_raw, out);
}

// round 7
// speedup vs baseline: 4.3122x; 1.0545x over previous
#include <cuda_runtime.h>
#include <cstdint>

// ---------------------------------------------------------------------------
// Problem constants
// ---------------------------------------------------------------------------
#define BATCH 8
#define NNODE 500
#define NQ    25
#define ENC   512
#define DIN   300
#define NC    70
#define NET   3
#define HOPS  3
#define MROWS (BATCH*NNODE)   // 4000
#define QROWS (BATCH*NQ)      // 200
#define MAXNZ 192

// GEMM smem geometry (u32 units)
#define ASTRIDE 36
#define BSTRIDE 136
#define ABUF (128*ASTRIDE)          // 4608
#define BBUF (32*BSTRIDE)           // 4352
#define GEMM_SMEM ((2*ABUF + 2*BBUF) * 4)   // 71680 bytes
#define ATTN_SMEM (NQ*ENC*4)                // 51200 bytes

// ---------------------------------------------------------------------------
// Device scratch
// ---------------------------------------------------------------------------
__device__ float g_nc  [MROWS*ENC];
__device__ float g_qc  [QROWS*ENC];
__device__ float g_L   [MROWS*ENC];
__device__ float g_L2  [MROWS*ENC];
__device__ float g_hm  [MROWS*ENC];
__device__ float g_U   [MROWS*ENC];
__device__ float g_n2q [MROWS*ENC];
__device__ float g_smax[MROWS];
__device__ float g_q2n [BATCH*ENC];
__device__ float g_g   [MROWS*4*ENC];
__device__ float g_h1p [4*MROWS*128];
__device__ float g_raw [MROWS];
// tf32-rounded copies of inputs
__device__ float g_Wnr [DIN*ENC];
__device__ float g_Wqr [DIN*ENC];
__device__ float g_Whr [ENC*ENC];
__device__ float g_Wcr [2*ENC*ENC];
__device__ float g_W1r [4*ENC*128];
__device__ float g_ngr [MROWS*DIN];
__device__ float g_qgr [QROWS*DIN];
// adjacency sparsity
__device__ int   g_nzc [MROWS];
__device__ int   g_nzi [MROWS*MAXNZ];
__device__ float g_nzv [MROWS*MAXNZ];

// ---------------------------------------------------------------------------
// Helpers
// ---------------------------------------------------------------------------
__device__ __forceinline__ float warpSum(float v) {
#pragma unroll
    for (int o = 16; o; o >>= 1) v += __shfl_xor_sync(0xffffffffu, v, o);
    return v;
}
__device__ __forceinline__ float warpMax(float v) {
#pragma unroll
    for (int o = 16; o; o >>= 1) v = fmaxf(v, __shfl_xor_sync(0xffffffffu, v, o));
    return v;
}
__device__ __forceinline__ float tf32r(float f) {
    uint32_t u;
    asm("cvt.rna.tf32.f32 %0, %1;" : "=r"(u) : "f"(f));
    return __uint_as_float(u);
}
__device__ __forceinline__ void mma_tf32(float* c, const uint32_t* a, const uint32_t* b) {
    asm volatile(
        "mma.sync.aligned.m16n8k8.row.col.f32.tf32.tf32.f32 "
        "{%0,%1,%2,%3}, {%4,%5,%6,%7}, {%8,%9}, {%0,%1,%2,%3};"
        : "+f"(c[0]), "+f"(c[1]), "+f"(c[2]), "+f"(c[3])
        : "r"(a[0]), "r"(a[1]), "r"(a[2]), "r"(a[3]), "r"(b[0]), "r"(b[1]));
}
__device__ __forceinline__ uint32_t smem_u32(const void* p) {
    return (uint32_t)__cvta_generic_to_shared(p);
}
__device__ __forceinline__ void cp_async16(uint32_t dst, const void* src, int sz) {
    asm volatile("cp.async.ca.shared.global [%0], [%1], 16, %2;\n"
                 :: "r"(dst), "l"(src), "r"(sz));
}
__device__ __forceinline__ void cp_commit() {
    asm volatile("cp.async.commit_group;\n" ::: "memory");
}
__device__ __forceinline__ void cp_wait0() {
    asm volatile("cp.async.wait_group 0;\n" ::: "memory");
}

// Zero a 128x128 output tile (coalesced), guarded by r < M.
__device__ __forceinline__ void zero_tile(float* __restrict__ C, int ldc,
                                          int rowBlock, int colBlock, int M)
{
    const float4 z = make_float4(0.f, 0.f, 0.f, 0.f);
    for (int i = threadIdx.x; i < 128 * 32; i += 256) {
        int r = rowBlock + (i >> 5);
        int c4 = (i & 31) * 4;
        if (r < M)
            *reinterpret_cast<float4*>(C + (size_t)r * ldc + colBlock + c4) = z;
    }
}

// Is any row of [rowBlock, rowBlock+128) active (i < nlen[b])?
__device__ __forceinline__ bool tile_active(int rowBlock, const int* __restrict__ nlen)
{
    int b0 = rowBlock / NNODE;
    int b1 = (rowBlock + 127) / NNODE;
    if (b1 >= BATCH) b1 = BATCH - 1;
    bool act = false;
    for (int b = b0; b <= b1; b++) {
        int seg = rowBlock - b * NNODE;
        if (seg < 0) seg = 0;
        if (seg < nlen[b]) act = true;
    }
    return act;
}

// ---------------------------------------------------------------------------
// prep: tf32-round all GEMM operand inputs + build adjacency nz lists.
// ---------------------------------------------------------------------------
#define NB_ROUND 2555    // ceil(653944/256)
#define NB_NZ    500     // 4000 rows / 8 warps per block
__global__ void prep_kernel(
    const float4* __restrict__ Wn, const float4* __restrict__ Wq,
    const float4* __restrict__ Wh, const float4* __restrict__ Wc,
    const float4* __restrict__ W1, const float4* __restrict__ ng,
    const float4* __restrict__ qg,
    float4* __restrict__ oWn, float4* __restrict__ oWq, float4* __restrict__ oWh,
    float4* __restrict__ oWc, float4* __restrict__ oW1, float4* __restrict__ ong,
    float4* __restrict__ oqg,
    const float* __restrict__ adj, int* __restrict__ nzc,
    int* __restrict__ nzi, float* __restrict__ nzv)
{
    if (blockIdx.x < NB_ROUND) {
        int idx = blockIdx.x * 256 + threadIdx.x;
        const float4* src; float4* dst; int off;
        if      (idx < 38400)  { src = Wn; dst = oWn; off = idx; }
        else if (idx < 76800)  { src = Wq; dst = oWq; off = idx - 38400; }
        else if (idx < 142336) { src = Wh; dst = oWh; off = idx - 76800; }
        else if (idx < 273408) { src = Wc; dst = oWc; off = idx - 142336; }
        else if (idx < 338944) { src = W1; dst = oW1; off = idx - 273408; }
        else if (idx < 638944) { src = ng; dst = ong; off = idx - 338944; }
        else if (idx < 653944) { src = qg; dst = oqg; off = idx - 638944; }
        else return;
        float4 v = src[off];
        v.x = tf32r(v.x); v.y = tf32r(v.y); v.z = tf32r(v.z); v.w = tf32r(v.w);
        dst[off] = v;
    } else {
        int gw = (blockIdx.x - NB_ROUND) * 8 + (threadIdx.x >> 5);
        int lane = threadIdx.x & 31;
        if (gw >= MROWS) return;
        int b = gw / NNODE;
        int i = gw - b * NNODE;
        const float* a0 = adj + ((size_t)b * NET) * NNODE * NNODE + (size_t)i * NNODE;
        const float* a1 = a0 + NNODE * NNODE;
        const float* a2 = a1 + NNODE * NNODE;
        int cnt = 0;
        for (int jb = 0; jb < NNODE; jb += 32) {
            int j = jb + lane;
            float v = 0.f;
            if (j < NNODE) v = a0[j] + a1[j] + a2[j];
            unsigned m = __ballot_sync(0xffffffffu, v != 0.f);
            int pos = cnt + __popc(m & ((1u << lane) - 1u));
            if (v != 0.f && pos < MAXNZ) {
                nzi[gw * MAXNZ + pos] = j;
                nzv[gw * MAXNZ + pos] = v;
            }
            cnt += __popc(m);
        }
        if (lane == 0) nzc[gw] = cnt;
    }
}

// ---------------------------------------------------------------------------
// GEMM core (BK=32, tile 128x128, 8 warps, cp.async double-buffered)
// ---------------------------------------------------------------------------
struct GemmCtx {
    uint32_t* sh;
    int tid, lane, warp, wm, wn, tg, tq;
};

__device__ __forceinline__ void gemm_ctx_init(GemmCtx& cx, uint32_t* sh) {
    cx.sh = sh;
    cx.tid = threadIdx.x; cx.lane = cx.tid & 31; cx.warp = cx.tid >> 5;
    cx.wm = cx.warp >> 1; cx.wn = cx.warp & 1;
    cx.tg = cx.lane >> 2; cx.tq = cx.lane & 3;
}

__device__ __forceinline__ void gemm_core(
    GemmCtx& cx,
    const float* __restrict__ A, int lda,
    const float* __restrict__ Ab, int ldab, int ksplit,
    const float* __restrict__ W, int ldw,
    int rowBlock, int colBlock, int kBase, int M, int K,
    float acc[2][8][4])
{
    uint32_t* sh = cx.sh;
    const int tid = cx.tid, tg = cx.tg, tq = cx.tq, wm = cx.wm, wn = cx.wn;
    uint32_t* Bbase = sh + 2 * ABUF;

    auto loadTiles = [&](int k0, int buf) {
        uint32_t* Ad = sh + buf * ABUF;
        uint32_t* Bd = Bbase + buf * BBUF;
#pragma unroll
        for (int it = 0; it < 4; it++) {
            int idx = it * 256 + tid;
            int m = idx >> 3, cc = idx & 7;
            int gr = rowBlock + m;
            int kk = k0 + cc * 4;
            int gk = kBase + kk;
            const float* src = (gk < ksplit)
                ? A  + (size_t)gr * lda  + gk
                : Ab + (size_t)gr * ldab + (gk - ksplit);
            int sz = (gr < M && kk < K) ? 16 : 0;
            cp_async16(smem_u32(Ad + m * ASTRIDE + cc * 4), src, sz);
        }
#pragma unroll
        for (int it = 0; it < 4; it++) {
            int idx = it * 256 + tid;
            int k = idx >> 5, cc = idx & 31;
            int kk = k0 + k;
            const float* src = W + (size_t)(kBase + kk) * ldw + colBlock + cc * 4;
            int sz = (kk < K) ? 16 : 0;
            cp_async16(smem_u32(Bd + k * BSTRIDE + cc * 4), src, sz);
        }
        cp_commit();
    };

    const int nsteps = (K + 31) / 32;
    loadTiles(0, 0);
    int buf = 0;

    for (int s = 0; s < nsteps; s++) {
        cp_wait0();
        __syncthreads();
        if (s + 1 < nsteps) loadTiles((s + 1) * 32, buf ^ 1);

        uint32_t* As = sh + buf * ABUF;
        uint32_t* Bs = Bbase + buf * BBUF;
#pragma unroll
        for (int ks = 0; ks < 4; ks++) {
            const int kb = ks * 8;
            uint32_t af[2][4], bf[8][2];
#pragma unroll
            for (int mt = 0; mt < 2; mt++) {
                int r0 = wm * 32 + mt * 16 + tg;
                af[mt][0] = As[(r0    ) * ASTRIDE + kb + tq];
                af[mt][1] = As[(r0 + 8) * ASTRIDE + kb + tq];
                af[mt][2] = As[(r0    ) * ASTRIDE + kb + tq + 4];
                af[mt][3] = As[(r0 + 8) * ASTRIDE + kb + tq + 4];
            }
#pragma unroll
            for (int nt = 0; nt < 8; nt++) {
                int c0 = wn * 64 + nt * 8 + tg;
                bf[nt][0] = Bs[(kb + tq    ) * BSTRIDE + c0];
                bf[nt][1] = Bs[(kb + tq + 4) * BSTRIDE + c0];
            }
#pragma unroll
            for (int mt = 0; mt < 2; mt++)
#pragma unroll
                for (int nt = 0; nt < 8; nt++)
                    mma_tf32(acc[mt][nt], af[mt], bf[nt]);
        }
        buf ^= 1;
        __syncthreads();
    }
}

// ---------------------------------------------------------------------------
// Combined compress GEMM: blockIdx.y<32 -> nodes (tanh + masked L),
// else -> query (plain). K=300. (No row skipping: nc needed for all rows.)
// ---------------------------------------------------------------------------
__global__ void __launch_bounds__(256, 1) gemm_compress(
    const float* __restrict__ ng, const float* __restrict__ Wn,
    const float* __restrict__ bn, float* __restrict__ nc,
    float* __restrict__ L, const int* __restrict__ nlen,
    const float* __restrict__ qg, const float* __restrict__ Wq,
    const float* __restrict__ bq, float* __restrict__ qc)
{
    extern __shared__ uint32_t sh_[];
    GemmCtx cx; gemm_ctx_init(cx, sh_);
    float acc[2][8][4];
#pragma unroll
    for (int i = 0; i < 2; i++)
#pragma unroll
        for (int j = 0; j < 8; j++)
#pragma unroll
            for (int l = 0; l < 4; l++) acc[i][j][l] = 0.f;

    const bool isQ = blockIdx.y >= 32;
    const float* A    = isQ ? qg : ng;
    const float* W    = isQ ? Wq : Wn;
    const float* bias = isQ ? bq : bn;
    float* C          = isQ ? qc : nc;
    const int M       = isQ ? QROWS : MROWS;
    const int rowBlock = (isQ ? blockIdx.y - 32 : blockIdx.y) * 128;
    const int colBlock = blockIdx.x * 128;

    gemm_core(cx, A, DIN, A, DIN, DIN, W, ENC,
              rowBlock, colBlock, 0, M, DIN, acc);

#pragma unroll
    for (int mt = 0; mt < 2; mt++) {
#pragma unroll
        for (int half = 0; half < 2; half++) {
            int r = rowBlock + cx.wm * 32 + mt * 16 + cx.tg + half * 8;
            if (r >= M) continue;
            float rowmask = 1.f;
            if (!isQ) {
                int bb = r / NNODE;
                int ii = r - bb * NNODE;
                rowmask = (ii < nlen[bb]) ? 1.f : 0.f;
            }
#pragma unroll
            for (int nt = 0; nt < 8; nt++) {
#pragma unroll
                for (int e = 0; e < 2; e++) {
                    int c = colBlock + cx.wn * 64 + nt * 8 + cx.tq * 2 + e;
                    float v = acc[mt][nt][half * 2 + e] + bias[c];
                    size_t off = (size_t)r * ENC + c;
                    if (isQ) {
                        C[off] = v;
                    } else {
                        float t = tanhf(v);
                        C[off] = t;
                        L[off] = tf32r(t) * rowmask;
                    }
                }
            }
        }
    }
}

// ---------------------------------------------------------------------------
// Hop GEMM A: hm = (L @ Wh + bh) * nmask. Dead tiles write zeros fast.
// ---------------------------------------------------------------------------
__global__ void __launch_bounds__(256, 1) gemm_hm(
    const float* __restrict__ Lc, const float* __restrict__ Wh,
    const float* __restrict__ bh, float* __restrict__ hm,
    const int* __restrict__ nlen)
{
    const int rowBlock = blockIdx.y * 128;
    const int colBlock = blockIdx.x * 128;
    const int M = MROWS;

    if (!tile_active(rowBlock, nlen)) {
        zero_tile(hm, ENC, rowBlock, colBlock, M);
        return;
    }

    extern __shared__ uint32_t sh_[];
    GemmCtx cx; gemm_ctx_init(cx, sh_);
    float acc[2][8][4];
#pragma unroll
    for (int i = 0; i < 2; i++)
#pragma unroll
        for (int j = 0; j < 8; j++)
#pragma unroll
            for (int l = 0; l < 4; l++) acc[i][j][l] = 0.f;

    gemm_core(cx, Lc, ENC, Lc, ENC, ENC, Wh, ENC,
              rowBlock, colBlock, 0, M, ENC, acc);

#pragma unroll
    for (int mt = 0; mt < 2; mt++) {
#pragma unroll
        for (int half = 0; half < 2; half++) {
            int r = rowBlock + cx.wm * 32 + mt * 16 + cx.tg + half * 8;
            if (r >= M) continue;
            int bb = r / NNODE;
            int ii = r - bb * NNODE;
            float rowmask = (ii < nlen[bb]) ? 1.f : 0.f;
#pragma unroll
            for (int nt = 0; nt < 8; nt++) {
#pragma unroll
                for (int e = 0; e < 2; e++) {
                    int c = colBlock + cx.wn * 64 + nt * 8 + cx.tq * 2 + e;
                    float v = acc[mt][nt][half * 2 + e] + bh[c];
                    hm[(size_t)r * ENC + c] = v * rowmask;
                }
            }
        }
    }
}

// ---------------------------------------------------------------------------
// Hop GEMM B: att = sigmoid([U,L] @ Wc + bc)*nmask;
//             Lnew = tf32r(att*tanh(U) + (1-att)*Lold)
// Dead tiles: Lnew = Lold = 0 -> write zeros fast (ping-pong buffer!).
// ---------------------------------------------------------------------------
__global__ void __launch_bounds__(256, 1) gemm_att(
    const float* __restrict__ U, const float* __restrict__ Lold,
    const float* __restrict__ Wc, const float* __restrict__ bc,
    const int* __restrict__ nlen, float* __restrict__ Lnew)
{
    const int rowBlock = blockIdx.y * 128;
    const int colBlock = blockIdx.x * 128;
    const int M = MROWS;

    if (!tile_active(rowBlock, nlen)) {
        zero_tile(Lnew, ENC, rowBlock, colBlock, M);
        return;
    }

    extern __shared__ uint32_t sh_[];
    GemmCtx cx; gemm_ctx_init(cx, sh_);
    float acc[2][8][4];
#pragma unroll
    for (int i = 0; i < 2; i++)
#pragma unroll
        for (int j = 0; j < 8; j++)
#pragma unroll
            for (int l = 0; l < 4; l++) acc[i][j][l] = 0.f;

    gemm_core(cx, U, ENC, Lold, ENC, ENC, Wc, ENC,
              rowBlock, colBlock, 0, M, 2 * ENC, acc);

#pragma unroll
    for (int mt = 0; mt < 2; mt++) {
#pragma unroll
        for (int half = 0; half < 2; half++) {
            int r = rowBlock + cx.wm * 32 + mt * 16 + cx.tg + half * 8;
            if (r >= M) continue;
            int bb = r / NNODE;
            int ii = r - bb * NNODE;
            float rowmask = (ii < nlen[bb]) ? 1.f : 0.f;
#pragma unroll
            for (int nt = 0; nt < 8; nt++) {
#pragma unroll
                for (int e = 0; e < 2; e++) {
                    int c = colBlock + cx.wn * 64 + nt * 8 + cx.tq * 2 + e;
                    float v = acc[mt][nt][half * 2 + e] + bc[c];
                    size_t off = (size_t)r * ENC + c;
                    float att = rowmask / (1.f + __expf(-v));
                    Lnew[off] = tf32r(att * tanhf(U[off]) +
                                      (1.f - att) * Lold[off]);
                }
            }
        }
    }
}

// ---------------------------------------------------------------------------
// W1 GEMM: split-K=4; slab z (all rows needed — raw scores every node)
// ---------------------------------------------------------------------------
__global__ void __launch_bounds__(256, 1) gemm_w1(
    const float* __restrict__ g, const float* __restrict__ W1,
    float* __restrict__ h1p)
{
    extern __shared__ uint32_t sh_[];
    GemmCtx cx; gemm_ctx_init(cx, sh_);
    float acc[2][8][4];
#pragma unroll
    for (int i = 0; i < 2; i++)
#pragma unroll
        for (int j = 0; j < 8; j++)
#pragma unroll
            for (int l = 0; l < 4; l++) acc[i][j][l] = 0.f;

    const int rowBlock = blockIdx.y * 128;
    const int colBlock = 0;
    const int z = blockIdx.z;
    const int M = MROWS;

    gemm_core(cx, g, 4*ENC, g, 4*ENC, 4*ENC, W1, 128,
              rowBlock, colBlock, z * 512, M, 512, acc);

#pragma unroll
    for (int mt = 0; mt < 2; mt++) {
#pragma unroll
        for (int half = 0; half < 2; half++) {
            int r = rowBlock + cx.wm * 32 + mt * 16 + cx.tg + half * 8;
            if (r >= M) continue;
#pragma unroll
            for (int nt = 0; nt < 8; nt++) {
#pragma unroll
                for (int e = 0; e < 2; e++) {
                    int c = colBlock + cx.wn * 64 + nt * 8 + cx.tq * 2 + e;
                    float v = acc[mt][nt][half * 2 + e];
                    h1p[((size_t)z * M + r) * 128 + c] = v;
                }
            }
        }
    }
}

// ---------------------------------------------------------------------------
// U[m,:] = sum_t val[t]*hm[b, idx[t], :] + hm[m,:]; tf32-rounded.
// Masked rows (i >= nlen[b]): U only feeds masked outputs -> write zeros.
// ---------------------------------------------------------------------------
__global__ void spmm_nz(const int* __restrict__ nzc, const int* __restrict__ nzi,
                        const float* __restrict__ nzv, const float* __restrict__ adj,
                        const float* __restrict__ hm, float* __restrict__ U,
                        const int* __restrict__ nlen)
{
    const int m = blockIdx.x;
    const int b = m / NNODE;
    const int i = m - b * NNODE;
    const int d0 = threadIdx.x * 4;

    if (i >= nlen[b]) {
        *reinterpret_cast<float4*>(U + (size_t)m * ENC + d0) =
            make_float4(0.f, 0.f, 0.f, 0.f);
        return;
    }

    const float* hmb = hm + (size_t)b * NNODE * ENC;
    int cnt = nzc[m];
    float4 acc = *reinterpret_cast<const float4*>(hm + (size_t)m * ENC + d0);

    if (cnt <= MAXNZ) {
        __shared__ int   si[MAXNZ];
        __shared__ float sv[MAXNZ];
        for (int t = threadIdx.x; t < cnt; t += 128) {
            si[t] = nzi[m * MAXNZ + t];
            sv[t] = nzv[m * MAXNZ + t];
        }
        __syncthreads();
#pragma unroll 4
        for (int t = 0; t < cnt; t++) {
            float a = sv[t];
            const float4 hv = *reinterpret_cast<const float4*>(
                hmb + (size_t)si[t] * ENC + d0);
            acc.x += a * hv.x; acc.y += a * hv.y;
            acc.z += a * hv.z; acc.w += a * hv.w;
        }
    } else {
        const float* a0 = adj + ((size_t)b * NET) * NNODE * NNODE + (size_t)i * NNODE;
        const float* a1 = a0 + NNODE * NNODE;
        const float* a2 = a1 + NNODE * NNODE;
        for (int j = 0; j < NNODE; j++) {
            float a = a0[j] + a1[j] + a2[j];
            if (a != 0.f) {
                const float4 hv = *reinterpret_cast<const float4*>(
                    hmb + (size_t)j * ENC + d0);
                acc.x += a * hv.x; acc.y += a * hv.y;
                acc.z += a * hv.z; acc.w += a * hv.w;
            }
        }
    }
    acc.x = tf32r(acc.x); acc.y = tf32r(acc.y);
    acc.z = tf32r(acc.z); acc.w = tf32r(acc.w);
    *reinterpret_cast<float4*>(U + (size_t)m * ENC + d0) = acc;
}

// ---------------------------------------------------------------------------
// Attention: grid (16 tiles, 8 batches), block 256 (8 warps), qc tile in smem.
// ---------------------------------------------------------------------------
__global__ void __launch_bounds__(256) attn2(
    const float* __restrict__ L, const float* __restrict__ qc,
    const float* __restrict__ wa, float* __restrict__ n2q,
    float* __restrict__ smax)
{
    extern __shared__ float qs[];   // [NQ][ENC]
    __shared__ float sqv[32];
    const int b = blockIdx.y;
    const int tile = blockIdx.x;
    const int tid = threadIdx.x, lane = tid & 31, warp = tid >> 5;

    {
        const float4* src = (const float4*)(qc + (size_t)b * NQ * ENC);
        float4* dst = (float4*)qs;
        for (int i = tid; i < NQ * ENC / 4; i += 256) dst[i] = src[i];
    }
    __syncthreads();

    for (int q = warp; q < NQ; q += 8) {
        float s = 0.f;
        for (int d = lane; d < ENC; d += 32) s += qs[q * ENC + d] * wa[ENC + d];
        s = warpSum(s);
        if (lane == 0) sqv[q] = s;
    }

    float4 wan[4], was[4];
#pragma unroll
    for (int j = 0; j < 4; j++) {
        wan[j] = *(const float4*)(wa + j * 128 + lane * 4);
        was[j] = *(const float4*)(wa + 2 * ENC + j * 128 + lane * 4);
    }
    __syncthreads();

#pragma unroll
    for (int t = 0; t < 4; t++) {
        int n = tile * 32 + t * 8 + warp;
        if (n >= NNODE) continue;
        int m = b * NNODE + n;

        float4 lw[4];
        float sn = 0.f;
#pragma unroll
        for (int j = 0; j < 4; j++) {
            float4 Lv = *(const float4*)(L + (size_t)m * ENC + j * 128 + lane * 4);
            sn += Lv.x * wan[j].x + Lv.y * wan[j].y
                + Lv.z * wan[j].z + Lv.w * wan[j].w;
            lw[j].x = Lv.x * was[j].x; lw[j].y = Lv.y * was[j].y;
            lw[j].z = Lv.z * was[j].z; lw[j].w = Lv.w * was[j].w;
        }
        sn = warpSum(sn);

        float simq = -1e30f;
#pragma unroll
        for (int q = 0; q < NQ; q++) {
            float s = 0.f;
#pragma unroll
            for (int j = 0; j < 4; j++) {
                const float4 qv = *(const float4*)(qs + q * ENC + j * 128 + lane * 4);
                s += lw[j].x * qv.x + lw[j].y * qv.y
                   + lw[j].z * qv.z + lw[j].w * qv.w;
            }
            s = warpSum(s);
            if (lane == q) simq = sn + sqv[q] + s;
        }
        float mx = warpMax(lane < NQ ? simq : -1e30f);
        float e = (lane < NQ) ? __expf(simq - mx) : 0.f;
        float Z = warpSum(e);
        float p = e / Z;
        if (lane == 0) smax[m] = mx;

        float4 accv[4];
#pragma unroll
        for (int j = 0; j < 4; j++) accv[j] = make_float4(0.f, 0.f, 0.f, 0.f);
#pragma unroll
        for (int q = 0; q < NQ; q++) {
            float pq = __shfl_sync(0xffffffffu, p, q);
#pragma unroll
            for (int j = 0; j < 4; j++) {
                const float4 qv = *(const float4*)(qs + q * ENC + j * 128 + lane * 4);
                accv[j].x += pq * qv.x; accv[j].y += pq * qv.y;
                accv[j].z += pq * qv.z; accv[j].w += pq * qv.w;
            }
        }
#pragma unroll
        for (int j = 0; j < 4; j++)
            *(float4*)(n2q + (size_t)m * ENC + j * 128 + lane * 4) = accv[j];
    }
}

// ---------------------------------------------------------------------------
// Per batch: bvec = softmax_n(smax); q2n = bvec @ nc
// ---------------------------------------------------------------------------
__global__ void q2n_kernel(const float* __restrict__ smax, const float* __restrict__ nc,
                           float* __restrict__ q2n)
{
    const int b = blockIdx.x;
    const int tid = threadIdx.x;            // 256
    const int lane = tid & 31, warp = tid >> 5;
    __shared__ float w[NNODE];
    __shared__ float red[8];

    float mx = -1e30f;
    for (int n = tid; n < NNODE; n += 256) mx = fmaxf(mx, smax[b * NNODE + n]);
    mx = warpMax(mx);
    if (lane == 0) red[warp] = mx;
    __syncthreads();
    float bmax = red[0];
#pragma unroll
    for (int i = 1; i < 8; i++) bmax = fmaxf(bmax, red[i]);
    __syncthreads();

    float s = 0.f;
    for (int n = tid; n < NNODE; n += 256) {
        float e = __expf(smax[b * NNODE + n] - bmax);
        w[n] = e; s += e;
    }
    s = warpSum(s);
    if (lane == 0) red[warp] = s;
    __syncthreads();
    float Z = 0.f;
#pragma unroll
    for (int i = 0; i < 8; i++) Z += red[i];
    float inv = 1.f / Z;

    const int d0 = tid * 2;
    float a0 = 0.f, a1 = 0.f;
#pragma unroll 4
    for (int n = 0; n < NNODE; n++) {
        float ww = w[n] * inv;
        const float2 r = *reinterpret_cast<const float2*>(
            nc + ((size_t)b * NNODE + n) * ENC + d0);
        a0 += ww * r.x; a1 += ww * r.y;
    }
    q2n[b * ENC + d0]     = a0;
    q2n[b * ENC + d0 + 1] = a1;
}

// ---------------------------------------------------------------------------
// g = [nc, n2q, nc*n2q, nc*q2n], tf32-rounded
// ---------------------------------------------------------------------------
__global__ void build_g(const float* __restrict__ nc, const float* __restrict__ n2q,
                        const float* __restrict__ q2n, float* __restrict__ g)
{
    int idx = blockIdx.x * 256 + threadIdx.x;
    int m = idx >> 9, d = idx & 511;
    int b = m / NNODE;
    float a = nc[idx], t = n2q[idx], qn = q2n[b * ENC + d];
    size_t base = (size_t)m * (4 * ENC) + d;
    g[base]           = tf32r(a);
    g[base + ENC]     = tf32r(t);
    g[base + 2 * ENC] = tf32r(a * t);
    g[base + 3 * ENC] = tf32r(a * qn);
}

// ---------------------------------------------------------------------------
// raw[m] = sum_h tanh(sum_s h1p[s][m][h] + b1[h]) * W2[h] + b2
// ---------------------------------------------------------------------------
__global__ void raw2_kernel(const float* __restrict__ h1p, const float* __restrict__ b1,
                            const float* __restrict__ W2, const float* __restrict__ b2,
                            float* __restrict__ raw)
{
    int gw = (blockIdx.x * blockDim.x + threadIdx.x) >> 5;
    int lane = threadIdx.x & 31;
    if (gw >= MROWS) return;
    const size_t stride = (size_t)MROWS * 128;
    float s = 0.f;
    for (int h = lane; h < 128; h += 32) {
        size_t o = (size_t)gw * 128 + h;
        float v = h1p[o] + h1p[o + stride] + h1p[o + 2*stride] + h1p[o + 3*stride]
                + b1[h];
        s += tanhf(v) * W2[h];
    }
    s = warpSum(s);
    if (lane == 0) raw[gw] = s + b2[0];
}

// ---------------------------------------------------------------------------
// out[b,c] = max_n f(mask*raw),  f(0) = -1e6
// ---------------------------------------------------------------------------
__global__ void out_kernel(const int* __restrict__ mask, const float* __restrict__ raw,
                           float* __restrict__ out)
{
    int gw = (blockIdx.x * blockDim.x + threadIdx.x) >> 5;
    int lane = threadIdx.x & 31;
    if (gw >= BATCH * NC) return;
    int b = gw / NC, c = gw - b * NC;
    const int* mr = mask + ((size_t)b * NC + c) * NNODE;
    const float* rr = raw + b * NNODE;
    float mx = -1e30f;
    for (int n = lane; n < NNODE; n += 32) {
        float p = (float)mr[n] * rr[n];
        if (p == 0.f) p = -1e6f;
        mx = fmaxf(mx, p);
    }
    mx = warpMax(mx);
    if (lane == 0) out[gw] = mx;
}

// ---------------------------------------------------------------------------
// Launch
// ---------------------------------------------------------------------------
extern "C" void kernel_launch(void* const* d_in, const int* in_sizes, int n_in,
                              void* d_out, int out_size)
{
    const float* nodes_glove = (const float*)d_in[0];
    const float* query_glove = (const float*)d_in[1];
    const float* adj         = (const float*)d_in[2];
    const int*   nlen        = (const int*)  d_in[3];
    const int*   mask        = (const int*)  d_in[4];
    const float* Wn = (const float*)d_in[5];
    const float* bn = (const float*)d_in[6];
    const float* Wq = (const float*)d_in[7];
    const float* bq = (const float*)d_in[8];
    const float* Wh = (const float*)d_in[9];
    const float* bh = (const float*)d_in[10];
    const float* Wc = (const float*)d_in[11];
    const float* bc = (const float*)d_in[12];
    const float* wa = (const float*)d_in[13];
    const float* W1 = (const float*)d_in[14];
    const float* b1 = (const float*)d_in[15];
    const float* W2 = (const float*)d_in[16];
    const float* b2 = (const float*)d_in[17];
    float* out = (float*)d_out;

    float *p_nc, *p_qc, *p_L, *p_L2, *p_hm, *p_U,
          *p_n2q, *p_smax, *p_q2n, *p_g, *p_h1p, *p_raw;
    float *p_Wnr, *p_Wqr, *p_Whr, *p_Wcr, *p_W1r, *p_ngr, *p_qgr;
    float *p_nzv; int *p_nzc, *p_nzi;
    cudaGetSymbolAddress((void**)&p_nc,  g_nc);
    cudaGetSymbolAddress((void**)&p_qc,  g_qc);
    cudaGetSymbolAddress((void**)&p_L,   g_L);
    cudaGetSymbolAddress((void**)&p_L2,  g_L2);
    cudaGetSymbolAddress((void**)&p_hm,  g_hm);
    cudaGetSymbolAddress((void**)&p_U,   g_U);
    cudaGetSymbolAddress((void**)&p_n2q, g_n2q);
    cudaGetSymbolAddress((void**)&p_smax,g_smax);
    cudaGetSymbolAddress((void**)&p_q2n, g_q2n);
    cudaGetSymbolAddress((void**)&p_g,   g_g);
    cudaGetSymbolAddress((void**)&p_h1p, g_h1p);
    cudaGetSymbolAddress((void**)&p_raw, g_raw);
    cudaGetSymbolAddress((void**)&p_Wnr, g_Wnr);
    cudaGetSymbolAddress((void**)&p_Wqr, g_Wqr);
    cudaGetSymbolAddress((void**)&p_Whr, g_Whr);
    cudaGetSymbolAddress((void**)&p_Wcr, g_Wcr);
    cudaGetSymbolAddress((void**)&p_W1r, g_W1r);
    cudaGetSymbolAddress((void**)&p_ngr, g_ngr);
    cudaGetSymbolAddress((void**)&p_qgr, g_qgr);
    cudaGetSymbolAddress((void**)&p_nzc, g_nzc);
    cudaGetSymbolAddress((void**)&p_nzi, g_nzi);
    cudaGetSymbolAddress((void**)&p_nzv, g_nzv);

    cudaFuncSetAttribute(gemm_compress, cudaFuncAttributeMaxDynamicSharedMemorySize, GEMM_SMEM);
    cudaFuncSetAttribute(gemm_hm,       cudaFuncAttributeMaxDynamicSharedMemorySize, GEMM_SMEM);
    cudaFuncSetAttribute(gemm_att,      cudaFuncAttributeMaxDynamicSharedMemorySize, GEMM_SMEM);
    cudaFuncSetAttribute(gemm_w1,       cudaFuncAttributeMaxDynamicSharedMemorySize, GEMM_SMEM);
    cudaFuncSetAttribute(attn2,         cudaFuncAttributeMaxDynamicSharedMemorySize, ATTN_SMEM);

    prep_kernel<<<NB_ROUND + NB_NZ, 256>>>(
        (const float4*)Wn, (const float4*)Wq, (const float4*)Wh,
        (const float4*)Wc, (const float4*)W1,
        (const float4*)nodes_glove, (const float4*)query_glove,
        (float4*)p_Wnr, (float4*)p_Wqr, (float4*)p_Whr,
        (float4*)p_Wcr, (float4*)p_W1r, (float4*)p_ngr, (float4*)p_qgr,
        adj, p_nzc, p_nzi, p_nzv);

    gemm_compress<<<dim3(ENC/128, 34), 256, GEMM_SMEM>>>(
        p_ngr, p_Wnr, bn, p_nc, p_L, nlen, p_qgr, p_Wqr, bq, p_qc);

    float* Lc = p_L;
    float* Ln = p_L2;
    for (int h = 0; h < HOPS; h++) {
        gemm_hm<<<dim3(ENC/128, 32), 256, GEMM_SMEM>>>(Lc, p_Whr, bh, p_hm, nlen);
        spmm_nz<<<MROWS, 128>>>(p_nzc, p_nzi, p_nzv, adj, p_hm, p_U, nlen);
        gemm_att<<<dim3(ENC/128, 32), 256, GEMM_SMEM>>>(p_U, Lc, p_Wcr, bc, nlen, Ln);
        float* t = Lc; Lc = Ln; Ln = t;
    }

    attn2<<<dim3(16, 8), 256, ATTN_SMEM>>>(Lc, p_qc, wa, p_n2q, p_smax);
    q2n_kernel<<<BATCH, 256>>>(p_smax, p_nc, p_q2n);

    build_g<<<MROWS*ENC/256, 256>>>(p_nc, p_n2q, p_q2n, p_g);
    gemm_w1<<<dim3(1, 32, 4), 256, GEMM_SMEM>>>(p_g, p_W1r, p_h1p);
    raw2_kernel<<<(MROWS*32 + 255) / 256, 256>>>(p_h1p, b1, W2, b2, p_raw);

    out_kernel<<<(BATCH*NC*32 + 255) / 256, 256>>>(mask, p_raw, out);
}

// round 8
// speedup vs baseline: 4.4094x; 1.0225x over previous
#include <cuda_runtime.h>
#include <cstdint>

// ---------------------------------------------------------------------------
// Problem constants
// ---------------------------------------------------------------------------
#define BATCH 8
#define NNODE 500
#define NQ    25
#define ENC   512
#define DIN   300
#define NC    70
#define NET   3
#define HOPS  3
#define MROWS (BATCH*NNODE)   // 4000
#define QROWS (BATCH*NQ)      // 200
#define MAXNZ 192

// GEMM smem geometry (u32 units)
#define NSTAGE  4
#define ASTRIDE 36
#define BSTRIDE 136
#define ABUF (128*ASTRIDE)          // 4608
#define BBUF (32*BSTRIDE)           // 4352
#define STAGEBUF (ABUF + BBUF)      // 8960 u32 = 35840 B
#define GEMM_SMEM (NSTAGE*STAGEBUF*4)   // 143360 bytes
#define ATTN_SMEM (NQ*ENC*4)            // 51200 bytes

// ---------------------------------------------------------------------------
// Device scratch
// ---------------------------------------------------------------------------
__device__ float g_nc  [MROWS*ENC];
__device__ float g_qc  [QROWS*ENC];
__device__ float g_L   [MROWS*ENC];
__device__ float g_L2  [MROWS*ENC];
__device__ float g_hm  [MROWS*ENC];
__device__ float g_U   [MROWS*ENC];
__device__ float g_n2q [MROWS*ENC];
__device__ float g_smax[MROWS];
__device__ float g_q2n [BATCH*ENC];
__device__ float g_g   [MROWS*4*ENC];
__device__ float g_h1p [4*MROWS*128];
__device__ float g_raw [MROWS];
// tf32-rounded copies of inputs
__device__ float g_Wnr [DIN*ENC];
__device__ float g_Wqr [DIN*ENC];
__device__ float g_Whr [ENC*ENC];
__device__ float g_Wcr [2*ENC*ENC];
__device__ float g_W1r [4*ENC*128];
__device__ float g_ngr [MROWS*DIN];
__device__ float g_qgr [QROWS*DIN];
// adjacency sparsity
__device__ int   g_nzc [MROWS];
__device__ int   g_nzi [MROWS*MAXNZ];
__device__ float g_nzv [MROWS*MAXNZ];

// ---------------------------------------------------------------------------
// Helpers
// ---------------------------------------------------------------------------
__device__ __forceinline__ float warpSum(float v) {
#pragma unroll
    for (int o = 16; o; o >>= 1) v += __shfl_xor_sync(0xffffffffu, v, o);
    return v;
}
__device__ __forceinline__ float warpMax(float v) {
#pragma unroll
    for (int o = 16; o; o >>= 1) v = fmaxf(v, __shfl_xor_sync(0xffffffffu, v, o));
    return v;
}
__device__ __forceinline__ float tf32r(float f) {
    uint32_t u;
    asm("cvt.rna.tf32.f32 %0, %1;" : "=r"(u) : "f"(f));
    return __uint_as_float(u);
}
__device__ __forceinline__ void mma_tf32(float* c, const uint32_t* a, const uint32_t* b) {
    asm volatile(
        "mma.sync.aligned.m16n8k8.row.col.f32.tf32.tf32.f32 "
        "{%0,%1,%2,%3}, {%4,%5,%6,%7}, {%8,%9}, {%0,%1,%2,%3};"
        : "+f"(c[0]), "+f"(c[1]), "+f"(c[2]), "+f"(c[3])
        : "r"(a[0]), "r"(a[1]), "r"(a[2]), "r"(a[3]), "r"(b[0]), "r"(b[1]));
}
__device__ __forceinline__ uint32_t smem_u32(const void* p) {
    return (uint32_t)__cvta_generic_to_shared(p);
}
__device__ __forceinline__ void cp_async16(uint32_t dst, const void* src, int sz) {
    asm volatile("cp.async.ca.shared.global [%0], [%1], 16, %2;\n"
                 :: "r"(dst), "l"(src), "r"(sz));
}
__device__ __forceinline__ void cp_commit() {
    asm volatile("cp.async.commit_group;\n" ::: "memory");
}
template<int N>
__device__ __forceinline__ void cp_wait() {
    asm volatile("cp.async.wait_group %0;\n" :: "n"(N) : "memory");
}

// Zero a 128x128 output tile (coalesced), guarded by r < M.
__device__ __forceinline__ void zero_tile(float* __restrict__ C, int ldc,
                                          int rowBlock, int colBlock, int M)
{
    const float4 z = make_float4(0.f, 0.f, 0.f, 0.f);
    for (int i = threadIdx.x; i < 128 * 32; i += 256) {
        int r = rowBlock + (i >> 5);
        int c4 = (i & 31) * 4;
        if (r < M)
            *reinterpret_cast<float4*>(C + (size_t)r * ldc + colBlock + c4) = z;
    }
}

// Is any row of [rowBlock, rowBlock+128) active (i < nlen[b])?
__device__ __forceinline__ bool tile_active(int rowBlock, const int* __restrict__ nlen)
{
    int b0 = rowBlock / NNODE;
    int b1 = (rowBlock + 127) / NNODE;
    if (b1 >= BATCH) b1 = BATCH - 1;
    bool act = false;
    for (int b = b0; b <= b1; b++) {
        int seg = rowBlock - b * NNODE;
        if (seg < 0) seg = 0;
        if (seg < nlen[b]) act = true;
    }
    return act;
}

// ---------------------------------------------------------------------------
// prep: tf32-round all GEMM operand inputs + build adjacency nz lists.
// ---------------------------------------------------------------------------
#define NB_ROUND 2555    // ceil(653944/256)
#define NB_NZ    500     // 4000 rows / 8 warps per block
__global__ void prep_kernel(
    const float4* __restrict__ Wn, const float4* __restrict__ Wq,
    const float4* __restrict__ Wh, const float4* __restrict__ Wc,
    const float4* __restrict__ W1, const float4* __restrict__ ng,
    const float4* __restrict__ qg,
    float4* __restrict__ oWn, float4* __restrict__ oWq, float4* __restrict__ oWh,
    float4* __restrict__ oWc, float4* __restrict__ oW1, float4* __restrict__ ong,
    float4* __restrict__ oqg,
    const float* __restrict__ adj, int* __restrict__ nzc,
    int* __restrict__ nzi, float* __restrict__ nzv)
{
    if (blockIdx.x < NB_ROUND) {
        int idx = blockIdx.x * 256 + threadIdx.x;
        const float4* src; float4* dst; int off;
        if      (idx < 38400)  { src = Wn; dst = oWn; off = idx; }
        else if (idx < 76800)  { src = Wq; dst = oWq; off = idx - 38400; }
        else if (idx < 142336) { src = Wh; dst = oWh; off = idx - 76800; }
        else if (idx < 273408) { src = Wc; dst = oWc; off = idx - 142336; }
        else if (idx < 338944) { src = W1; dst = oW1; off = idx - 273408; }
        else if (idx < 638944) { src = ng; dst = ong; off = idx - 338944; }
        else if (idx < 653944) { src = qg; dst = oqg; off = idx - 638944; }
        else return;
        float4 v = src[off];
        v.x = tf32r(v.x); v.y = tf32r(v.y); v.z = tf32r(v.z); v.w = tf32r(v.w);
        dst[off] = v;
    } else {
        int gw = (blockIdx.x - NB_ROUND) * 8 + (threadIdx.x >> 5);
        int lane = threadIdx.x & 31;
        if (gw >= MROWS) return;
        int b = gw / NNODE;
        int i = gw - b * NNODE;
        const float* a0 = adj + ((size_t)b * NET) * NNODE * NNODE + (size_t)i * NNODE;
        const float* a1 = a0 + NNODE * NNODE;
        const float* a2 = a1 + NNODE * NNODE;
        int cnt = 0;
        for (int jb = 0; jb < NNODE; jb += 32) {
            int j = jb + lane;
            float v = 0.f;
            if (j < NNODE) v = a0[j] + a1[j] + a2[j];
            unsigned m = __ballot_sync(0xffffffffu, v != 0.f);
            int pos = cnt + __popc(m & ((1u << lane) - 1u));
            if (v != 0.f && pos < MAXNZ) {
                nzi[gw * MAXNZ + pos] = j;
                nzv[gw * MAXNZ + pos] = v;
            }
            cnt += __popc(m);
        }
        if (lane == 0) nzc[gw] = cnt;
    }
}

// ---------------------------------------------------------------------------
// GEMM core (BK=32, tile 128x128, 8 warps, NSTAGE-deep cp.async pipeline)
// ---------------------------------------------------------------------------
struct GemmCtx {
    uint32_t* sh;
    int tid, lane, warp, wm, wn, tg, tq;
};

__device__ __forceinline__ void gemm_ctx_init(GemmCtx& cx, uint32_t* sh) {
    cx.sh = sh;
    cx.tid = threadIdx.x; cx.lane = cx.tid & 31; cx.warp = cx.tid >> 5;
    cx.wm = cx.warp >> 1; cx.wn = cx.warp & 1;
    cx.tg = cx.lane >> 2; cx.tq = cx.lane & 3;
}

__device__ __forceinline__ void gemm_core(
    GemmCtx& cx,
    const float* __restrict__ A, int lda,
    const float* __restrict__ Ab, int ldab, int ksplit,
    const float* __restrict__ W, int ldw,
    int rowBlock, int colBlock, int kBase, int M, int K,
    float acc[2][8][4])
{
    uint32_t* sh = cx.sh;
    const int tid = cx.tid, tg = cx.tg, tq = cx.tq, wm = cx.wm, wn = cx.wn;

    // One pipeline stage load; kk >= K lanes issue zero-size (zero-fill) copies,
    // so every call is exactly one commit group (uniform wait counts at tail).
    auto loadTiles = [&](int k0, int buf) {
        uint32_t* Ad = sh + buf * STAGEBUF;
        uint32_t* Bd = Ad + ABUF;
#pragma unroll
        for (int it = 0; it < 4; it++) {
            int idx = it * 256 + tid;
            int m = idx >> 3, cc = idx & 7;
            int gr = rowBlock + m;
            int kk = k0 + cc * 4;
            int gk = kBase + kk;
            bool ok = (gr < M && kk < K);
            // keep pointer arithmetic in-range when !ok (addr not dereferenced,
            // but stay well-defined)
            int gks = ok ? gk : 0;
            const float* src = (gks < ksplit)
                ? A  + (size_t)gr * lda  + gks
                : Ab + (size_t)gr * ldab + (gks - ksplit);
            cp_async16(smem_u32(Ad + m * ASTRIDE + cc * 4), src, ok ? 16 : 0);
        }
#pragma unroll
        for (int it = 0; it < 4; it++) {
            int idx = it * 256 + tid;
            int k = idx >> 5, cc = idx & 31;
            int kk = k0 + k;
            bool ok = (kk < K);
            int gks = ok ? (kBase + kk) : 0;
            const float* src = W + (size_t)gks * ldw + colBlock + cc * 4;
            cp_async16(smem_u32(Bd + k * BSTRIDE + cc * 4), src, ok ? 16 : 0);
        }
        cp_commit();
    };

    const int nsteps = (K + 31) / 32;

    // prologue: NSTAGE-1 stage loads (tail ones may be all-dummy; still 1 group each)
#pragma unroll
    for (int i = 0; i < NSTAGE - 1; i++)
        loadTiles(i * 32, i);

    for (int s = 0; s < nsteps; s++) {
        cp_wait<NSTAGE - 2>();      // group s complete
        __syncthreads();            // all warps done with buffer being reloaded below

        const int buf = s % NSTAGE;
        uint32_t* As = sh + buf * STAGEBUF;
        uint32_t* Bs = As + ABUF;
#pragma unroll
        for (int ks = 0; ks < 4; ks++) {
            const int kb = ks * 8;
            uint32_t af[2][4], bf[8][2];
#pragma unroll
            for (int mt = 0; mt < 2; mt++) {
                int r0 = wm * 32 + mt * 16 + tg;
                af[mt][0] = As[(r0    ) * ASTRIDE + kb + tq];
                af[mt][1] = As[(r0 + 8) * ASTRIDE + kb + tq];
                af[mt][2] = As[(r0    ) * ASTRIDE + kb + tq + 4];
                af[mt][3] = As[(r0 + 8) * ASTRIDE + kb + tq + 4];
            }
#pragma unroll
            for (int nt = 0; nt < 8; nt++) {
                int c0 = wn * 64 + nt * 8 + tg;
                bf[nt][0] = Bs[(kb + tq    ) * BSTRIDE + c0];
                bf[nt][1] = Bs[(kb + tq + 4) * BSTRIDE + c0];
            }
#pragma unroll
            for (int mt = 0; mt < 2; mt++)
#pragma unroll
                for (int nt = 0; nt < 8; nt++)
                    mma_tf32(acc[mt][nt], af[mt], bf[nt]);
        }

        // refill buffer (s + NSTAGE-1) % NSTAGE == (s-1) % NSTAGE;
        // all warps finished reading it before this iteration's syncthreads.
        loadTiles((s + NSTAGE - 1) * 32, (s + NSTAGE - 1) % NSTAGE);
    }
    cp_wait<0>();   // drain dummy groups before smem reuse by any caller
    __syncthreads();
}

// ---------------------------------------------------------------------------
// Combined compress GEMM: blockIdx.y<32 -> nodes (tanh + masked L),
// else -> query (plain). K=300.
// ---------------------------------------------------------------------------
__global__ void __launch_bounds__(256, 1) gemm_compress(
    const float* __restrict__ ng, const float* __restrict__ Wn,
    const float* __restrict__ bn, float* __restrict__ nc,
    float* __restrict__ L, const int* __restrict__ nlen,
    const float* __restrict__ qg, const float* __restrict__ Wq,
    const float* __restrict__ bq, float* __restrict__ qc)
{
    extern __shared__ uint32_t sh_[];
    GemmCtx cx; gemm_ctx_init(cx, sh_);
    float acc[2][8][4];
#pragma unroll
    for (int i = 0; i < 2; i++)
#pragma unroll
        for (int j = 0; j < 8; j++)
#pragma unroll
            for (int l = 0; l < 4; l++) acc[i][j][l] = 0.f;

    const bool isQ = blockIdx.y >= 32;
    const float* A    = isQ ? qg : ng;
    const float* W    = isQ ? Wq : Wn;
    const float* bias = isQ ? bq : bn;
    float* C          = isQ ? qc : nc;
    const int M       = isQ ? QROWS : MROWS;
    const int rowBlock = (isQ ? blockIdx.y - 32 : blockIdx.y) * 128;
    const int colBlock = blockIdx.x * 128;

    gemm_core(cx, A, DIN, A, DIN, DIN, W, ENC,
              rowBlock, colBlock, 0, M, DIN, acc);

#pragma unroll
    for (int mt = 0; mt < 2; mt++) {
#pragma unroll
        for (int half = 0; half < 2; half++) {
            int r = rowBlock + cx.wm * 32 + mt * 16 + cx.tg + half * 8;
            if (r >= M) continue;
            float rowmask = 1.f;
            if (!isQ) {
                int bb = r / NNODE;
                int ii = r - bb * NNODE;
                rowmask = (ii < nlen[bb]) ? 1.f : 0.f;
            }
#pragma unroll
            for (int nt = 0; nt < 8; nt++) {
#pragma unroll
                for (int e = 0; e < 2; e++) {
                    int c = colBlock + cx.wn * 64 + nt * 8 + cx.tq * 2 + e;
                    float v = acc[mt][nt][half * 2 + e] + bias[c];
                    size_t off = (size_t)r * ENC + c;
                    if (isQ) {
                        C[off] = v;
                    } else {
                        float t = tanhf(v);
                        C[off] = t;
                        L[off] = tf32r(t) * rowmask;
                    }
                }
            }
        }
    }
}

// ---------------------------------------------------------------------------
// Hop GEMM A: hm = (L @ Wh + bh) * nmask. Dead tiles write zeros fast.
// ---------------------------------------------------------------------------
__global__ void __launch_bounds__(256, 1) gemm_hm(
    const float* __restrict__ Lc, const float* __restrict__ Wh,
    const float* __restrict__ bh, float* __restrict__ hm,
    const int* __restrict__ nlen)
{
    const int rowBlock = blockIdx.y * 128;
    const int colBlock = blockIdx.x * 128;
    const int M = MROWS;

    if (!tile_active(rowBlock, nlen)) {
        zero_tile(hm, ENC, rowBlock, colBlock, M);
        return;
    }

    extern __shared__ uint32_t sh_[];
    GemmCtx cx; gemm_ctx_init(cx, sh_);
    float acc[2][8][4];
#pragma unroll
    for (int i = 0; i < 2; i++)
#pragma unroll
        for (int j = 0; j < 8; j++)
#pragma unroll
            for (int l = 0; l < 4; l++) acc[i][j][l] = 0.f;

    gemm_core(cx, Lc, ENC, Lc, ENC, ENC, Wh, ENC,
              rowBlock, colBlock, 0, M, ENC, acc);

#pragma unroll
    for (int mt = 0; mt < 2; mt++) {
#pragma unroll
        for (int half = 0; half < 2; half++) {
            int r = rowBlock + cx.wm * 32 + mt * 16 + cx.tg + half * 8;
            if (r >= M) continue;
            int bb = r / NNODE;
            int ii = r - bb * NNODE;
            float rowmask = (ii < nlen[bb]) ? 1.f : 0.f;
#pragma unroll
            for (int nt = 0; nt < 8; nt++) {
#pragma unroll
                for (int e = 0; e < 2; e++) {
                    int c = colBlock + cx.wn * 64 + nt * 8 + cx.tq * 2 + e;
                    float v = acc[mt][nt][half * 2 + e] + bh[c];
                    hm[(size_t)r * ENC + c] = v * rowmask;
                }
            }
        }
    }
}

// ---------------------------------------------------------------------------
// Hop GEMM B: att = sigmoid([U,L] @ Wc + bc)*nmask;
//             Lnew = tf32r(att*tanh(U) + (1-att)*Lold)
// Dead tiles: Lnew = Lold = 0 -> write zeros fast (ping-pong buffer!).
// ---------------------------------------------------------------------------
__global__ void __launch_bounds__(256, 1) gemm_att(
    const float* __restrict__ U, const float* __restrict__ Lold,
    const float* __restrict__ Wc, const float* __restrict__ bc,
    const int* __restrict__ nlen, float* __restrict__ Lnew)
{
    const int rowBlock = blockIdx.y * 128;
    const int colBlock = blockIdx.x * 128;
    const int M = MROWS;

    if (!tile_active(rowBlock, nlen)) {
        zero_tile(Lnew, ENC, rowBlock, colBlock, M);
        return;
    }

    extern __shared__ uint32_t sh_[];
    GemmCtx cx; gemm_ctx_init(cx, sh_);
    float acc[2][8][4];
#pragma unroll
    for (int i = 0; i < 2; i++)
#pragma unroll
        for (int j = 0; j < 8; j++)
#pragma unroll
            for (int l = 0; l < 4; l++) acc[i][j][l] = 0.f;

    gemm_core(cx, U, ENC, Lold, ENC, ENC, Wc, ENC,
              rowBlock, colBlock, 0, M, 2 * ENC, acc);

#pragma unroll
    for (int mt = 0; mt < 2; mt++) {
#pragma unroll
        for (int half = 0; half < 2; half++) {
            int r = rowBlock + cx.wm * 32 + mt * 16 + cx.tg + half * 8;
            if (r >= M) continue;
            int bb = r / NNODE;
            int ii = r - bb * NNODE;
            float rowmask = (ii < nlen[bb]) ? 1.f : 0.f;
#pragma unroll
            for (int nt = 0; nt < 8; nt++) {
#pragma unroll
                for (int e = 0; e < 2; e++) {
                    int c = colBlock + cx.wn * 64 + nt * 8 + cx.tq * 2 + e;
                    float v = acc[mt][nt][half * 2 + e] + bc[c];
                    size_t off = (size_t)r * ENC + c;
                    float att = rowmask / (1.f + __expf(-v));
                    Lnew[off] = tf32r(att * tanhf(U[off]) +
                                      (1.f - att) * Lold[off]);
                }
            }
        }
    }
}

// ---------------------------------------------------------------------------
// W1 GEMM: split-K=4; slab z
// ---------------------------------------------------------------------------
__global__ void __launch_bounds__(256, 1) gemm_w1(
    const float* __restrict__ g, const float* __restrict__ W1,
    float* __restrict__ h1p)
{
    extern __shared__ uint32_t sh_[];
    GemmCtx cx; gemm_ctx_init(cx, sh_);
    float acc[2][8][4];
#pragma unroll
    for (int i = 0; i < 2; i++)
#pragma unroll
        for (int j = 0; j < 8; j++)
#pragma unroll
            for (int l = 0; l < 4; l++) acc[i][j][l] = 0.f;

    const int rowBlock = blockIdx.y * 128;
    const int colBlock = 0;
    const int z = blockIdx.z;
    const int M = MROWS;

    gemm_core(cx, g, 4*ENC, g, 4*ENC, 4*ENC, W1, 128,
              rowBlock, colBlock, z * 512, M, 512, acc);

#pragma unroll
    for (int mt = 0; mt < 2; mt++) {
#pragma unroll
        for (int half = 0; half < 2; half++) {
            int r = rowBlock + cx.wm * 32 + mt * 16 + cx.tg + half * 8;
            if (r >= M) continue;
#pragma unroll
            for (int nt = 0; nt < 8; nt++) {
#pragma unroll
                for (int e = 0; e < 2; e++) {
                    int c = colBlock + cx.wn * 64 + nt * 8 + cx.tq * 2 + e;
                    float v = acc[mt][nt][half * 2 + e];
                    h1p[((size_t)z * M + r) * 128 + c] = v;
                }
            }
        }
    }
}

// ---------------------------------------------------------------------------
// U[m,:] = sum_t val[t]*hm[b, idx[t], :] + hm[m,:]; tf32-rounded.
// Masked rows: write zeros.
// ---------------------------------------------------------------------------
__global__ void spmm_nz(const int* __restrict__ nzc, const int* __restrict__ nzi,
                        const float* __restrict__ nzv, const float* __restrict__ adj,
                        const float* __restrict__ hm, float* __restrict__ U,
                        const int* __restrict__ nlen)
{
    const int m = blockIdx.x;
    const int b = m / NNODE;
    const int i = m - b * NNODE;
    const int d0 = threadIdx.x * 4;

    if (i >= nlen[b]) {
        *reinterpret_cast<float4*>(U + (size_t)m * ENC + d0) =
            make_float4(0.f, 0.f, 0.f, 0.f);
        return;
    }

    const float* hmb = hm + (size_t)b * NNODE * ENC;
    int cnt = nzc[m];
    float4 acc = *reinterpret_cast<const float4*>(hm + (size_t)m * ENC + d0);

    if (cnt <= MAXNZ) {
        __shared__ int   si[MAXNZ];
        __shared__ float sv[MAXNZ];
        for (int t = threadIdx.x; t < cnt; t += 128) {
            si[t] = nzi[m * MAXNZ + t];
            sv[t] = nzv[m * MAXNZ + t];
        }
        __syncthreads();
#pragma unroll 4
        for (int t = 0; t < cnt; t++) {
            float a = sv[t];
            const float4 hv = *reinterpret_cast<const float4*>(
                hmb + (size_t)si[t] * ENC + d0);
            acc.x += a * hv.x; acc.y += a * hv.y;
            acc.z += a * hv.z; acc.w += a * hv.w;
        }
    } else {
        const float* a0 = adj + ((size_t)b * NET) * NNODE * NNODE + (size_t)i * NNODE;
        const float* a1 = a0 + NNODE * NNODE;
        const float* a2 = a1 + NNODE * NNODE;
        for (int j = 0; j < NNODE; j++) {
            float a = a0[j] + a1[j] + a2[j];
            if (a != 0.f) {
                const float4 hv = *reinterpret_cast<const float4*>(
                    hmb + (size_t)j * ENC + d0);
                acc.x += a * hv.x; acc.y += a * hv.y;
                acc.z += a * hv.z; acc.w += a * hv.w;
            }
        }
    }
    acc.x = tf32r(acc.x); acc.y = tf32r(acc.y);
    acc.z = tf32r(acc.z); acc.w = tf32r(acc.w);
    *reinterpret_cast<float4*>(U + (size_t)m * ENC + d0) = acc;
}

// ---------------------------------------------------------------------------
// Attention: grid (16 tiles, 8 batches), block 256 (8 warps), qc tile in smem.
// ---------------------------------------------------------------------------
__global__ void __launch_bounds__(256) attn2(
    const float* __restrict__ L, const float* __restrict__ qc,
    const float* __restrict__ wa, float* __restrict__ n2q,
    float* __restrict__ smax)
{
    extern __shared__ float qs[];   // [NQ][ENC]
    __shared__ float sqv[32];
    const int b = blockIdx.y;
    const int tile = blockIdx.x;
    const int tid = threadIdx.x, lane = tid & 31, warp = tid >> 5;

    {
        const float4* src = (const float4*)(qc + (size_t)b * NQ * ENC);
        float4* dst = (float4*)qs;
        for (int i = tid; i < NQ * ENC / 4; i += 256) dst[i] = src[i];
    }
    __syncthreads();

    for (int q = warp; q < NQ; q += 8) {
        float s = 0.f;
        for (int d = lane; d < ENC; d += 32) s += qs[q * ENC + d] * wa[ENC + d];
        s = warpSum(s);
        if (lane == 0) sqv[q] = s;
    }

    float4 wan[4], was[4];
#pragma unroll
    for (int j = 0; j < 4; j++) {
        wan[j] = *(const float4*)(wa + j * 128 + lane * 4);
        was[j] = *(const float4*)(wa + 2 * ENC + j * 128 + lane * 4);
    }
    __syncthreads();

#pragma unroll
    for (int t = 0; t < 4; t++) {
        int n = tile * 32 + t * 8 + warp;
        if (n >= NNODE) continue;
        int m = b * NNODE + n;

        float4 lw[4];
        float sn = 0.f;
#pragma unroll
        for (int j = 0; j < 4; j++) {
            float4 Lv = *(const float4*)(L + (size_t)m * ENC + j * 128 + lane * 4);
            sn += Lv.x * wan[j].x + Lv.y * wan[j].y
                + Lv.z * wan[j].z + Lv.w * wan[j].w;
            lw[j].x = Lv.x * was[j].x; lw[j].y = Lv.y * was[j].y;
            lw[j].z = Lv.z * was[j].z; lw[j].w = Lv.w * was[j].w;
        }
        sn = warpSum(sn);

        float simq = -1e30f;
#pragma unroll
        for (int q = 0; q < NQ; q++) {
            float s = 0.f;
#pragma unroll
            for (int j = 0; j < 4; j++) {
                const float4 qv = *(const float4*)(qs + q * ENC + j * 128 + lane * 4);
                s += lw[j].x * qv.x + lw[j].y * qv.y
                   + lw[j].z * qv.z + lw[j].w * qv.w;
            }
            s = warpSum(s);
            if (lane == q) simq = sn + sqv[q] + s;
        }
        float mx = warpMax(lane < NQ ? simq : -1e30f);
        float e = (lane < NQ) ? __expf(simq - mx) : 0.f;
        float Z = warpSum(e);
        float p = e / Z;
        if (lane == 0) smax[m] = mx;

        float4 accv[4];
#pragma unroll
        for (int j = 0; j < 4; j++) accv[j] = make_float4(0.f, 0.f, 0.f, 0.f);
#pragma unroll
        for (int q = 0; q < NQ; q++) {
            float pq = __shfl_sync(0xffffffffu, p, q);
#pragma unroll
            for (int j = 0; j < 4; j++) {
                const float4 qv = *(const float4*)(qs + q * ENC + j * 128 + lane * 4);
                accv[j].x += pq * qv.x; accv[j].y += pq * qv.y;
                accv[j].z += pq * qv.z; accv[j].w += pq * qv.w;
            }
        }
#pragma unroll
        for (int j = 0; j < 4; j++)
            *(float4*)(n2q + (size_t)m * ENC + j * 128 + lane * 4) = accv[j];
    }
}

// ---------------------------------------------------------------------------
// Per batch: bvec = softmax_n(smax); q2n = bvec @ nc
// ---------------------------------------------------------------------------
__global__ void q2n_kernel(const float* __restrict__ smax, const float* __restrict__ nc,
                           float* __restrict__ q2n)
{
    const int b = blockIdx.x;
    const int tid = threadIdx.x;            // 256
    const int lane = tid & 31, warp = tid >> 5;
    __shared__ float w[NNODE];
    __shared__ float red[8];

    float mx = -1e30f;
    for (int n = tid; n < NNODE; n += 256) mx = fmaxf(mx, smax[b * NNODE + n]);
    mx = warpMax(mx);
    if (lane == 0) red[warp] = mx;
    __syncthreads();
    float bmax = red[0];
#pragma unroll
    for (int i = 1; i < 8; i++) bmax = fmaxf(bmax, red[i]);
    __syncthreads();

    float s = 0.f;
    for (int n = tid; n < NNODE; n += 256) {
        float e = __expf(smax[b * NNODE + n] - bmax);
        w[n] = e; s += e;
    }
    s = warpSum(s);
    if (lane == 0) red[warp] = s;
    __syncthreads();
    float Z = 0.f;
#pragma unroll
    for (int i = 0; i < 8; i++) Z += red[i];
    float inv = 1.f / Z;

    const int d0 = tid * 2;
    float a0 = 0.f, a1 = 0.f;
#pragma unroll 4
    for (int n = 0; n < NNODE; n++) {
        float ww = w[n] * inv;
        const float2 r = *reinterpret_cast<const float2*>(
            nc + ((size_t)b * NNODE + n) * ENC + d0);
        a0 += ww * r.x; a1 += ww * r.y;
    }
    q2n[b * ENC + d0]     = a0;
    q2n[b * ENC + d0 + 1] = a1;
}

// ---------------------------------------------------------------------------
// g = [nc, n2q, nc*n2q, nc*q2n], tf32-rounded
// ---------------------------------------------------------------------------
__global__ void build_g(const float* __restrict__ nc, const float* __restrict__ n2q,
                        const float* __restrict__ q2n, float* __restrict__ g)
{
    int idx = blockIdx.x * 256 + threadIdx.x;
    int m = idx >> 9, d = idx & 511;
    int b = m / NNODE;
    float a = nc[idx], t = n2q[idx], qn = q2n[b * ENC + d];
    size_t base = (size_t)m * (4 * ENC) + d;
    g[base]           = tf32r(a);
    g[base + ENC]     = tf32r(t);
    g[base + 2 * ENC] = tf32r(a * t);
    g[base + 3 * ENC] = tf32r(a * qn);
}

// ---------------------------------------------------------------------------
// raw[m] = sum_h tanh(sum_s h1p[s][m][h] + b1[h]) * W2[h] + b2
// ---------------------------------------------------------------------------
__global__ void raw2_kernel(const float* __restrict__ h1p, const float* __restrict__ b1,
                            const float* __restrict__ W2, const float* __restrict__ b2,
                            float* __restrict__ raw)
{
    int gw = (blockIdx.x * blockDim.x + threadIdx.x) >> 5;
    int lane = threadIdx.x & 31;
    if (gw >= MROWS) return;
    const size_t stride = (size_t)MROWS * 128;
    float s = 0.f;
    for (int h = lane; h < 128; h += 32) {
        size_t o = (size_t)gw * 128 + h;
        float v = h1p[o] + h1p[o + stride] + h1p[o + 2*stride] + h1p[o + 3*stride]
                + b1[h];
        s += tanhf(v) * W2[h];
    }
    s = warpSum(s);
    if (lane == 0) raw[gw] = s + b2[0];
}

// ---------------------------------------------------------------------------
// out[b,c] = max_n f(mask*raw),  f(0) = -1e6
// ---------------------------------------------------------------------------
__global__ void out_kernel(const int* __restrict__ mask, const float* __restrict__ raw,
                           float* __restrict__ out)
{
    int gw = (blockIdx.x * blockDim.x + threadIdx.x) >> 5;
    int lane = threadIdx.x & 31;
    if (gw >= BATCH * NC) return;
    int b = gw / NC, c = gw - b * NC;
    const int* mr = mask + ((size_t)b * NC + c) * NNODE;
    const float* rr = raw + b * NNODE;
    float mx = -1e30f;
    for (int n = lane; n < NNODE; n += 32) {
        float p = (float)mr[n] * rr[n];
        if (p == 0.f) p = -1e6f;
        mx = fmaxf(mx, p);
    }
    mx = warpMax(mx);
    if (lane == 0) out[gw] = mx;
}

// ---------------------------------------------------------------------------
// Launch
// ---------------------------------------------------------------------------
extern "C" void kernel_launch(void* const* d_in, const int* in_sizes, int n_in,
                              void* d_out, int out_size)
{
    const float* nodes_glove = (const float*)d_in[0];
    const float* query_glove = (const float*)d_in[1];
    const float* adj         = (const float*)d_in[2];
    const int*   nlen        = (const int*)  d_in[3];
    const int*   mask        = (const int*)  d_in[4];
    const float* Wn = (const float*)d_in[5];
    const float* bn = (const float*)d_in[6];
    const float* Wq = (const float*)d_in[7];
    const float* bq = (const float*)d_in[8];
    const float* Wh = (const float*)d_in[9];
    const float* bh = (const float*)d_in[10];
    const float* Wc = (const float*)d_in[11];
    const float* bc = (const float*)d_in[12];
    const float* wa = (const float*)d_in[13];
    const float* W1 = (const float*)d_in[14];
    const float* b1 = (const float*)d_in[15];
    const float* W2 = (const float*)d_in[16];
    const float* b2 = (const float*)d_in[17];
    float* out = (float*)d_out;

    float *p_nc, *p_qc, *p_L, *p_L2, *p_hm, *p_U,
          *p_n2q, *p_smax, *p_q2n, *p_g, *p_h1p, *p_raw;
    float *p_Wnr, *p_Wqr, *p_Whr, *p_Wcr, *p_W1r, *p_ngr, *p_qgr;
    float *p_nzv; int *p_nzc, *p_nzi;
    cudaGetSymbolAddress((void**)&p_nc,  g_nc);
    cudaGetSymbolAddress((void**)&p_qc,  g_qc);
    cudaGetSymbolAddress((void**)&p_L,   g_L);
    cudaGetSymbolAddress((void**)&p_L2,  g_L2);
    cudaGetSymbolAddress((void**)&p_hm,  g_hm);
    cudaGetSymbolAddress((void**)&p_U,   g_U);
    cudaGetSymbolAddress((void**)&p_n2q, g_n2q);
    cudaGetSymbolAddress((void**)&p_smax,g_smax);
    cudaGetSymbolAddress((void**)&p_q2n, g_q2n);
    cudaGetSymbolAddress((void**)&p_g,   g_g);
    cudaGetSymbolAddress((void**)&p_h1p, g_h1p);
    cudaGetSymbolAddress((void**)&p_raw, g_raw);
    cudaGetSymbolAddress((void**)&p_Wnr, g_Wnr);
    cudaGetSymbolAddress((void**)&p_Wqr, g_Wqr);
    cudaGetSymbolAddress((void**)&p_Whr, g_Whr);
    cudaGetSymbolAddress((void**)&p_Wcr, g_Wcr);
    cudaGetSymbolAddress((void**)&p_W1r, g_W1r);
    cudaGetSymbolAddress((void**)&p_ngr, g_ngr);
    cudaGetSymbolAddress((void**)&p_qgr, g_qgr);
    cudaGetSymbolAddress((void**)&p_nzc, g_nzc);
    cudaGetSymbolAddress((void**)&p_nzi, g_nzi);
    cudaGetSymbolAddress((void**)&p_nzv, g_nzv);

    cudaFuncSetAttribute(gemm_compress, cudaFuncAttributeMaxDynamicSharedMemorySize, GEMM_SMEM);
    cudaFuncSetAttribute(gemm_hm,       cudaFuncAttributeMaxDynamicSharedMemorySize, GEMM_SMEM);
    cudaFuncSetAttribute(gemm_att,      cudaFuncAttributeMaxDynamicSharedMemorySize, GEMM_SMEM);
    cudaFuncSetAttribute(gemm_w1,       cudaFuncAttributeMaxDynamicSharedMemorySize, GEMM_SMEM);
    cudaFuncSetAttribute(attn2,         cudaFuncAttributeMaxDynamicSharedMemorySize, ATTN_SMEM);

    prep_kernel<<<NB_ROUND + NB_NZ, 256>>>(
        (const float4*)Wn, (const float4*)Wq, (const float4*)Wh,
        (const float4*)Wc, (const float4*)W1,
        (const float4*)nodes_glove, (const float4*)query_glove,
        (float4*)p_Wnr, (float4*)p_Wqr, (float4*)p_Whr,
        (float4*)p_Wcr, (float4*)p_W1r, (float4*)p_ngr, (float4*)p_qgr,
        adj, p_nzc, p_nzi, p_nzv);

    gemm_compress<<<dim3(ENC/128, 34), 256, GEMM_SMEM>>>(
        p_ngr, p_Wnr, bn, p_nc, p_L, nlen, p_qgr, p_Wqr, bq, p_qc);

    float* Lc = p_L;
    float* Ln = p_L2;
    for (int h = 0; h < HOPS; h++) {
        gemm_hm<<<dim3(ENC/128, 32), 256, GEMM_SMEM>>>(Lc, p_Whr, bh, p_hm, nlen);
        spmm_nz<<<MROWS, 128>>>(p_nzc, p_nzi, p_nzv, adj, p_hm, p_U, nlen);
        gemm_att<<<dim3(ENC/128, 32), 256, GEMM_SMEM>>>(p_U, Lc, p_Wcr, bc, nlen, Ln);
        float* t = Lc; Lc = Ln; Ln = t;
    }

    attn2<<<dim3(16, 8), 256, ATTN_SMEM>>>(Lc, p_qc, wa, p_n2q, p_smax);
    q2n_kernel<<<BATCH, 256>>>(p_smax, p_nc, p_q2n);

    build_g<<<MROWS*ENC/256, 256>>>(p_nc, p_n2q, p_q2n, p_g);
    gemm_w1<<<dim3(1, 32, 4), 256, GEMM_SMEM>>>(p_g, p_W1r, p_h1p);
    raw2_kernel<<<(MROWS*32 + 255) / 256, 256>>>(p_h1p, b1, W2, b2, p_raw);

    out_kernel<<<(BATCH*NC*32 + 255) / 256, 256>>>(mask, p_raw, out);
}